// round 7
// baseline (speedup 1.0000x reference)
#include <cuda_runtime.h>
#include <cuda_bf16.h>
#include <math.h>
#include <stdint.h>
#include <string.h>

// Problem constants
#define BATCH 16
#define CIN   256
#define HW    4096
#define O3    1536
#define HID   512
#define NH    8
#define HD    64
#define NMEM  4
#define NC    8
#define CHUNK 512

typedef unsigned long long u64;

// Scratch (device globals — allocation-free rule)
__device__ float g_s[BATCH * HW];
__device__ __nv_bfloat16 g_w1[O3 * CIN];
__device__ __nv_bfloat16 g_w2[O3 * CIN];
__device__ __nv_bfloat16 g_wo1[CIN * HID];
__device__ __nv_bfloat16 g_wo2[CIN * HID];
__device__ __nv_bfloat16 g_x1[(size_t)BATCH * HW * CIN];   // transposed [b][n][c]
__device__ __nv_bfloat16 g_x2[(size_t)BATCH * HW * CIN];
__device__ float g_qkv[(size_t)BATCH * O3 * HW];           // 402 MB
__device__ float g_rmax[BATCH * NH * HD];
__device__ float g_rinv[BATCH * NH * HD];
__device__ float g_part[(size_t)NC * BATCH * NH * HD * HD];
__device__ float g_ctx[BATCH * NH * HD * HD];
__device__ __nv_bfloat16 g_a1[(size_t)BATCH * HW * HID];   // att^T split [b][pos][hid]
__device__ __nv_bfloat16 g_a2[(size_t)BATCH * HW * HID];

// ---- packed f32x2 helpers ------------------------------------------------
__device__ __forceinline__ u64 pack_dup(float v) {
    u64 r; asm("mov.b64 %0, {%1, %2};" : "=l"(r) : "f"(v), "f"(v)); return r;
}
__device__ __forceinline__ void ffma2(u64& d, u64 a, u64 b) {
    asm("fma.rn.f32x2 %0, %1, %2, %0;" : "+l"(d) : "l"(a), "l"(b));
}
__device__ __forceinline__ float2 unpack2(u64 v) {
    float2 f; asm("mov.b64 {%0, %1}, %2;" : "=f"(f.x), "=f"(f.y) : "l"(v)); return f;
}

// ---- mma.sync helpers ------------------------------------------------------
__device__ __forceinline__ uint32_t smem_u32(const void* p) {
    uint32_t a;
    asm("{ .reg .u64 t; cvta.to.shared.u64 t, %1; cvt.u32.u64 %0, t; }"
        : "=r"(a) : "l"(p));
    return a;
}
__device__ __forceinline__ void ldm4(uint32_t* r, uint32_t addr) {
    asm volatile("ldmatrix.sync.aligned.m8n8.x4.shared.b16 {%0,%1,%2,%3}, [%4];"
                 : "=r"(r[0]), "=r"(r[1]), "=r"(r[2]), "=r"(r[3]) : "r"(addr));
}
__device__ __forceinline__ void mma_bf16(float* c, const uint32_t* a,
                                         uint32_t b0, uint32_t b1) {
    asm volatile(
        "mma.sync.aligned.m16n8k16.row.col.f32.bf16.bf16.f32 "
        "{%0,%1,%2,%3}, {%4,%5,%6,%7}, {%8,%9}, {%0,%1,%2,%3};"
        : "+f"(c[0]), "+f"(c[1]), "+f"(c[2]), "+f"(c[3])
        : "r"(a[0]), "r"(a[1]), "r"(a[2]), "r"(a[3]), "r"(b0), "r"(b1));
}
__device__ __forceinline__ void cp16(uint32_t dst, const void* src) {
    asm volatile("cp.async.cg.shared.global [%0], [%1], 16;"
                 :: "r"(dst), "l"(src));
}
#define CP_COMMIT() asm volatile("cp.async.commit_group;" ::: "memory")
#define CP_WAIT1()  asm volatile("cp.async.wait_group 1;" ::: "memory")
#define CP_WAIT0()  asm volatile("cp.async.wait_group 0;" ::: "memory")

__device__ __forceinline__ uint32_t pkbf(float lo, float hi) {
    __nv_bfloat162 t = __floats2bfloat162_rn(lo, hi);
    uint32_t r; memcpy(&r, &t, 4); return r;
}

// ---------------------------------------------------------------------------
// Kernel 1: per-position rmsnorm scale
// ---------------------------------------------------------------------------
__global__ __launch_bounds__(256) void colscale_kernel(const float* __restrict__ x,
                                                       float* __restrict__ s) {
    int idx = blockIdx.x * 256 + threadIdx.x;
    if (idx >= BATCH * HW) return;
    int b = idx >> 12, pos = idx & (HW - 1);
    const float* p = x + (size_t)b * CIN * HW + pos;
    float acc = 0.f;
#pragma unroll 8
    for (int c = 0; c < CIN; c++) {
        float v = p[(size_t)c * HW];
        acc += v * v;
    }
    s[idx] = 16.0f / fmaxf(sqrtf(acc), 1e-12f);
}

// ---------------------------------------------------------------------------
// Kernel 1b: W fold + bf16 2-way split
// ---------------------------------------------------------------------------
__global__ __launch_bounds__(256) void wconv_kernel(const float* __restrict__ w,
                                                    const float* __restrict__ g,
                                                    __nv_bfloat16* __restrict__ w1,
                                                    __nv_bfloat16* __restrict__ w2) {
    int i = blockIdx.x * 256 + threadIdx.x;
    if (i >= O3 * CIN) return;
    float wg = w[i] * g[i & (CIN - 1)];
    __nv_bfloat16 h = __float2bfloat16_rn(wg);
    w1[i] = h;
    w2[i] = __float2bfloat16_rn(wg - __bfloat162float(h));
}

// Kernel 1b2: w_out bf16 2-way split
__global__ __launch_bounds__(256) void woconv_kernel(const float* __restrict__ w,
                                                     __nv_bfloat16* __restrict__ w1,
                                                     __nv_bfloat16* __restrict__ w2) {
    int i = blockIdx.x * 256 + threadIdx.x;
    if (i >= CIN * HID) return;
    float v = w[i];
    __nv_bfloat16 h = __float2bfloat16_rn(v);
    w1[i] = h;
    w2[i] = __float2bfloat16_rn(v - __bfloat162float(h));
}

// ---------------------------------------------------------------------------
// Kernel 1c: X transpose to [b][n][c], fold rmsnorm scale, bf16 2-way split
// ---------------------------------------------------------------------------
__global__ __launch_bounds__(256) void xconv_kernel(const float* __restrict__ x,
                                                    const float* __restrict__ s,
                                                    __nv_bfloat16* __restrict__ x1,
                                                    __nv_bfloat16* __restrict__ x2) {
    int b = blockIdx.z;
    int c0 = blockIdx.y * 32, n0 = blockIdx.x * 32;
    __shared__ float t[32][33];
    int tid = threadIdx.x;
    int tx = tid & 31, ty = tid >> 5;
#pragma unroll
    for (int i = 0; i < 4; i++) {
        int c = ty + i * 8;
        t[c][tx] = x[((size_t)b * CIN + c0 + c) * HW + n0 + tx];
    }
    __syncthreads();
#pragma unroll
    for (int i = 0; i < 4; i++) {
        int nr = ty + i * 8;
        float sv = s[b * HW + n0 + nr];
        float v = t[tx][nr] * sv;
        __nv_bfloat16 h = __float2bfloat16_rn(v);
        size_t o = ((size_t)b * HW + n0 + nr) * CIN + c0 + tx;
        x1[o] = h;
        x2[o] = __float2bfloat16_rn(v - __bfloat162float(h));
    }
}

// ---------------------------------------------------------------------------
// Kernel 2: QKV GEMM, mma.sync bf16 split, cp.async double-buffered smem +
// register double-buffered fragments. 256 thr / 8 warps (4m x 2n), warp tile
// 32x64, CTA tile 128x128, K-tile 64.
// ---------------------------------------------------------------------------
#define LDK    72
#define TILEB  (128 * LDK * 2)        // 18432
#define STAGEB (4 * TILEB)            // 73728
#define QSMTOT (2 * STAGEB)           // 147456
#define OFF_A1 0
#define OFF_A2 TILEB
#define OFF_B1 (2 * TILEB)
#define OFF_B2 (3 * TILEB)

__global__ void __launch_bounds__(256)
qkv_mma_kernel(const __nv_bfloat16* __restrict__ w1,
               const __nv_bfloat16* __restrict__ w2,
               const __nv_bfloat16* __restrict__ x1,
               const __nv_bfloat16* __restrict__ x2,
               float* __restrict__ out) {
    extern __shared__ char smem[];
    uint32_t sb = smem_u32(smem);
    int tid = threadIdx.x;
    int warp = tid >> 5, lane = tid & 31;
    int b = blockIdx.z;
    int rowBase = blockIdx.y * 128;
    int colBase = blockIdx.x * 128;

    const char* src[4] = {
        (const char*)(w1 + (size_t)rowBase * CIN),
        (const char*)(w2 + (size_t)rowBase * CIN),
        (const char*)(x1 + ((size_t)b * HW + colBase) * CIN),
        (const char*)(x2 + ((size_t)b * HW + colBase) * CIN)};

    int lrow = tid >> 3, lseg = tid & 7;

    auto load_stage = [&](int st, int k0) {
        uint32_t dbase = sb + st * STAGEB;
#pragma unroll
        for (int t4 = 0; t4 < 4; t4++) {
            const char* sp = src[t4] + k0 * 2 + lseg * 16;
            uint32_t dp = dbase + t4 * TILEB + lrow * (LDK * 2) + lseg * 16;
#pragma unroll
            for (int j = 0; j < 4; j++)
                cp16(dp + j * 32 * (LDK * 2), sp + (size_t)(lrow + j * 32) * (CIN * 2));
        }
    };

    int mwarp = (warp >> 1) * 32;
    int nwarp = (warp & 1) * 64;

    float acc[2][8][4];
#pragma unroll
    for (int mi = 0; mi < 2; mi++)
#pragma unroll
        for (int nf = 0; nf < 8; nf++)
#pragma unroll
            for (int q = 0; q < 4; q++) acc[mi][nf][q] = 0.f;

    int flrow = lane & 7, mat = lane >> 3;
    int frow = (mat & 1) * 8 + flrow;
    int fk   = (mat >> 1) * 8;

    // register-double-buffered fragments
    uint32_t fa1[2][2][4], fa2[2][2][4], fb1[2][4][4], fb2[2][4][4];

    auto ldfrags = [&](int buf, uint32_t stb, int ks) {
        int kk = ks * 16 + fk;
#pragma unroll
        for (int mi = 0; mi < 2; mi++) {
            uint32_t off = (uint32_t)((mwarp + mi * 16 + frow) * (LDK * 2) + kk * 2);
            ldm4(fa1[buf][mi], stb + OFF_A1 + off);
            ldm4(fa2[buf][mi], stb + OFF_A2 + off);
        }
#pragma unroll
        for (int nb = 0; nb < 4; nb++) {
            uint32_t off = (uint32_t)((nwarp + nb * 16 + frow) * (LDK * 2) + kk * 2);
            ldm4(fb1[buf][nb], stb + OFF_B1 + off);
            ldm4(fb2[buf][nb], stb + OFF_B2 + off);
        }
    };

    load_stage(0, 0);
    CP_COMMIT();

    for (int kt = 0; kt < 4; kt++) {
        if (kt < 3) {
            load_stage((kt + 1) & 1, (kt + 1) * 64);
            CP_COMMIT();
            CP_WAIT1();
        } else {
            CP_WAIT0();
        }
        __syncthreads();
        uint32_t stb = sb + (kt & 1) * STAGEB;

        ldfrags(0, stb, 0);
#pragma unroll
        for (int ks = 0; ks < 4; ks++) {
            int cur = ks & 1;
            if (ks < 3) ldfrags(cur ^ 1, stb, ks + 1);
#pragma unroll
            for (int mi = 0; mi < 2; mi++)
#pragma unroll
                for (int nf = 0; nf < 8; nf++) {
                    int nb = nf >> 1, hi = nf & 1;
                    mma_bf16(acc[mi][nf], fa1[cur][mi], fb1[cur][nb][hi], fb1[cur][nb][hi + 2]);
                    mma_bf16(acc[mi][nf], fa1[cur][mi], fb2[cur][nb][hi], fb2[cur][nb][hi + 2]);
                    mma_bf16(acc[mi][nf], fa2[cur][mi], fb1[cur][nb][hi], fb1[cur][nb][hi + 2]);
                }
        }
        __syncthreads();
    }

    float* obase = out + (size_t)b * O3 * HW;
#pragma unroll
    for (int mi = 0; mi < 2; mi++) {
        int row = rowBase + mwarp + mi * 16 + (lane >> 2);
#pragma unroll
        for (int nf = 0; nf < 8; nf++) {
            int col = colBase + nwarp + nf * 8 + (lane & 3) * 2;
            *(float2*)(obase + (size_t)row * HW + col) =
                make_float2(acc[mi][nf][0], acc[mi][nf][1]);
            *(float2*)(obase + (size_t)(row + 8) * HW + col) =
                make_float2(acc[mi][nf][2], acc[mi][nf][3]);
        }
    }
}

// ---------------------------------------------------------------------------
// Kernel 3a: k-softmax stats per (b,h,d) row
// ---------------------------------------------------------------------------
__global__ __launch_bounds__(256) void kstats_kernel(const float* __restrict__ qkv,
                                                     const float* __restrict__ memkv,
                                                     float* __restrict__ rmax,
                                                     float* __restrict__ rinv) {
    int d = blockIdx.x, h = blockIdx.y, b = blockIdx.z;
    int tid = threadIdx.x;
    const float* kr = qkv + ((size_t)b * O3 + HID + h * HD + d) * HW;
    const float* MK = memkv + ((size_t)h * HD + d) * NMEM;

    float v[16];
#pragma unroll
    for (int i = 0; i < 16; i++) v[i] = kr[i * 256 + tid];
    float m = v[0];
#pragma unroll
    for (int i = 1; i < 16; i++) m = fmaxf(m, v[i]);
    if (tid < NMEM) m = fmaxf(m, MK[tid]);

    __shared__ float red[8];
#pragma unroll
    for (int o = 16; o; o >>= 1) m = fmaxf(m, __shfl_xor_sync(0xFFFFFFFFu, m, o));
    if ((tid & 31) == 0) red[tid >> 5] = m;
    __syncthreads();
    if (tid == 0) {
        float t = red[0];
#pragma unroll
        for (int i = 1; i < 8; i++) t = fmaxf(t, red[i]);
        red[0] = t;
    }
    __syncthreads();
    m = red[0];
    __syncthreads();

    float ss = 0.f;
#pragma unroll
    for (int i = 0; i < 16; i++) ss += __expf(v[i] - m);
    if (tid < NMEM) ss += __expf(MK[tid] - m);
#pragma unroll
    for (int o = 16; o; o >>= 1) ss += __shfl_xor_sync(0xFFFFFFFFu, ss, o);
    if ((tid & 31) == 0) red[tid >> 5] = ss;
    __syncthreads();
    if (tid == 0) {
        float t = 0.f;
#pragma unroll
        for (int i = 0; i < 8; i++) t += red[i];
        int idx = (b * NH + h) * HD + d;
        rmax[idx] = m;
        rinv[idx] = 1.0f / t;
    }
}

// ---------------------------------------------------------------------------
// Kernel 3b: partial context via mma.sync bf16 split.
// Per (chunk,h,b): part[d][e] = sum_{n in chunk} exp(K[d][n]-rmax[d]) V[e][n].
// M=64, N=64, K=512; n-tile 64; 8 warps (2m x 4n), warp tile 32x16.
// ---------------------------------------------------------------------------
#define CLDK 72
#define CT_B (64 * CLDK * 2)   // 9216 per split tile

__global__ __launch_bounds__(256) void ctxpart_mma_kernel(
        const float* __restrict__ qkv,
        const float* __restrict__ rmax,
        float* __restrict__ part) {
    __shared__ __align__(16) char csm[4 * CT_B];
    __shared__ float rm[64];
    uint32_t sb = smem_u32(csm);
    int tid = threadIdx.x, warp = tid >> 5, lane = tid & 31;
    int c = blockIdx.x, h = blockIdx.y, b = blockIdx.z;
    const float* K = qkv + ((size_t)b * O3 + HID + h * HD) * HW;
    const float* V = qkv + ((size_t)b * O3 + 2 * HID + h * HD) * HW;

    if (tid < 64) rm[tid] = rmax[(b * NH + h) * HD + tid];
    __syncthreads();

    int mwarp = (warp >> 2) * 32;
    int nwarp = (warp & 3) * 16;

    float acc[2][2][4];
#pragma unroll
    for (int mi = 0; mi < 2; mi++)
#pragma unroll
        for (int nf = 0; nf < 2; nf++)
#pragma unroll
            for (int q = 0; q < 4; q++) acc[mi][nf][q] = 0.f;

    int flrow = lane & 7, mat = lane >> 3;
    int frow = (mat & 1) * 8 + flrow;
    int fk   = (mat >> 1) * 8;

    int row = tid & 63, q = tid >> 6;   // q: 0..3, each covers 16 n-cols

    for (int kt = 0; kt < 8; kt++) {
        int n0 = c * CHUNK + kt * 64 + q * 16;
        const float* kp = K + (size_t)row * HW + n0;
        const float* vp = V + (size_t)row * HW + n0;
        float rmv = rm[row];
        uint32_t k1[8], k2[8], w1r[8], w2r[8];
#pragma unroll
        for (int u = 0; u < 8; u++) {
            float e0 = __expf(kp[2 * u] - rmv);
            float e1 = __expf(kp[2 * u + 1] - rmv);
            __nv_bfloat16 h0 = __float2bfloat16_rn(e0), h1 = __float2bfloat16_rn(e1);
            k1[u] = pkbf(e0, e1);
            k2[u] = pkbf(e0 - __bfloat162float(h0), e1 - __bfloat162float(h1));
            float v0 = vp[2 * u], v1 = vp[2 * u + 1];
            __nv_bfloat16 g0 = __float2bfloat16_rn(v0), g1 = __float2bfloat16_rn(v1);
            w1r[u] = pkbf(v0, v1);
            w2r[u] = pkbf(v0 - __bfloat162float(g0), v1 - __bfloat162float(g1));
        }
        __syncthreads();   // previous iteration's ldmatrix reads done
        {
            char* p0 = csm + row * (CLDK * 2) + q * 32;
#pragma unroll
            for (int u = 0; u < 8; u++) {
                *(uint32_t*)(p0 + u * 4)            = k1[u];
                *(uint32_t*)(p0 + CT_B + u * 4)     = k2[u];
                *(uint32_t*)(p0 + 2 * CT_B + u * 4) = w1r[u];
                *(uint32_t*)(p0 + 3 * CT_B + u * 4) = w2r[u];
            }
        }
        __syncthreads();

#pragma unroll
        for (int ks = 0; ks < 4; ks++) {
            int kk = ks * 16 + fk;
            uint32_t a1f[2][4], a2f[2][4], b1f[4], b2f[4];
#pragma unroll
            for (int mi = 0; mi < 2; mi++) {
                uint32_t off = (uint32_t)((mwarp + mi * 16 + frow) * (CLDK * 2) + kk * 2);
                ldm4(a1f[mi], sb + off);
                ldm4(a2f[mi], sb + CT_B + off);
            }
            {
                uint32_t off = (uint32_t)((nwarp + frow) * (CLDK * 2) + kk * 2);
                ldm4(b1f, sb + 2 * CT_B + off);
                ldm4(b2f, sb + 3 * CT_B + off);
            }
#pragma unroll
            for (int mi = 0; mi < 2; mi++)
#pragma unroll
                for (int nf = 0; nf < 2; nf++) {
                    mma_bf16(acc[mi][nf], a1f[mi], b1f[nf], b1f[nf + 2]);
                    mma_bf16(acc[mi][nf], a1f[mi], b2f[nf], b2f[nf + 2]);
                    mma_bf16(acc[mi][nf], a2f[mi], b1f[nf], b1f[nf + 2]);
                }
        }
    }

    float* pb = part + ((size_t)c * BATCH * NH + b * NH + h) * (HD * HD);
#pragma unroll
    for (int mi = 0; mi < 2; mi++) {
        int d = mwarp + mi * 16 + (lane >> 2);
#pragma unroll
        for (int nf = 0; nf < 2; nf++) {
            int e = nwarp + nf * 8 + (lane & 3) * 2;
            *(float2*)(&pb[d * HD + e]) = make_float2(acc[mi][nf][0], acc[mi][nf][1]);
            *(float2*)(&pb[(d + 8) * HD + e]) = make_float2(acc[mi][nf][2], acc[mi][nf][3]);
        }
    }
}

// ---------------------------------------------------------------------------
// Kernel 3c: reduce partials + mem-kv tail + rinv scaling -> ctx
// ---------------------------------------------------------------------------
__global__ __launch_bounds__(256) void ctxreduce_kernel(const float* __restrict__ part,
                                                        const float* __restrict__ memkv,
                                                        const float* __restrict__ rmax,
                                                        const float* __restrict__ rinv,
                                                        float* __restrict__ ctx) {
    int h = blockIdx.x, b = blockIdx.y;
    __shared__ float mkx[64][4];
    __shared__ float mvs[64][4];
    __shared__ float riv[64];
    int tid = threadIdx.x;
    if (tid < 64) riv[tid] = rinv[(b * NH + h) * HD + tid];
    {
        int d = tid >> 2, j = tid & 3;
        mkx[d][j] = __expf(memkv[((size_t)h * HD + d) * NMEM + j] -
                           rmax[(b * NH + h) * HD + d]);
        mvs[d][j] = memkv[(size_t)NH * HD * NMEM + ((size_t)h * HD + d) * NMEM + j];
    }
    __syncthreads();
    size_t base = (size_t)(b * NH + h) * (HD * HD);
    for (int l = tid; l < HD * HD; l += 256) {
        int d = l >> 6, e = l & 63;
        float s2 = 0.f;
#pragma unroll
        for (int cc = 0; cc < NC; cc++)
            s2 += part[(size_t)cc * BATCH * NH * HD * HD + base + l];
#pragma unroll
        for (int j = 0; j < 4; j++) s2 += mkx[d][j] * mvs[e][j];
        ctx[base + l] = s2 * riv[d];
    }
}

// ---------------------------------------------------------------------------
// Kernel 4: q-softmax + out[e][p] = sum_d ctx[d][e]*qs[d][p]; writes bf16
// splits TRANSPOSED [b][pos][hid] for the tensorized outnorm.
// ---------------------------------------------------------------------------
__global__ __launch_bounds__(256) void attend_kernel(const float* __restrict__ qkv,
                                                     const float* __restrict__ ctx,
                                                     __nv_bfloat16* __restrict__ a1,
                                                     __nv_bfloat16* __restrict__ a2) {
    int pos0 = blockIdx.x * 64;
    int h = blockIdx.y, b = blockIdx.z;
    const float* Q = qkv + ((size_t)b * O3 + h * HD) * HW;
    const float* cb = ctx + (size_t)(b * NH + h) * HD * HD;

    __shared__ __align__(16) float cs[64][68];
    __shared__ __align__(16) float qs[64][68];

    int tid = threadIdx.x;
    for (int l = tid; l < HD * HD; l += 256) {
        int d = l >> 6, e = l & 63;
        cs[d][e] = cb[l];
        qs[d][e] = Q[(size_t)d * HW + pos0 + e];
    }
    __syncthreads();

    if (tid < 64) {
        float m = -1e30f;
#pragma unroll
        for (int d = 0; d < HD; d++) m = fmaxf(m, qs[d][tid]);
        float ss = 0.f;
#pragma unroll
        for (int d = 0; d < HD; d++) ss += __expf(qs[d][tid] - m);
        float inv = 0.125f / ss;
#pragma unroll
        for (int d = 0; d < HD; d++)
            qs[d][tid] = __expf(qs[d][tid] - m) * inv;
    }
    __syncthreads();

    int tx = tid & 15, ty = tid >> 4;
    u64 acc[4][2];
#pragma unroll
    for (int i = 0; i < 4; i++) { acc[i][0] = 0ULL; acc[i][1] = 0ULL; }

#pragma unroll 4
    for (int d = 0; d < HD; d++) {
        float4 cf = *(const float4*)(&cs[d][ty * 4]);
        u64 c0 = pack_dup(cf.x), c1 = pack_dup(cf.y);
        u64 c2 = pack_dup(cf.z), c3 = pack_dup(cf.w);
        ulonglong2 qq = *(const ulonglong2*)(&qs[d][tx * 4]);
        ffma2(acc[0][0], c0, qq.x); ffma2(acc[0][1], c0, qq.y);
        ffma2(acc[1][0], c1, qq.x); ffma2(acc[1][1], c1, qq.y);
        ffma2(acc[2][0], c2, qq.x); ffma2(acc[2][1], c2, qq.y);
        ffma2(acc[3][0], c3, qq.x); ffma2(acc[3][1], c3, qq.y);
    }

    // Stage transposed result into cs as os[pos][e]
    __syncthreads();
#pragma unroll
    for (int i = 0; i < 4; i++) {
        float2 a = unpack2(acc[i][0]);
        float2 bb = unpack2(acc[i][1]);
        int e = ty * 4 + i;
        cs[tx * 4 + 0][e] = a.x;
        cs[tx * 4 + 1][e] = a.y;
        cs[tx * 4 + 2][e] = bb.x;
        cs[tx * 4 + 3][e] = bb.y;
    }
    __syncthreads();

    {
        int pos = tid >> 2, e0 = (tid & 3) * 16;
        size_t base = ((size_t)b * HW + pos0 + pos) * HID + h * HD + e0;
        uint32_t r1[8], r2[8];
#pragma unroll
        for (int u = 0; u < 8; u++) {
            float v0 = cs[pos][e0 + 2 * u], v1 = cs[pos][e0 + 2 * u + 1];
            __nv_bfloat16 h0 = __float2bfloat16_rn(v0);
            __nv_bfloat16 h1 = __float2bfloat16_rn(v1);
            r1[u] = pkbf(v0, v1);
            r2[u] = pkbf(v0 - __bfloat162float(h0), v1 - __bfloat162float(h1));
        }
        *(uint4*)((char*)a1 + base * 2)      = make_uint4(r1[0], r1[1], r1[2], r1[3]);
        *(uint4*)((char*)a1 + base * 2 + 16) = make_uint4(r1[4], r1[5], r1[6], r1[7]);
        *(uint4*)((char*)a2 + base * 2)      = make_uint4(r2[0], r2[1], r2[2], r2[3]);
        *(uint4*)((char*)a2 + base * 2 + 16) = make_uint4(r2[4], r2[5], r2[6], r2[7]);
    }
}

// ---------------------------------------------------------------------------
// Kernel 5: out GEMM via mma.sync bf16 split + bias + fused rmsnorm.
// 256 thr / 8 warps (4m x 2n), warp tile 64x32, register-pipelined fragments.
// ---------------------------------------------------------------------------
#define OA_T   (256 * LDK * 2)        // 36864 per A split
#define OB_T   (64 * LDK * 2)         // 9216 per B split
#define OSTAGE (2 * OA_T + 2 * OB_T)  // 92160
#define OSMTOT (2 * OSTAGE)           // 184320
#define O_A1   0
#define O_A2   OA_T
#define O_B1   (2 * OA_T)
#define O_B2   (2 * OA_T + OB_T)

__global__ void __launch_bounds__(256)
outnorm_mma_kernel(const __nv_bfloat16* __restrict__ wo1,
                   const __nv_bfloat16* __restrict__ wo2,
                   const __nv_bfloat16* __restrict__ a1,
                   const __nv_bfloat16* __restrict__ a2,
                   const float* __restrict__ bias,
                   const float* __restrict__ gout,
                   float* __restrict__ out) {
    extern __shared__ char smem[];
    uint32_t sb = smem_u32(smem);
    __shared__ float colsq[64];
    __shared__ float invs[64];

    int tid = threadIdx.x;
    int warp = tid >> 5, lane = tid & 31;
    int b = blockIdx.y;
    int pos0 = blockIdx.x * 64;

    const char* srcA1 = (const char*)wo1;
    const char* srcA2 = (const char*)wo2;
    const char* srcB1 = (const char*)(a1 + ((size_t)b * HW + pos0) * HID);
    const char* srcB2 = (const char*)(a2 + ((size_t)b * HW + pos0) * HID);

    int lrow = tid >> 3, lseg = tid & 7;

    auto load_stage = [&](int st, int k0) {
        uint32_t dbase = sb + st * OSTAGE;
#pragma unroll
        for (int j = 0; j < 8; j++) {
            int row = lrow + j * 32;
            uint32_t dp = dbase + row * (LDK * 2) + lseg * 16;
            cp16(dp + O_A1, srcA1 + (size_t)row * (HID * 2) + k0 * 2 + lseg * 16);
            cp16(dp + O_A2, srcA2 + (size_t)row * (HID * 2) + k0 * 2 + lseg * 16);
        }
#pragma unroll
        for (int j = 0; j < 2; j++) {
            int row = lrow + j * 32;
            uint32_t dp = dbase + row * (LDK * 2) + lseg * 16;
            cp16(dp + O_B1, srcB1 + (size_t)row * (HID * 2) + k0 * 2 + lseg * 16);
            cp16(dp + O_B2, srcB2 + (size_t)row * (HID * 2) + k0 * 2 + lseg * 16);
        }
    };

    int mwarp = (warp >> 1) * 64;
    int nwarp = (warp & 1) * 32;

    float acc[4][4][4];
#pragma unroll
    for (int mi = 0; mi < 4; mi++)
#pragma unroll
        for (int nf = 0; nf < 4; nf++)
#pragma unroll
            for (int q = 0; q < 4; q++) acc[mi][nf][q] = 0.f;

    int flrow = lane & 7, mat = lane >> 3;
    int frow = (mat & 1) * 8 + flrow;
    int fk   = (mat >> 1) * 8;

    uint32_t fa1[2][4][4], fa2[2][4][4], fb1[2][2][4], fb2[2][2][4];

    auto ldfrags = [&](int buf, uint32_t stb, int ks) {
        int kk = ks * 16 + fk;
#pragma unroll
        for (int mi = 0; mi < 4; mi++) {
            uint32_t off = (uint32_t)((mwarp + mi * 16 + frow) * (LDK * 2) + kk * 2);
            ldm4(fa1[buf][mi], stb + O_A1 + off);
            ldm4(fa2[buf][mi], stb + O_A2 + off);
        }
#pragma unroll
        for (int nb = 0; nb < 2; nb++) {
            uint32_t off = (uint32_t)((nwarp + nb * 16 + frow) * (LDK * 2) + kk * 2);
            ldm4(fb1[buf][nb], stb + O_B1 + off);
            ldm4(fb2[buf][nb], stb + O_B2 + off);
        }
    };

    if (tid < 64) colsq[tid] = 0.f;

    load_stage(0, 0);
    CP_COMMIT();

    for (int kt = 0; kt < 8; kt++) {
        if (kt < 7) {
            load_stage((kt + 1) & 1, (kt + 1) * 64);
            CP_COMMIT();
            CP_WAIT1();
        } else {
            CP_WAIT0();
        }
        __syncthreads();
        uint32_t stb = sb + (kt & 1) * OSTAGE;

        ldfrags(0, stb, 0);
#pragma unroll
        for (int ks = 0; ks < 4; ks++) {
            int cur = ks & 1;
            if (ks < 3) ldfrags(cur ^ 1, stb, ks + 1);
#pragma unroll
            for (int mi = 0; mi < 4; mi++)
#pragma unroll
                for (int nf = 0; nf < 4; nf++) {
                    int nb = nf >> 1, hi = nf & 1;
                    mma_bf16(acc[mi][nf], fa1[cur][mi], fb1[cur][nb][hi], fb1[cur][nb][hi + 2]);
                    mma_bf16(acc[mi][nf], fa1[cur][mi], fb2[cur][nb][hi], fb2[cur][nb][hi + 2]);
                    mma_bf16(acc[mi][nf], fa2[cur][mi], fb1[cur][nb][hi], fb1[cur][nb][hi + 2]);
                }
        }
        __syncthreads();
    }

    // bias + column sum-of-squares
    float cs0[4], cs1[4];
#pragma unroll
    for (int nf = 0; nf < 4; nf++) { cs0[nf] = 0.f; cs1[nf] = 0.f; }
#pragma unroll
    for (int mi = 0; mi < 4; mi++) {
        int row = mwarp + mi * 16 + (lane >> 2);
        float bi0 = bias[row], bi1 = bias[row + 8];
#pragma unroll
        for (int nf = 0; nf < 4; nf++) {
            acc[mi][nf][0] += bi0;
            acc[mi][nf][1] += bi0;
            acc[mi][nf][2] += bi1;
            acc[mi][nf][3] += bi1;
            cs0[nf] += acc[mi][nf][0] * acc[mi][nf][0] + acc[mi][nf][2] * acc[mi][nf][2];
            cs1[nf] += acc[mi][nf][1] * acc[mi][nf][1] + acc[mi][nf][3] * acc[mi][nf][3];
        }
    }
#pragma unroll
    for (int nf = 0; nf < 4; nf++) {
#pragma unroll
        for (int o = 4; o < 32; o <<= 1) {
            cs0[nf] += __shfl_xor_sync(0xFFFFFFFFu, cs0[nf], o);
            cs1[nf] += __shfl_xor_sync(0xFFFFFFFFu, cs1[nf], o);
        }
    }
    if (lane < 4) {
#pragma unroll
        for (int nf = 0; nf < 4; nf++) {
            int col = nwarp + nf * 8 + lane * 2;
            atomicAdd(&colsq[col], cs0[nf]);
            atomicAdd(&colsq[col + 1], cs1[nf]);
        }
    }
    __syncthreads();
    if (tid < 64) invs[tid] = 16.0f / fmaxf(sqrtf(colsq[tid]), 1e-12f);
    __syncthreads();

    float* ob = out + (size_t)b * CIN * HW + pos0;
#pragma unroll
    for (int mi = 0; mi < 4; mi++) {
        int row = mwarp + mi * 16 + (lane >> 2);
        float gr0 = gout[row], gr1 = gout[row + 8];
#pragma unroll
        for (int nf = 0; nf < 4; nf++) {
            int col = nwarp + nf * 8 + (lane & 3) * 2;
            float i0 = invs[col], i1 = invs[col + 1];
            *(float2*)(ob + (size_t)row * HW + col) =
                make_float2(acc[mi][nf][0] * i0 * gr0, acc[mi][nf][1] * i1 * gr0);
            *(float2*)(ob + (size_t)(row + 8) * HW + col) =
                make_float2(acc[mi][nf][2] * i0 * gr1, acc[mi][nf][3] * i1 * gr1);
        }
    }
}

// ---------------------------------------------------------------------------
extern "C" void kernel_launch(void* const* d_in, const int* in_sizes, int n_in,
                              void* d_out, int out_size) {
    const float* x      = (const float*)d_in[0];
    const float* g_in   = (const float*)d_in[1];
    const float* w_qkv  = (const float*)d_in[2];
    const float* mem_kv = (const float*)d_in[3];
    const float* w_out  = (const float*)d_in[4];
    const float* b_out  = (const float*)d_in[5];
    const float* g_out  = (const float*)d_in[6];
    float* out = (float*)d_out;

    float *s_ptr, *qkv_ptr, *rmax_ptr, *rinv_ptr, *part_ptr, *ctx_ptr;
    __nv_bfloat16 *w1_ptr, *w2_ptr, *wo1_ptr, *wo2_ptr, *x1_ptr, *x2_ptr, *a1_ptr, *a2_ptr;
    cudaGetSymbolAddress((void**)&s_ptr,    g_s);
    cudaGetSymbolAddress((void**)&w1_ptr,   g_w1);
    cudaGetSymbolAddress((void**)&w2_ptr,   g_w2);
    cudaGetSymbolAddress((void**)&wo1_ptr,  g_wo1);
    cudaGetSymbolAddress((void**)&wo2_ptr,  g_wo2);
    cudaGetSymbolAddress((void**)&x1_ptr,   g_x1);
    cudaGetSymbolAddress((void**)&x2_ptr,   g_x2);
    cudaGetSymbolAddress((void**)&qkv_ptr,  g_qkv);
    cudaGetSymbolAddress((void**)&rmax_ptr, g_rmax);
    cudaGetSymbolAddress((void**)&rinv_ptr, g_rinv);
    cudaGetSymbolAddress((void**)&part_ptr, g_part);
    cudaGetSymbolAddress((void**)&ctx_ptr,  g_ctx);
    cudaGetSymbolAddress((void**)&a1_ptr,   g_a1);
    cudaGetSymbolAddress((void**)&a2_ptr,   g_a2);

    cudaFuncSetAttribute(qkv_mma_kernel,
                         cudaFuncAttributeMaxDynamicSharedMemorySize, QSMTOT);
    cudaFuncSetAttribute(outnorm_mma_kernel,
                         cudaFuncAttributeMaxDynamicSharedMemorySize, OSMTOT);

    colscale_kernel<<<(BATCH * HW + 255) / 256, 256>>>(x, s_ptr);
    wconv_kernel<<<(O3 * CIN + 255) / 256, 256>>>(w_qkv, g_in, w1_ptr, w2_ptr);
    woconv_kernel<<<(CIN * HID + 255) / 256, 256>>>(w_out, wo1_ptr, wo2_ptr);
    xconv_kernel<<<dim3(HW / 32, CIN / 32, BATCH), 256>>>(x, s_ptr, x1_ptr, x2_ptr);
    qkv_mma_kernel<<<dim3(HW / 128, O3 / 128, BATCH), 256, QSMTOT>>>(
        w1_ptr, w2_ptr, x1_ptr, x2_ptr, qkv_ptr);
    kstats_kernel<<<dim3(HD, NH, BATCH), 256>>>(qkv_ptr, mem_kv, rmax_ptr, rinv_ptr);
    ctxpart_mma_kernel<<<dim3(NC, NH, BATCH), 256>>>(qkv_ptr, rmax_ptr, part_ptr);
    ctxreduce_kernel<<<dim3(NH, BATCH), 256>>>(part_ptr, mem_kv, rmax_ptr, rinv_ptr, ctx_ptr);
    attend_kernel<<<dim3(HW / 64, NH, BATCH), 256>>>(qkv_ptr, ctx_ptr, a1_ptr, a2_ptr);
    outnorm_mma_kernel<<<dim3(HW / 64, BATCH), 256, OSMTOT>>>(
        wo1_ptr, wo2_ptr, a1_ptr, a2_ptr, b_out, g_out, out);
}

// round 8
// speedup vs baseline: 1.1060x; 1.1060x over previous
#include <cuda_runtime.h>
#include <cuda_bf16.h>
#include <math.h>
#include <stdint.h>
#include <string.h>

// Problem constants
#define BATCH 16
#define CIN   256
#define HW    4096
#define O3    1536
#define HID   512
#define NH    8
#define HD    64
#define NMEM  4
#define NC    8
#define CHUNK 512

typedef unsigned long long u64;

// Scratch (device globals — allocation-free rule)
__device__ float g_s[BATCH * HW];
__device__ __nv_bfloat16 g_w1[O3 * CIN];
__device__ __nv_bfloat16 g_w2[O3 * CIN];
__device__ __nv_bfloat16 g_wo1[CIN * HID];
__device__ __nv_bfloat16 g_wo2[CIN * HID];
__device__ __nv_bfloat16 g_x1[(size_t)BATCH * HW * CIN];   // transposed [b][n][c]
__device__ __nv_bfloat16 g_x2[(size_t)BATCH * HW * CIN];
__device__ float g_qkv[(size_t)BATCH * O3 * HW];           // 402 MB
__device__ float g_rmax[BATCH * NH * HD];
__device__ float g_rinv[BATCH * NH * HD];
__device__ float g_part[(size_t)NC * BATCH * NH * HD * HD];
__device__ float g_ctx[BATCH * NH * HD * HD];
__device__ __nv_bfloat16 g_a1[(size_t)BATCH * HW * HID];   // att^T split [b][pos][hid]
__device__ __nv_bfloat16 g_a2[(size_t)BATCH * HW * HID];

// ---- packed f32x2 helpers ------------------------------------------------
__device__ __forceinline__ u64 pack_dup(float v) {
    u64 r; asm("mov.b64 %0, {%1, %2};" : "=l"(r) : "f"(v), "f"(v)); return r;
}
__device__ __forceinline__ void ffma2(u64& d, u64 a, u64 b) {
    asm("fma.rn.f32x2 %0, %1, %2, %0;" : "+l"(d) : "l"(a), "l"(b));
}
__device__ __forceinline__ float2 unpack2(u64 v) {
    float2 f; asm("mov.b64 {%0, %1}, %2;" : "=f"(f.x), "=f"(f.y) : "l"(v)); return f;
}

// ---- mma.sync helpers ------------------------------------------------------
__device__ __forceinline__ uint32_t smem_u32(const void* p) {
    uint32_t a;
    asm("{ .reg .u64 t; cvta.to.shared.u64 t, %1; cvt.u32.u64 %0, t; }"
        : "=r"(a) : "l"(p));
    return a;
}
__device__ __forceinline__ void ldm4(uint32_t* r, uint32_t addr) {
    asm volatile("ldmatrix.sync.aligned.m8n8.x4.shared.b16 {%0,%1,%2,%3}, [%4];"
                 : "=r"(r[0]), "=r"(r[1]), "=r"(r[2]), "=r"(r[3]) : "r"(addr));
}
__device__ __forceinline__ void mma_bf16(float* c, const uint32_t* a,
                                         uint32_t b0, uint32_t b1) {
    asm volatile(
        "mma.sync.aligned.m16n8k16.row.col.f32.bf16.bf16.f32 "
        "{%0,%1,%2,%3}, {%4,%5,%6,%7}, {%8,%9}, {%0,%1,%2,%3};"
        : "+f"(c[0]), "+f"(c[1]), "+f"(c[2]), "+f"(c[3])
        : "r"(a[0]), "r"(a[1]), "r"(a[2]), "r"(a[3]), "r"(b0), "r"(b1));
}
__device__ __forceinline__ void cp16(uint32_t dst, const void* src) {
    asm volatile("cp.async.cg.shared.global [%0], [%1], 16;"
                 :: "r"(dst), "l"(src));
}
#define CP_COMMIT() asm volatile("cp.async.commit_group;" ::: "memory")
#define CP_WAIT1()  asm volatile("cp.async.wait_group 1;" ::: "memory")
#define CP_WAIT0()  asm volatile("cp.async.wait_group 0;" ::: "memory")

__device__ __forceinline__ uint32_t pkbf(float lo, float hi) {
    __nv_bfloat162 t = __floats2bfloat162_rn(lo, hi);
    uint32_t r; memcpy(&r, &t, 4); return r;
}

// ---------------------------------------------------------------------------
// Kernel 1: per-position rmsnorm scale
// ---------------------------------------------------------------------------
__global__ __launch_bounds__(256) void colscale_kernel(const float* __restrict__ x,
                                                       float* __restrict__ s) {
    int idx = blockIdx.x * 256 + threadIdx.x;
    if (idx >= BATCH * HW) return;
    int b = idx >> 12, pos = idx & (HW - 1);
    const float* p = x + (size_t)b * CIN * HW + pos;
    float acc = 0.f;
#pragma unroll 8
    for (int c = 0; c < CIN; c++) {
        float v = p[(size_t)c * HW];
        acc += v * v;
    }
    s[idx] = 16.0f / fmaxf(sqrtf(acc), 1e-12f);
}

// ---------------------------------------------------------------------------
// Kernel 1b: W fold + bf16 2-way split
// ---------------------------------------------------------------------------
__global__ __launch_bounds__(256) void wconv_kernel(const float* __restrict__ w,
                                                    const float* __restrict__ g,
                                                    __nv_bfloat16* __restrict__ w1,
                                                    __nv_bfloat16* __restrict__ w2) {
    int i = blockIdx.x * 256 + threadIdx.x;
    if (i >= O3 * CIN) return;
    float wg = w[i] * g[i & (CIN - 1)];
    __nv_bfloat16 h = __float2bfloat16_rn(wg);
    w1[i] = h;
    w2[i] = __float2bfloat16_rn(wg - __bfloat162float(h));
}

// Kernel 1b2: w_out bf16 2-way split
__global__ __launch_bounds__(256) void woconv_kernel(const float* __restrict__ w,
                                                     __nv_bfloat16* __restrict__ w1,
                                                     __nv_bfloat16* __restrict__ w2) {
    int i = blockIdx.x * 256 + threadIdx.x;
    if (i >= CIN * HID) return;
    float v = w[i];
    __nv_bfloat16 h = __float2bfloat16_rn(v);
    w1[i] = h;
    w2[i] = __float2bfloat16_rn(v - __bfloat162float(h));
}

// ---------------------------------------------------------------------------
// Kernel 1c: X transpose to [b][n][c], fold rmsnorm scale, bf16 2-way split
// ---------------------------------------------------------------------------
__global__ __launch_bounds__(256) void xconv_kernel(const float* __restrict__ x,
                                                    const float* __restrict__ s,
                                                    __nv_bfloat16* __restrict__ x1,
                                                    __nv_bfloat16* __restrict__ x2) {
    int b = blockIdx.z;
    int c0 = blockIdx.y * 32, n0 = blockIdx.x * 32;
    __shared__ float t[32][33];
    int tid = threadIdx.x;
    int tx = tid & 31, ty = tid >> 5;
#pragma unroll
    for (int i = 0; i < 4; i++) {
        int c = ty + i * 8;
        t[c][tx] = x[((size_t)b * CIN + c0 + c) * HW + n0 + tx];
    }
    __syncthreads();
#pragma unroll
    for (int i = 0; i < 4; i++) {
        int nr = ty + i * 8;
        float sv = s[b * HW + n0 + nr];
        float v = t[tx][nr] * sv;
        __nv_bfloat16 h = __float2bfloat16_rn(v);
        size_t o = ((size_t)b * HW + n0 + nr) * CIN + c0 + tx;
        x1[o] = h;
        x2[o] = __float2bfloat16_rn(v - __bfloat162float(h));
    }
}

// ---------------------------------------------------------------------------
// Kernel 2: QKV GEMM, mma.sync bf16 split, cp.async double-buffered.
// CTA tile 256x128, K-tile 64, 256 thr / 8 warps (4m x 2n), warp tile 64x64.
// MMA:LDSM ratio 6:1.
// ---------------------------------------------------------------------------
#define QLDK   72
#define QA_T   (256 * QLDK * 2)        // 36864 per A split
#define QB_T   (128 * QLDK * 2)        // 18432 per B split
#define QSTAGE (2 * QA_T + 2 * QB_T)   // 110592
#define QSMTOT (2 * QSTAGE)            // 221184
#define Q_A1   0
#define Q_A2   QA_T
#define Q_B1   (2 * QA_T)
#define Q_B2   (2 * QA_T + QB_T)

__global__ void __launch_bounds__(256)
qkv_mma_kernel(const __nv_bfloat16* __restrict__ w1,
               const __nv_bfloat16* __restrict__ w2,
               const __nv_bfloat16* __restrict__ x1,
               const __nv_bfloat16* __restrict__ x2,
               float* __restrict__ out) {
    extern __shared__ char smem[];
    uint32_t sb = smem_u32(smem);
    int tid = threadIdx.x;
    int warp = tid >> 5, lane = tid & 31;
    int b = blockIdx.z;
    int rowBase = blockIdx.y * 256;
    int colBase = blockIdx.x * 128;

    const char* srcA1 = (const char*)(w1 + (size_t)rowBase * CIN);
    const char* srcA2 = (const char*)(w2 + (size_t)rowBase * CIN);
    const char* srcB1 = (const char*)(x1 + ((size_t)b * HW + colBase) * CIN);
    const char* srcB2 = (const char*)(x2 + ((size_t)b * HW + colBase) * CIN);

    int lrow = tid >> 3, lseg = tid & 7;   // 32 rows x 8 segs per pass

    auto load_stage = [&](int st, int k0) {
        uint32_t dbase = sb + st * QSTAGE;
#pragma unroll
        for (int j = 0; j < 8; j++) {      // A: 256 rows
            int row = lrow + j * 32;
            uint32_t dp = dbase + row * (QLDK * 2) + lseg * 16;
            cp16(dp + Q_A1, srcA1 + (size_t)row * (CIN * 2) + k0 * 2 + lseg * 16);
            cp16(dp + Q_A2, srcA2 + (size_t)row * (CIN * 2) + k0 * 2 + lseg * 16);
        }
#pragma unroll
        for (int j = 0; j < 4; j++) {      // B: 128 rows
            int row = lrow + j * 32;
            uint32_t dp = dbase + row * (QLDK * 2) + lseg * 16;
            cp16(dp + Q_B1, srcB1 + (size_t)row * (CIN * 2) + k0 * 2 + lseg * 16);
            cp16(dp + Q_B2, srcB2 + (size_t)row * (CIN * 2) + k0 * 2 + lseg * 16);
        }
    };

    int mwarp = (warp >> 1) * 64;
    int nwarp = (warp & 1) * 64;

    float acc[4][8][4];
#pragma unroll
    for (int mi = 0; mi < 4; mi++)
#pragma unroll
        for (int nf = 0; nf < 8; nf++)
#pragma unroll
            for (int q = 0; q < 4; q++) acc[mi][nf][q] = 0.f;

    int flrow = lane & 7, mat = lane >> 3;
    int frow = (mat & 1) * 8 + flrow;
    int fk   = (mat >> 1) * 8;

    load_stage(0, 0);
    CP_COMMIT();

    for (int kt = 0; kt < 4; kt++) {
        if (kt < 3) {
            load_stage((kt + 1) & 1, (kt + 1) * 64);
            CP_COMMIT();
            CP_WAIT1();
        } else {
            CP_WAIT0();
        }
        __syncthreads();
        uint32_t stb = sb + (kt & 1) * QSTAGE;

#pragma unroll
        for (int ks = 0; ks < 4; ks++) {
            int kk = ks * 16 + fk;
            uint32_t fa1[4][4], fa2[4][4];
#pragma unroll
            for (int mi = 0; mi < 4; mi++) {
                uint32_t off = (uint32_t)((mwarp + mi * 16 + frow) * (QLDK * 2) + kk * 2);
                ldm4(fa1[mi], stb + Q_A1 + off);
                ldm4(fa2[mi], stb + Q_A2 + off);
            }
            uint32_t fb1[4][4], fb2[4][4];
#pragma unroll
            for (int nb = 0; nb < 4; nb++) {
                uint32_t off = (uint32_t)((nwarp + nb * 16 + frow) * (QLDK * 2) + kk * 2);
                ldm4(fb1[nb], stb + Q_B1 + off);
                ldm4(fb2[nb], stb + Q_B2 + off);
            }
#pragma unroll
            for (int mi = 0; mi < 4; mi++)
#pragma unroll
                for (int nf = 0; nf < 8; nf++) {
                    int nb = nf >> 1, hi = nf & 1;
                    mma_bf16(acc[mi][nf], fa1[mi], fb1[nb][hi], fb1[nb][hi + 2]);
                    mma_bf16(acc[mi][nf], fa1[mi], fb2[nb][hi], fb2[nb][hi + 2]);
                    mma_bf16(acc[mi][nf], fa2[mi], fb1[nb][hi], fb1[nb][hi + 2]);
                }
        }
        __syncthreads();
    }

    float* obase = out + (size_t)b * O3 * HW;
#pragma unroll
    for (int mi = 0; mi < 4; mi++) {
        int row = rowBase + mwarp + mi * 16 + (lane >> 2);
#pragma unroll
        for (int nf = 0; nf < 8; nf++) {
            int col = colBase + nwarp + nf * 8 + (lane & 3) * 2;
            *(float2*)(obase + (size_t)row * HW + col) =
                make_float2(acc[mi][nf][0], acc[mi][nf][1]);
            *(float2*)(obase + (size_t)(row + 8) * HW + col) =
                make_float2(acc[mi][nf][2], acc[mi][nf][3]);
        }
    }
}

// ---------------------------------------------------------------------------
// Kernel 3a: k-softmax stats per (b,h,d) row
// ---------------------------------------------------------------------------
__global__ __launch_bounds__(256) void kstats_kernel(const float* __restrict__ qkv,
                                                     const float* __restrict__ memkv,
                                                     float* __restrict__ rmax,
                                                     float* __restrict__ rinv) {
    int d = blockIdx.x, h = blockIdx.y, b = blockIdx.z;
    int tid = threadIdx.x;
    const float* kr = qkv + ((size_t)b * O3 + HID + h * HD + d) * HW;
    const float* MK = memkv + ((size_t)h * HD + d) * NMEM;

    float v[16];
#pragma unroll
    for (int i = 0; i < 16; i++) v[i] = kr[i * 256 + tid];
    float m = v[0];
#pragma unroll
    for (int i = 1; i < 16; i++) m = fmaxf(m, v[i]);
    if (tid < NMEM) m = fmaxf(m, MK[tid]);

    __shared__ float red[8];
#pragma unroll
    for (int o = 16; o; o >>= 1) m = fmaxf(m, __shfl_xor_sync(0xFFFFFFFFu, m, o));
    if ((tid & 31) == 0) red[tid >> 5] = m;
    __syncthreads();
    if (tid == 0) {
        float t = red[0];
#pragma unroll
        for (int i = 1; i < 8; i++) t = fmaxf(t, red[i]);
        red[0] = t;
    }
    __syncthreads();
    m = red[0];
    __syncthreads();

    float ss = 0.f;
#pragma unroll
    for (int i = 0; i < 16; i++) ss += __expf(v[i] - m);
    if (tid < NMEM) ss += __expf(MK[tid] - m);
#pragma unroll
    for (int o = 16; o; o >>= 1) ss += __shfl_xor_sync(0xFFFFFFFFu, ss, o);
    if ((tid & 31) == 0) red[tid >> 5] = ss;
    __syncthreads();
    if (tid == 0) {
        float t = 0.f;
#pragma unroll
        for (int i = 0; i < 8; i++) t += red[i];
        int idx = (b * NH + h) * HD + d;
        rmax[idx] = m;
        rinv[idx] = 1.0f / t;
    }
}

// ---------------------------------------------------------------------------
// Kernel 3b: partial context over n chunks (FFMA2 SIMT — proven fastest)
// ---------------------------------------------------------------------------
__global__ __launch_bounds__(256) void ctxpart_kernel(const float* __restrict__ qkv,
                                                      const float* __restrict__ rmax,
                                                      float* __restrict__ part) {
    int c = blockIdx.x, h = blockIdx.y, b = blockIdx.z;
    const float* K = qkv + ((size_t)b * O3 + HID + h * HD) * HW;
    const float* V = qkv + ((size_t)b * O3 + 2 * HID + h * HD) * HW;

    __shared__ __align__(16) float Kt[64][68];
    __shared__ __align__(16) float Vt[64][68];
    __shared__ float rm[64];

    int tid = threadIdx.x;
    if (tid < 64) rm[tid] = rmax[(b * NH + h) * HD + tid];
    __syncthreads();

    int tx = tid & 15, ty = tid >> 4;
    u64 acc[4][2];
#pragma unroll
    for (int i = 0; i < 4; i++) { acc[i][0] = 0ULL; acc[i][1] = 0ULL; }

    for (int nt = 0; nt < CHUNK / 64; nt++) {
        int n0 = c * CHUNK + nt * 64;
#pragma unroll
        for (int l = 0; l < 16; l++) {
            int lin = l * 256 + tid;
            int d = lin >> 6, j = lin & 63;
            Kt[j][d] = __expf(K[(size_t)d * HW + n0 + j] - rm[d]);
            Vt[j][d] = V[(size_t)d * HW + n0 + j];
        }
        __syncthreads();
#pragma unroll 4
        for (int j = 0; j < 64; j++) {
            float4 kf = *(const float4*)(&Kt[j][ty * 4]);
            u64 k0 = pack_dup(kf.x), k1 = pack_dup(kf.y);
            u64 k2 = pack_dup(kf.z), k3 = pack_dup(kf.w);
            ulonglong2 vv = *(const ulonglong2*)(&Vt[j][tx * 4]);
            ffma2(acc[0][0], k0, vv.x); ffma2(acc[0][1], k0, vv.y);
            ffma2(acc[1][0], k1, vv.x); ffma2(acc[1][1], k1, vv.y);
            ffma2(acc[2][0], k2, vv.x); ffma2(acc[2][1], k2, vv.y);
            ffma2(acc[3][0], k3, vv.x); ffma2(acc[3][1], k3, vv.y);
        }
        __syncthreads();
    }

    float* pb = part + ((size_t)c * BATCH * NH + b * NH + h) * (HD * HD);
#pragma unroll
    for (int i = 0; i < 4; i++) {
        float2 a = unpack2(acc[i][0]);
        float2 bb = unpack2(acc[i][1]);
        *(float4*)(&pb[(ty * 4 + i) * HD + tx * 4]) = make_float4(a.x, a.y, bb.x, bb.y);
    }
}

// ---------------------------------------------------------------------------
// Kernel 3c: reduce partials + mem-kv tail + rinv scaling -> ctx
// ---------------------------------------------------------------------------
__global__ __launch_bounds__(256) void ctxreduce_kernel(const float* __restrict__ part,
                                                        const float* __restrict__ memkv,
                                                        const float* __restrict__ rmax,
                                                        const float* __restrict__ rinv,
                                                        float* __restrict__ ctx) {
    int h = blockIdx.x, b = blockIdx.y;
    __shared__ float mkx[64][4];
    __shared__ float mvs[64][4];
    __shared__ float riv[64];
    int tid = threadIdx.x;
    if (tid < 64) riv[tid] = rinv[(b * NH + h) * HD + tid];
    {
        int d = tid >> 2, j = tid & 3;
        mkx[d][j] = __expf(memkv[((size_t)h * HD + d) * NMEM + j] -
                           rmax[(b * NH + h) * HD + d]);
        mvs[d][j] = memkv[(size_t)NH * HD * NMEM + ((size_t)h * HD + d) * NMEM + j];
    }
    __syncthreads();
    size_t base = (size_t)(b * NH + h) * (HD * HD);
    for (int l = tid; l < HD * HD; l += 256) {
        int d = l >> 6, e = l & 63;
        float s2 = 0.f;
#pragma unroll
        for (int cc = 0; cc < NC; cc++)
            s2 += part[(size_t)cc * BATCH * NH * HD * HD + base + l];
#pragma unroll
        for (int j = 0; j < 4; j++) s2 += mkx[d][j] * mvs[e][j];
        ctx[base + l] = s2 * riv[d];
    }
}

// ---------------------------------------------------------------------------
// Kernel 4: q-softmax + out[e][p] = sum_d ctx[d][e]*qs[d][p]; writes bf16
// splits TRANSPOSED [b][pos][hid] for the tensorized outnorm.
// ---------------------------------------------------------------------------
__global__ __launch_bounds__(256) void attend_kernel(const float* __restrict__ qkv,
                                                     const float* __restrict__ ctx,
                                                     __nv_bfloat16* __restrict__ a1,
                                                     __nv_bfloat16* __restrict__ a2) {
    int pos0 = blockIdx.x * 64;
    int h = blockIdx.y, b = blockIdx.z;
    const float* Q = qkv + ((size_t)b * O3 + h * HD) * HW;
    const float* cb = ctx + (size_t)(b * NH + h) * HD * HD;

    __shared__ __align__(16) float cs[64][68];
    __shared__ __align__(16) float qs[64][68];

    int tid = threadIdx.x;
    for (int l = tid; l < HD * HD; l += 256) {
        int d = l >> 6, e = l & 63;
        cs[d][e] = cb[l];
        qs[d][e] = Q[(size_t)d * HW + pos0 + e];
    }
    __syncthreads();

    if (tid < 64) {
        float m = -1e30f;
#pragma unroll
        for (int d = 0; d < HD; d++) m = fmaxf(m, qs[d][tid]);
        float ss = 0.f;
#pragma unroll
        for (int d = 0; d < HD; d++) ss += __expf(qs[d][tid] - m);
        float inv = 0.125f / ss;
#pragma unroll
        for (int d = 0; d < HD; d++)
            qs[d][tid] = __expf(qs[d][tid] - m) * inv;
    }
    __syncthreads();

    int tx = tid & 15, ty = tid >> 4;
    u64 acc[4][2];
#pragma unroll
    for (int i = 0; i < 4; i++) { acc[i][0] = 0ULL; acc[i][1] = 0ULL; }

#pragma unroll 4
    for (int d = 0; d < HD; d++) {
        float4 cf = *(const float4*)(&cs[d][ty * 4]);
        u64 c0 = pack_dup(cf.x), c1 = pack_dup(cf.y);
        u64 c2 = pack_dup(cf.z), c3 = pack_dup(cf.w);
        ulonglong2 qq = *(const ulonglong2*)(&qs[d][tx * 4]);
        ffma2(acc[0][0], c0, qq.x); ffma2(acc[0][1], c0, qq.y);
        ffma2(acc[1][0], c1, qq.x); ffma2(acc[1][1], c1, qq.y);
        ffma2(acc[2][0], c2, qq.x); ffma2(acc[2][1], c2, qq.y);
        ffma2(acc[3][0], c3, qq.x); ffma2(acc[3][1], c3, qq.y);
    }

    // Stage transposed result into cs as os[pos][e]
    __syncthreads();
#pragma unroll
    for (int i = 0; i < 4; i++) {
        float2 a = unpack2(acc[i][0]);
        float2 bb = unpack2(acc[i][1]);
        int e = ty * 4 + i;
        cs[tx * 4 + 0][e] = a.x;
        cs[tx * 4 + 1][e] = a.y;
        cs[tx * 4 + 2][e] = bb.x;
        cs[tx * 4 + 3][e] = bb.y;
    }
    __syncthreads();

    {
        int pos = tid >> 2, e0 = (tid & 3) * 16;
        size_t base = ((size_t)b * HW + pos0 + pos) * HID + h * HD + e0;
        uint32_t r1[8], r2[8];
#pragma unroll
        for (int u = 0; u < 8; u++) {
            float v0 = cs[pos][e0 + 2 * u], v1 = cs[pos][e0 + 2 * u + 1];
            __nv_bfloat16 h0 = __float2bfloat16_rn(v0);
            __nv_bfloat16 h1 = __float2bfloat16_rn(v1);
            r1[u] = pkbf(v0, v1);
            r2[u] = pkbf(v0 - __bfloat162float(h0), v1 - __bfloat162float(h1));
        }
        *(uint4*)((char*)a1 + base * 2)      = make_uint4(r1[0], r1[1], r1[2], r1[3]);
        *(uint4*)((char*)a1 + base * 2 + 16) = make_uint4(r1[4], r1[5], r1[6], r1[7]);
        *(uint4*)((char*)a2 + base * 2)      = make_uint4(r2[0], r2[1], r2[2], r2[3]);
        *(uint4*)((char*)a2 + base * 2 + 16) = make_uint4(r2[4], r2[5], r2[6], r2[7]);
    }
}

// ---------------------------------------------------------------------------
// Kernel 5: out GEMM via mma.sync bf16 split + bias + fused rmsnorm.
// CTA tile 256x128 (all channels x 128 positions), K-tile 32, 256 thr /
// 8 warps (4m x 2n), warp tile 64x64. MMA:LDSM 6:1.
// ---------------------------------------------------------------------------
#define OLDK   40                      // padded k stride (80 B rows, conflict-free)
#define OA_T   (256 * OLDK * 2)        // 20480 per A split
#define OB_T   (128 * OLDK * 2)        // 10240 per B split
#define OSTAGE (2 * OA_T + 2 * OB_T)   // 61440
#define OSMTOT (2 * OSTAGE)            // 122880
#define O_A1   0
#define O_A2   OA_T
#define O_B1   (2 * OA_T)
#define O_B2   (2 * OA_T + OB_T)

__global__ void __launch_bounds__(256)
outnorm_mma_kernel(const __nv_bfloat16* __restrict__ wo1,
                   const __nv_bfloat16* __restrict__ wo2,
                   const __nv_bfloat16* __restrict__ a1,
                   const __nv_bfloat16* __restrict__ a2,
                   const float* __restrict__ bias,
                   const float* __restrict__ gout,
                   float* __restrict__ out) {
    extern __shared__ char smem[];
    uint32_t sb = smem_u32(smem);
    __shared__ float colsq[128];
    __shared__ float invs[128];

    int tid = threadIdx.x;
    int warp = tid >> 5, lane = tid & 31;
    int b = blockIdx.y;
    int pos0 = blockIdx.x * 128;

    const char* srcA1 = (const char*)wo1;
    const char* srcA2 = (const char*)wo2;
    const char* srcB1 = (const char*)(a1 + ((size_t)b * HW + pos0) * HID);
    const char* srcB2 = (const char*)(a2 + ((size_t)b * HW + pos0) * HID);

    int lrow = tid >> 2, lseg = tid & 3;   // 64 rows x 4 segs per pass (32 k = 64 B)

    auto load_stage = [&](int st, int k0) {
        uint32_t dbase = sb + st * OSTAGE;
#pragma unroll
        for (int j = 0; j < 4; j++) {      // A: 256 rows
            int row = lrow + j * 64;
            uint32_t dp = dbase + row * (OLDK * 2) + lseg * 16;
            cp16(dp + O_A1, srcA1 + (size_t)row * (HID * 2) + k0 * 2 + lseg * 16);
            cp16(dp + O_A2, srcA2 + (size_t)row * (HID * 2) + k0 * 2 + lseg * 16);
        }
#pragma unroll
        for (int j = 0; j < 2; j++) {      // B: 128 rows
            int row = lrow + j * 64;
            uint32_t dp = dbase + row * (OLDK * 2) + lseg * 16;
            cp16(dp + O_B1, srcB1 + (size_t)row * (HID * 2) + k0 * 2 + lseg * 16);
            cp16(dp + O_B2, srcB2 + (size_t)row * (HID * 2) + k0 * 2 + lseg * 16);
        }
    };

    int mwarp = (warp >> 1) * 64;
    int nwarp = (warp & 1) * 64;

    float acc[4][8][4];
#pragma unroll
    for (int mi = 0; mi < 4; mi++)
#pragma unroll
        for (int nf = 0; nf < 8; nf++)
#pragma unroll
            for (int q = 0; q < 4; q++) acc[mi][nf][q] = 0.f;

    int flrow = lane & 7, mat = lane >> 3;
    int frow = (mat & 1) * 8 + flrow;
    int fk   = (mat >> 1) * 8;

    if (tid < 128) colsq[tid] = 0.f;

    load_stage(0, 0);
    CP_COMMIT();

    for (int kt = 0; kt < 16; kt++) {
        if (kt < 15) {
            load_stage((kt + 1) & 1, (kt + 1) * 32);
            CP_COMMIT();
            CP_WAIT1();
        } else {
            CP_WAIT0();
        }
        __syncthreads();
        uint32_t stb = sb + (kt & 1) * OSTAGE;

#pragma unroll
        for (int ks = 0; ks < 2; ks++) {
            int kk = ks * 16 + fk;
            uint32_t fa1[4][4], fa2[4][4];
#pragma unroll
            for (int mi = 0; mi < 4; mi++) {
                uint32_t off = (uint32_t)((mwarp + mi * 16 + frow) * (OLDK * 2) + kk * 2);
                ldm4(fa1[mi], stb + O_A1 + off);
                ldm4(fa2[mi], stb + O_A2 + off);
            }
            uint32_t fb1[4][4], fb2[4][4];
#pragma unroll
            for (int nb = 0; nb < 4; nb++) {
                uint32_t off = (uint32_t)((nwarp + nb * 16 + frow) * (OLDK * 2) + kk * 2);
                ldm4(fb1[nb], stb + O_B1 + off);
                ldm4(fb2[nb], stb + O_B2 + off);
            }
#pragma unroll
            for (int mi = 0; mi < 4; mi++)
#pragma unroll
                for (int nf = 0; nf < 8; nf++) {
                    int nb = nf >> 1, hi = nf & 1;
                    mma_bf16(acc[mi][nf], fa1[mi], fb1[nb][hi], fb1[nb][hi + 2]);
                    mma_bf16(acc[mi][nf], fa1[mi], fb2[nb][hi], fb2[nb][hi + 2]);
                    mma_bf16(acc[mi][nf], fa2[mi], fb1[nb][hi], fb1[nb][hi + 2]);
                }
        }
        __syncthreads();
    }

    // bias + column sum-of-squares
    float cs0[8], cs1[8];
#pragma unroll
    for (int nf = 0; nf < 8; nf++) { cs0[nf] = 0.f; cs1[nf] = 0.f; }
#pragma unroll
    for (int mi = 0; mi < 4; mi++) {
        int row = mwarp + mi * 16 + (lane >> 2);
        float bi0 = bias[row], bi1 = bias[row + 8];
#pragma unroll
        for (int nf = 0; nf < 8; nf++) {
            acc[mi][nf][0] += bi0;
            acc[mi][nf][1] += bi0;
            acc[mi][nf][2] += bi1;
            acc[mi][nf][3] += bi1;
            cs0[nf] += acc[mi][nf][0] * acc[mi][nf][0] + acc[mi][nf][2] * acc[mi][nf][2];
            cs1[nf] += acc[mi][nf][1] * acc[mi][nf][1] + acc[mi][nf][3] * acc[mi][nf][3];
        }
    }
#pragma unroll
    for (int nf = 0; nf < 8; nf++) {
#pragma unroll
        for (int o = 4; o < 32; o <<= 1) {
            cs0[nf] += __shfl_xor_sync(0xFFFFFFFFu, cs0[nf], o);
            cs1[nf] += __shfl_xor_sync(0xFFFFFFFFu, cs1[nf], o);
        }
    }
    if (lane < 4) {
#pragma unroll
        for (int nf = 0; nf < 8; nf++) {
            int col = nwarp + nf * 8 + lane * 2;
            atomicAdd(&colsq[col], cs0[nf]);
            atomicAdd(&colsq[col + 1], cs1[nf]);
        }
    }
    __syncthreads();
    if (tid < 128) invs[tid] = 16.0f / fmaxf(sqrtf(colsq[tid]), 1e-12f);
    __syncthreads();

    float* ob = out + (size_t)b * CIN * HW + pos0;
#pragma unroll
    for (int mi = 0; mi < 4; mi++) {
        int row = mwarp + mi * 16 + (lane >> 2);
        float gr0 = gout[row], gr1 = gout[row + 8];
#pragma unroll
        for (int nf = 0; nf < 8; nf++) {
            int col = nwarp + nf * 8 + (lane & 3) * 2;
            float i0 = invs[col], i1 = invs[col + 1];
            *(float2*)(ob + (size_t)row * HW + col) =
                make_float2(acc[mi][nf][0] * i0 * gr0, acc[mi][nf][1] * i1 * gr0);
            *(float2*)(ob + (size_t)(row + 8) * HW + col) =
                make_float2(acc[mi][nf][2] * i0 * gr1, acc[mi][nf][3] * i1 * gr1);
        }
    }
}

// ---------------------------------------------------------------------------
extern "C" void kernel_launch(void* const* d_in, const int* in_sizes, int n_in,
                              void* d_out, int out_size) {
    const float* x      = (const float*)d_in[0];
    const float* g_in   = (const float*)d_in[1];
    const float* w_qkv  = (const float*)d_in[2];
    const float* mem_kv = (const float*)d_in[3];
    const float* w_out  = (const float*)d_in[4];
    const float* b_out  = (const float*)d_in[5];
    const float* g_out  = (const float*)d_in[6];
    float* out = (float*)d_out;

    float *s_ptr, *qkv_ptr, *rmax_ptr, *rinv_ptr, *part_ptr, *ctx_ptr;
    __nv_bfloat16 *w1_ptr, *w2_ptr, *wo1_ptr, *wo2_ptr, *x1_ptr, *x2_ptr, *a1_ptr, *a2_ptr;
    cudaGetSymbolAddress((void**)&s_ptr,    g_s);
    cudaGetSymbolAddress((void**)&w1_ptr,   g_w1);
    cudaGetSymbolAddress((void**)&w2_ptr,   g_w2);
    cudaGetSymbolAddress((void**)&wo1_ptr,  g_wo1);
    cudaGetSymbolAddress((void**)&wo2_ptr,  g_wo2);
    cudaGetSymbolAddress((void**)&x1_ptr,   g_x1);
    cudaGetSymbolAddress((void**)&x2_ptr,   g_x2);
    cudaGetSymbolAddress((void**)&qkv_ptr,  g_qkv);
    cudaGetSymbolAddress((void**)&rmax_ptr, g_rmax);
    cudaGetSymbolAddress((void**)&rinv_ptr, g_rinv);
    cudaGetSymbolAddress((void**)&part_ptr, g_part);
    cudaGetSymbolAddress((void**)&ctx_ptr,  g_ctx);
    cudaGetSymbolAddress((void**)&a1_ptr,   g_a1);
    cudaGetSymbolAddress((void**)&a2_ptr,   g_a2);

    cudaFuncSetAttribute(qkv_mma_kernel,
                         cudaFuncAttributeMaxDynamicSharedMemorySize, QSMTOT);
    cudaFuncSetAttribute(outnorm_mma_kernel,
                         cudaFuncAttributeMaxDynamicSharedMemorySize, OSMTOT);

    colscale_kernel<<<(BATCH * HW + 255) / 256, 256>>>(x, s_ptr);
    wconv_kernel<<<(O3 * CIN + 255) / 256, 256>>>(w_qkv, g_in, w1_ptr, w2_ptr);
    woconv_kernel<<<(CIN * HID + 255) / 256, 256>>>(w_out, wo1_ptr, wo2_ptr);
    xconv_kernel<<<dim3(HW / 32, CIN / 32, BATCH), 256>>>(x, s_ptr, x1_ptr, x2_ptr);
    qkv_mma_kernel<<<dim3(HW / 128, O3 / 256, BATCH), 256, QSMTOT>>>(
        w1_ptr, w2_ptr, x1_ptr, x2_ptr, qkv_ptr);
    kstats_kernel<<<dim3(HD, NH, BATCH), 256>>>(qkv_ptr, mem_kv, rmax_ptr, rinv_ptr);
    ctxpart_kernel<<<dim3(NC, NH, BATCH), 256>>>(qkv_ptr, rmax_ptr, part_ptr);
    ctxreduce_kernel<<<dim3(NH, BATCH), 256>>>(part_ptr, mem_kv, rmax_ptr, rinv_ptr, ctx_ptr);
    attend_kernel<<<dim3(HW / 64, NH, BATCH), 256>>>(qkv_ptr, ctx_ptr, a1_ptr, a2_ptr);
    outnorm_mma_kernel<<<dim3(HW / 128, BATCH), 256, OSMTOT>>>(
        wo1_ptr, wo2_ptr, a1_ptr, a2_ptr, b_out, g_out, out);
}

// round 9
// speedup vs baseline: 1.1352x; 1.0264x over previous
#include <cuda_runtime.h>
#include <cuda_bf16.h>
#include <math.h>
#include <stdint.h>
#include <string.h>

// Problem constants
#define BATCH 16
#define CIN   256
#define HW    4096
#define O3    1536
#define HID   512
#define NH    8
#define HD    64
#define NMEM  4
#define NC    8
#define CHUNK 512

typedef unsigned long long u64;

// Scratch (device globals — allocation-free rule)
__device__ float g_s[BATCH * HW];
__device__ __nv_bfloat16 g_w1[O3 * CIN];
__device__ __nv_bfloat16 g_w2[O3 * CIN];
__device__ __nv_bfloat16 g_wo1[CIN * HID];
__device__ __nv_bfloat16 g_wo2[CIN * HID];
__device__ __nv_bfloat16 g_x1[(size_t)BATCH * HW * CIN];   // transposed [b][n][c]
__device__ __nv_bfloat16 g_x2[(size_t)BATCH * HW * CIN];
__device__ float g_qkv[(size_t)BATCH * O3 * HW];           // 402 MB
__device__ float g_rmax[BATCH * NH * HD];
__device__ float g_rinv[BATCH * NH * HD];
__device__ float g_part[(size_t)NC * BATCH * NH * HD * HD];
__device__ float g_ctx[BATCH * NH * HD * HD];
__device__ __nv_bfloat16 g_a1[(size_t)BATCH * HW * HID];   // att^T split [b][pos][hid]
__device__ __nv_bfloat16 g_a2[(size_t)BATCH * HW * HID];

// ---- packed f32x2 helpers ------------------------------------------------
__device__ __forceinline__ u64 pack_dup(float v) {
    u64 r; asm("mov.b64 %0, {%1, %2};" : "=l"(r) : "f"(v), "f"(v)); return r;
}
__device__ __forceinline__ void ffma2(u64& d, u64 a, u64 b) {
    asm("fma.rn.f32x2 %0, %1, %2, %0;" : "+l"(d) : "l"(a), "l"(b));
}
__device__ __forceinline__ float2 unpack2(u64 v) {
    float2 f; asm("mov.b64 {%0, %1}, %2;" : "=f"(f.x), "=f"(f.y) : "l"(v)); return f;
}

// ---- mma.sync helpers ------------------------------------------------------
__device__ __forceinline__ uint32_t smem_u32(const void* p) {
    uint32_t a;
    asm("{ .reg .u64 t; cvta.to.shared.u64 t, %1; cvt.u32.u64 %0, t; }"
        : "=r"(a) : "l"(p));
    return a;
}
__device__ __forceinline__ void ldm4(uint32_t* r, uint32_t addr) {
    asm volatile("ldmatrix.sync.aligned.m8n8.x4.shared.b16 {%0,%1,%2,%3}, [%4];"
                 : "=r"(r[0]), "=r"(r[1]), "=r"(r[2]), "=r"(r[3]) : "r"(addr));
}
__device__ __forceinline__ void mma_bf16(float* c, const uint32_t* a,
                                         uint32_t b0, uint32_t b1) {
    asm volatile(
        "mma.sync.aligned.m16n8k16.row.col.f32.bf16.bf16.f32 "
        "{%0,%1,%2,%3}, {%4,%5,%6,%7}, {%8,%9}, {%0,%1,%2,%3};"
        : "+f"(c[0]), "+f"(c[1]), "+f"(c[2]), "+f"(c[3])
        : "r"(a[0]), "r"(a[1]), "r"(a[2]), "r"(a[3]), "r"(b0), "r"(b1));
}
__device__ __forceinline__ void cp16(uint32_t dst, const void* src) {
    asm volatile("cp.async.cg.shared.global [%0], [%1], 16;"
                 :: "r"(dst), "l"(src));
}
#define CP_COMMIT() asm volatile("cp.async.commit_group;" ::: "memory")
#define CP_WAIT1()  asm volatile("cp.async.wait_group 1;" ::: "memory")
#define CP_WAIT0()  asm volatile("cp.async.wait_group 0;" ::: "memory")

__device__ __forceinline__ uint32_t pkbf(float lo, float hi) {
    __nv_bfloat162 t = __floats2bfloat162_rn(lo, hi);
    uint32_t r; memcpy(&r, &t, 4); return r;
}

// ---------------------------------------------------------------------------
// Kernel 1: per-position rmsnorm scale
// ---------------------------------------------------------------------------
__global__ __launch_bounds__(256) void colscale_kernel(const float* __restrict__ x,
                                                       float* __restrict__ s) {
    int idx = blockIdx.x * 256 + threadIdx.x;
    if (idx >= BATCH * HW) return;
    int b = idx >> 12, pos = idx & (HW - 1);
    const float* p = x + (size_t)b * CIN * HW + pos;
    float acc = 0.f;
#pragma unroll 8
    for (int c = 0; c < CIN; c++) {
        float v = p[(size_t)c * HW];
        acc += v * v;
    }
    s[idx] = 16.0f / fmaxf(sqrtf(acc), 1e-12f);
}

// ---------------------------------------------------------------------------
// Kernel 1b: W fold + bf16 2-way split
// ---------------------------------------------------------------------------
__global__ __launch_bounds__(256) void wconv_kernel(const float* __restrict__ w,
                                                    const float* __restrict__ g,
                                                    __nv_bfloat16* __restrict__ w1,
                                                    __nv_bfloat16* __restrict__ w2) {
    int i = blockIdx.x * 256 + threadIdx.x;
    if (i >= O3 * CIN) return;
    float wg = w[i] * g[i & (CIN - 1)];
    __nv_bfloat16 h = __float2bfloat16_rn(wg);
    w1[i] = h;
    w2[i] = __float2bfloat16_rn(wg - __bfloat162float(h));
}

// Kernel 1b2: w_out bf16 2-way split
__global__ __launch_bounds__(256) void woconv_kernel(const float* __restrict__ w,
                                                     __nv_bfloat16* __restrict__ w1,
                                                     __nv_bfloat16* __restrict__ w2) {
    int i = blockIdx.x * 256 + threadIdx.x;
    if (i >= CIN * HID) return;
    float v = w[i];
    __nv_bfloat16 h = __float2bfloat16_rn(v);
    w1[i] = h;
    w2[i] = __float2bfloat16_rn(v - __bfloat162float(h));
}

// ---------------------------------------------------------------------------
// Kernel 1c: X transpose to [b][n][c], fold rmsnorm scale, bf16 2-way split
// ---------------------------------------------------------------------------
__global__ __launch_bounds__(256) void xconv_kernel(const float* __restrict__ x,
                                                    const float* __restrict__ s,
                                                    __nv_bfloat16* __restrict__ x1,
                                                    __nv_bfloat16* __restrict__ x2) {
    int b = blockIdx.z;
    int c0 = blockIdx.y * 32, n0 = blockIdx.x * 32;
    __shared__ float t[32][33];
    int tid = threadIdx.x;
    int tx = tid & 31, ty = tid >> 5;
#pragma unroll
    for (int i = 0; i < 4; i++) {
        int c = ty + i * 8;
        t[c][tx] = x[((size_t)b * CIN + c0 + c) * HW + n0 + tx];
    }
    __syncthreads();
#pragma unroll
    for (int i = 0; i < 4; i++) {
        int nr = ty + i * 8;
        float sv = s[b * HW + n0 + nr];
        float v = t[tx][nr] * sv;
        __nv_bfloat16 h = __float2bfloat16_rn(v);
        size_t o = ((size_t)b * HW + n0 + nr) * CIN + c0 + tx;
        x1[o] = h;
        x2[o] = __float2bfloat16_rn(v - __bfloat162float(h));
    }
}

// ---------------------------------------------------------------------------
// Kernel 2: QKV GEMM, mma.sync bf16 split, cp.async double-buffered.
// CTA tile 128x128, K-tile 32, LDK=40 -> 80KB smem -> 2 CTAs/SM.
// 8 warps (4m x 2n), warp tile 32x64, fragment-scoped register use.
// ---------------------------------------------------------------------------
#define QLDK   40
#define QT_B   (128 * QLDK * 2)        // 10240 per split tile
#define QSTAGE (4 * QT_B)              // 40960
#define QSMTOT (2 * QSTAGE)            // 81920
#define Q_A1   0
#define Q_A2   QT_B
#define Q_B1   (2 * QT_B)
#define Q_B2   (3 * QT_B)

__global__ void __launch_bounds__(256, 2)
qkv_mma_kernel(const __nv_bfloat16* __restrict__ w1,
               const __nv_bfloat16* __restrict__ w2,
               const __nv_bfloat16* __restrict__ x1,
               const __nv_bfloat16* __restrict__ x2,
               float* __restrict__ out) {
    extern __shared__ char smem[];
    uint32_t sb = smem_u32(smem);
    int tid = threadIdx.x;
    int warp = tid >> 5, lane = tid & 31;
    int b = blockIdx.z;
    int rowBase = blockIdx.y * 128;
    int colBase = blockIdx.x * 128;

    const char* srcA1 = (const char*)(w1 + (size_t)rowBase * CIN);
    const char* srcA2 = (const char*)(w2 + (size_t)rowBase * CIN);
    const char* srcB1 = (const char*)(x1 + ((size_t)b * HW + colBase) * CIN);
    const char* srcB2 = (const char*)(x2 + ((size_t)b * HW + colBase) * CIN);

    int lrow = tid >> 2, lseg = tid & 3;   // 64 rows x 4 segs (32 k = 64B) per pass

    auto load_stage = [&](int st, int k0) {
        uint32_t dbase = sb + st * QSTAGE;
#pragma unroll
        for (int j = 0; j < 2; j++) {
            int row = lrow + j * 64;
            uint32_t dp = dbase + row * (QLDK * 2) + lseg * 16;
            const char* o1 = srcA1 + (size_t)row * (CIN * 2) + k0 * 2 + lseg * 16;
            const char* o2 = srcA2 + (size_t)row * (CIN * 2) + k0 * 2 + lseg * 16;
            const char* o3 = srcB1 + (size_t)row * (CIN * 2) + k0 * 2 + lseg * 16;
            const char* o4 = srcB2 + (size_t)row * (CIN * 2) + k0 * 2 + lseg * 16;
            cp16(dp + Q_A1, o1);
            cp16(dp + Q_A2, o2);
            cp16(dp + Q_B1, o3);
            cp16(dp + Q_B2, o4);
        }
    };

    int mwarp = (warp >> 1) * 32;
    int nwarp = (warp & 1) * 64;

    float acc[2][8][4];
#pragma unroll
    for (int mi = 0; mi < 2; mi++)
#pragma unroll
        for (int nf = 0; nf < 8; nf++)
#pragma unroll
            for (int q = 0; q < 4; q++) acc[mi][nf][q] = 0.f;

    int flrow = lane & 7, mat = lane >> 3;
    int frow = (mat & 1) * 8 + flrow;
    int fk   = (mat >> 1) * 8;

    load_stage(0, 0);
    CP_COMMIT();

    for (int kt = 0; kt < 8; kt++) {
        if (kt < 7) {
            load_stage((kt + 1) & 1, (kt + 1) * 32);
            CP_COMMIT();
            CP_WAIT1();
        } else {
            CP_WAIT0();
        }
        __syncthreads();
        uint32_t stb = sb + (kt & 1) * QSTAGE;

#pragma unroll
        for (int ks = 0; ks < 2; ks++) {
            int kk = ks * 16 + fk;
            uint32_t fa1[2][4], fb1[4][4];
#pragma unroll
            for (int mi = 0; mi < 2; mi++)
                ldm4(fa1[mi], stb + Q_A1 +
                     (uint32_t)((mwarp + mi * 16 + frow) * (QLDK * 2) + kk * 2));
#pragma unroll
            for (int nb = 0; nb < 4; nb++)
                ldm4(fb1[nb], stb + Q_B1 +
                     (uint32_t)((nwarp + nb * 16 + frow) * (QLDK * 2) + kk * 2));
#pragma unroll
            for (int mi = 0; mi < 2; mi++)
#pragma unroll
                for (int nf = 0; nf < 8; nf++)
                    mma_bf16(acc[mi][nf], fa1[mi], fb1[nf >> 1][nf & 1], fb1[nf >> 1][(nf & 1) + 2]);
            {
                uint32_t fa2[2][4];
#pragma unroll
                for (int mi = 0; mi < 2; mi++)
                    ldm4(fa2[mi], stb + Q_A2 +
                         (uint32_t)((mwarp + mi * 16 + frow) * (QLDK * 2) + kk * 2));
#pragma unroll
                for (int mi = 0; mi < 2; mi++)
#pragma unroll
                    for (int nf = 0; nf < 8; nf++)
                        mma_bf16(acc[mi][nf], fa2[mi], fb1[nf >> 1][nf & 1], fb1[nf >> 1][(nf & 1) + 2]);
            }
            {
                uint32_t fb2[4][4];
#pragma unroll
                for (int nb = 0; nb < 4; nb++)
                    ldm4(fb2[nb], stb + Q_B2 +
                         (uint32_t)((nwarp + nb * 16 + frow) * (QLDK * 2) + kk * 2));
#pragma unroll
                for (int mi = 0; mi < 2; mi++)
#pragma unroll
                    for (int nf = 0; nf < 8; nf++)
                        mma_bf16(acc[mi][nf], fa1[mi], fb2[nf >> 1][nf & 1], fb2[nf >> 1][(nf & 1) + 2]);
            }
        }
        __syncthreads();
    }

    float* obase = out + (size_t)b * O3 * HW;
#pragma unroll
    for (int mi = 0; mi < 2; mi++) {
        int row = rowBase + mwarp + mi * 16 + (lane >> 2);
#pragma unroll
        for (int nf = 0; nf < 8; nf++) {
            int col = colBase + nwarp + nf * 8 + (lane & 3) * 2;
            *(float2*)(obase + (size_t)row * HW + col) =
                make_float2(acc[mi][nf][0], acc[mi][nf][1]);
            *(float2*)(obase + (size_t)(row + 8) * HW + col) =
                make_float2(acc[mi][nf][2], acc[mi][nf][3]);
        }
    }
}

// ---------------------------------------------------------------------------
// Kernel 3a: k-softmax stats per (b,h,d) row
// ---------------------------------------------------------------------------
__global__ __launch_bounds__(256) void kstats_kernel(const float* __restrict__ qkv,
                                                     const float* __restrict__ memkv,
                                                     float* __restrict__ rmax,
                                                     float* __restrict__ rinv) {
    int d = blockIdx.x, h = blockIdx.y, b = blockIdx.z;
    int tid = threadIdx.x;
    const float* kr = qkv + ((size_t)b * O3 + HID + h * HD + d) * HW;
    const float* MK = memkv + ((size_t)h * HD + d) * NMEM;

    float v[16];
#pragma unroll
    for (int i = 0; i < 16; i++) v[i] = kr[i * 256 + tid];
    float m = v[0];
#pragma unroll
    for (int i = 1; i < 16; i++) m = fmaxf(m, v[i]);
    if (tid < NMEM) m = fmaxf(m, MK[tid]);

    __shared__ float red[8];
#pragma unroll
    for (int o = 16; o; o >>= 1) m = fmaxf(m, __shfl_xor_sync(0xFFFFFFFFu, m, o));
    if ((tid & 31) == 0) red[tid >> 5] = m;
    __syncthreads();
    if (tid == 0) {
        float t = red[0];
#pragma unroll
        for (int i = 1; i < 8; i++) t = fmaxf(t, red[i]);
        red[0] = t;
    }
    __syncthreads();
    m = red[0];
    __syncthreads();

    float ss = 0.f;
#pragma unroll
    for (int i = 0; i < 16; i++) ss += __expf(v[i] - m);
    if (tid < NMEM) ss += __expf(MK[tid] - m);
#pragma unroll
    for (int o = 16; o; o >>= 1) ss += __shfl_xor_sync(0xFFFFFFFFu, ss, o);
    if ((tid & 31) == 0) red[tid >> 5] = ss;
    __syncthreads();
    if (tid == 0) {
        float t = 0.f;
#pragma unroll
        for (int i = 0; i < 8; i++) t += red[i];
        int idx = (b * NH + h) * HD + d;
        rmax[idx] = m;
        rinv[idx] = 1.0f / t;
    }
}

// ---------------------------------------------------------------------------
// Kernel 3b: partial context over n chunks (FFMA2 SIMT — proven fastest)
// ---------------------------------------------------------------------------
__global__ __launch_bounds__(256) void ctxpart_kernel(const float* __restrict__ qkv,
                                                      const float* __restrict__ rmax,
                                                      float* __restrict__ part) {
    int c = blockIdx.x, h = blockIdx.y, b = blockIdx.z;
    const float* K = qkv + ((size_t)b * O3 + HID + h * HD) * HW;
    const float* V = qkv + ((size_t)b * O3 + 2 * HID + h * HD) * HW;

    __shared__ __align__(16) float Kt[64][68];
    __shared__ __align__(16) float Vt[64][68];
    __shared__ float rm[64];

    int tid = threadIdx.x;
    if (tid < 64) rm[tid] = rmax[(b * NH + h) * HD + tid];
    __syncthreads();

    int tx = tid & 15, ty = tid >> 4;
    u64 acc[4][2];
#pragma unroll
    for (int i = 0; i < 4; i++) { acc[i][0] = 0ULL; acc[i][1] = 0ULL; }

    for (int nt = 0; nt < CHUNK / 64; nt++) {
        int n0 = c * CHUNK + nt * 64;
#pragma unroll
        for (int l = 0; l < 16; l++) {
            int lin = l * 256 + tid;
            int d = lin >> 6, j = lin & 63;
            Kt[j][d] = __expf(K[(size_t)d * HW + n0 + j] - rm[d]);
            Vt[j][d] = V[(size_t)d * HW + n0 + j];
        }
        __syncthreads();
#pragma unroll 4
        for (int j = 0; j < 64; j++) {
            float4 kf = *(const float4*)(&Kt[j][ty * 4]);
            u64 k0 = pack_dup(kf.x), k1 = pack_dup(kf.y);
            u64 k2 = pack_dup(kf.z), k3 = pack_dup(kf.w);
            ulonglong2 vv = *(const ulonglong2*)(&Vt[j][tx * 4]);
            ffma2(acc[0][0], k0, vv.x); ffma2(acc[0][1], k0, vv.y);
            ffma2(acc[1][0], k1, vv.x); ffma2(acc[1][1], k1, vv.y);
            ffma2(acc[2][0], k2, vv.x); ffma2(acc[2][1], k2, vv.y);
            ffma2(acc[3][0], k3, vv.x); ffma2(acc[3][1], k3, vv.y);
        }
        __syncthreads();
    }

    float* pb = part + ((size_t)c * BATCH * NH + b * NH + h) * (HD * HD);
#pragma unroll
    for (int i = 0; i < 4; i++) {
        float2 a = unpack2(acc[i][0]);
        float2 bb = unpack2(acc[i][1]);
        *(float4*)(&pb[(ty * 4 + i) * HD + tx * 4]) = make_float4(a.x, a.y, bb.x, bb.y);
    }
}

// ---------------------------------------------------------------------------
// Kernel 3c: reduce partials + mem-kv tail + rinv scaling -> ctx
// ---------------------------------------------------------------------------
__global__ __launch_bounds__(256) void ctxreduce_kernel(const float* __restrict__ part,
                                                        const float* __restrict__ memkv,
                                                        const float* __restrict__ rmax,
                                                        const float* __restrict__ rinv,
                                                        float* __restrict__ ctx) {
    int h = blockIdx.x, b = blockIdx.y;
    __shared__ float mkx[64][4];
    __shared__ float mvs[64][4];
    __shared__ float riv[64];
    int tid = threadIdx.x;
    if (tid < 64) riv[tid] = rinv[(b * NH + h) * HD + tid];
    {
        int d = tid >> 2, j = tid & 3;
        mkx[d][j] = __expf(memkv[((size_t)h * HD + d) * NMEM + j] -
                           rmax[(b * NH + h) * HD + d]);
        mvs[d][j] = memkv[(size_t)NH * HD * NMEM + ((size_t)h * HD + d) * NMEM + j];
    }
    __syncthreads();
    size_t base = (size_t)(b * NH + h) * (HD * HD);
    for (int l = tid; l < HD * HD; l += 256) {
        int d = l >> 6, e = l & 63;
        float s2 = 0.f;
#pragma unroll
        for (int cc = 0; cc < NC; cc++)
            s2 += part[(size_t)cc * BATCH * NH * HD * HD + base + l];
#pragma unroll
        for (int j = 0; j < 4; j++) s2 += mkx[d][j] * mvs[e][j];
        ctx[base + l] = s2 * riv[d];
    }
}

// ---------------------------------------------------------------------------
// Kernel 4: q-softmax + out[e][p] = sum_d ctx[d][e]*qs[d][p]; writes bf16
// splits TRANSPOSED [b][pos][hid] for the tensorized outnorm.
// ---------------------------------------------------------------------------
__global__ __launch_bounds__(256) void attend_kernel(const float* __restrict__ qkv,
                                                     const float* __restrict__ ctx,
                                                     __nv_bfloat16* __restrict__ a1,
                                                     __nv_bfloat16* __restrict__ a2) {
    int pos0 = blockIdx.x * 64;
    int h = blockIdx.y, b = blockIdx.z;
    const float* Q = qkv + ((size_t)b * O3 + h * HD) * HW;
    const float* cb = ctx + (size_t)(b * NH + h) * HD * HD;

    __shared__ __align__(16) float cs[64][68];
    __shared__ __align__(16) float qs[64][68];

    int tid = threadIdx.x;
    for (int l = tid; l < HD * HD; l += 256) {
        int d = l >> 6, e = l & 63;
        cs[d][e] = cb[l];
        qs[d][e] = Q[(size_t)d * HW + pos0 + e];
    }
    __syncthreads();

    if (tid < 64) {
        float m = -1e30f;
#pragma unroll
        for (int d = 0; d < HD; d++) m = fmaxf(m, qs[d][tid]);
        float ss = 0.f;
#pragma unroll
        for (int d = 0; d < HD; d++) ss += __expf(qs[d][tid] - m);
        float inv = 0.125f / ss;
#pragma unroll
        for (int d = 0; d < HD; d++)
            qs[d][tid] = __expf(qs[d][tid] - m) * inv;
    }
    __syncthreads();

    int tx = tid & 15, ty = tid >> 4;
    u64 acc[4][2];
#pragma unroll
    for (int i = 0; i < 4; i++) { acc[i][0] = 0ULL; acc[i][1] = 0ULL; }

#pragma unroll 4
    for (int d = 0; d < HD; d++) {
        float4 cf = *(const float4*)(&cs[d][ty * 4]);
        u64 c0 = pack_dup(cf.x), c1 = pack_dup(cf.y);
        u64 c2 = pack_dup(cf.z), c3 = pack_dup(cf.w);
        ulonglong2 qq = *(const ulonglong2*)(&qs[d][tx * 4]);
        ffma2(acc[0][0], c0, qq.x); ffma2(acc[0][1], c0, qq.y);
        ffma2(acc[1][0], c1, qq.x); ffma2(acc[1][1], c1, qq.y);
        ffma2(acc[2][0], c2, qq.x); ffma2(acc[2][1], c2, qq.y);
        ffma2(acc[3][0], c3, qq.x); ffma2(acc[3][1], c3, qq.y);
    }

    // Stage transposed result into cs as os[pos][e]
    __syncthreads();
#pragma unroll
    for (int i = 0; i < 4; i++) {
        float2 a = unpack2(acc[i][0]);
        float2 bb = unpack2(acc[i][1]);
        int e = ty * 4 + i;
        cs[tx * 4 + 0][e] = a.x;
        cs[tx * 4 + 1][e] = a.y;
        cs[tx * 4 + 2][e] = bb.x;
        cs[tx * 4 + 3][e] = bb.y;
    }
    __syncthreads();

    {
        int pos = tid >> 2, e0 = (tid & 3) * 16;
        size_t base = ((size_t)b * HW + pos0 + pos) * HID + h * HD + e0;
        uint32_t r1[8], r2[8];
#pragma unroll
        for (int u = 0; u < 8; u++) {
            float v0 = cs[pos][e0 + 2 * u], v1 = cs[pos][e0 + 2 * u + 1];
            __nv_bfloat16 h0 = __float2bfloat16_rn(v0);
            __nv_bfloat16 h1 = __float2bfloat16_rn(v1);
            r1[u] = pkbf(v0, v1);
            r2[u] = pkbf(v0 - __bfloat162float(h0), v1 - __bfloat162float(h1));
        }
        *(uint4*)((char*)a1 + base * 2)      = make_uint4(r1[0], r1[1], r1[2], r1[3]);
        *(uint4*)((char*)a1 + base * 2 + 16) = make_uint4(r1[4], r1[5], r1[6], r1[7]);
        *(uint4*)((char*)a2 + base * 2)      = make_uint4(r2[0], r2[1], r2[2], r2[3]);
        *(uint4*)((char*)a2 + base * 2 + 16) = make_uint4(r2[4], r2[5], r2[6], r2[7]);
    }
}

// ---------------------------------------------------------------------------
// Kernel 5: out GEMM via mma.sync bf16 split + bias + fused rmsnorm.
// CTA tile 256x64, K-tile 32, LDK=40 -> 100KB smem -> 2 CTAs/SM.
// 8 warps (4m x 2n), warp tile 64x32.
// ---------------------------------------------------------------------------
#define OLDK   40
#define OA_T   (256 * OLDK * 2)        // 20480 per A split
#define OB_T   (64 * OLDK * 2)         // 5120 per B split
#define OSTAGE (2 * OA_T + 2 * OB_T)   // 51200
#define OSMTOT (2 * OSTAGE)            // 102400
#define O_A1   0
#define O_A2   OA_T
#define O_B1   (2 * OA_T)
#define O_B2   (2 * OA_T + OB_T)

__global__ void __launch_bounds__(256, 2)
outnorm_mma_kernel(const __nv_bfloat16* __restrict__ wo1,
                   const __nv_bfloat16* __restrict__ wo2,
                   const __nv_bfloat16* __restrict__ a1,
                   const __nv_bfloat16* __restrict__ a2,
                   const float* __restrict__ bias,
                   const float* __restrict__ gout,
                   float* __restrict__ out) {
    extern __shared__ char smem[];
    uint32_t sb = smem_u32(smem);
    __shared__ float colsq[64];
    __shared__ float invs[64];

    int tid = threadIdx.x;
    int warp = tid >> 5, lane = tid & 31;
    int b = blockIdx.y;
    int pos0 = blockIdx.x * 64;

    const char* srcA1 = (const char*)wo1;
    const char* srcA2 = (const char*)wo2;
    const char* srcB1 = (const char*)(a1 + ((size_t)b * HW + pos0) * HID);
    const char* srcB2 = (const char*)(a2 + ((size_t)b * HW + pos0) * HID);

    int lrow = tid >> 2, lseg = tid & 3;   // 64 rows x 4 segs per pass

    auto load_stage = [&](int st, int k0) {
        uint32_t dbase = sb + st * OSTAGE;
#pragma unroll
        for (int j = 0; j < 4; j++) {      // A: 256 rows
            int row = lrow + j * 64;
            uint32_t dp = dbase + row * (OLDK * 2) + lseg * 16;
            cp16(dp + O_A1, srcA1 + (size_t)row * (HID * 2) + k0 * 2 + lseg * 16);
            cp16(dp + O_A2, srcA2 + (size_t)row * (HID * 2) + k0 * 2 + lseg * 16);
        }
        {                                  // B: 64 rows
            int row = lrow;
            uint32_t dp = dbase + row * (OLDK * 2) + lseg * 16;
            cp16(dp + O_B1, srcB1 + (size_t)row * (HID * 2) + k0 * 2 + lseg * 16);
            cp16(dp + O_B2, srcB2 + (size_t)row * (HID * 2) + k0 * 2 + lseg * 16);
        }
    };

    int mwarp = (warp >> 1) * 64;
    int nwarp = (warp & 1) * 32;

    float acc[4][4][4];
#pragma unroll
    for (int mi = 0; mi < 4; mi++)
#pragma unroll
        for (int nf = 0; nf < 4; nf++)
#pragma unroll
            for (int q = 0; q < 4; q++) acc[mi][nf][q] = 0.f;

    int flrow = lane & 7, mat = lane >> 3;
    int frow = (mat & 1) * 8 + flrow;
    int fk   = (mat >> 1) * 8;

    if (tid < 64) colsq[tid] = 0.f;

    load_stage(0, 0);
    CP_COMMIT();

    for (int kt = 0; kt < 16; kt++) {
        if (kt < 15) {
            load_stage((kt + 1) & 1, (kt + 1) * 32);
            CP_COMMIT();
            CP_WAIT1();
        } else {
            CP_WAIT0();
        }
        __syncthreads();
        uint32_t stb = sb + (kt & 1) * OSTAGE;

#pragma unroll
        for (int ks = 0; ks < 2; ks++) {
            int kk = ks * 16 + fk;
            uint32_t fa1[4][4], fb1[2][4];
#pragma unroll
            for (int mi = 0; mi < 4; mi++)
                ldm4(fa1[mi], stb + O_A1 +
                     (uint32_t)((mwarp + mi * 16 + frow) * (OLDK * 2) + kk * 2));
#pragma unroll
            for (int nb = 0; nb < 2; nb++)
                ldm4(fb1[nb], stb + O_B1 +
                     (uint32_t)((nwarp + nb * 16 + frow) * (OLDK * 2) + kk * 2));
#pragma unroll
            for (int mi = 0; mi < 4; mi++)
#pragma unroll
                for (int nf = 0; nf < 4; nf++)
                    mma_bf16(acc[mi][nf], fa1[mi], fb1[nf >> 1][nf & 1], fb1[nf >> 1][(nf & 1) + 2]);
            {
                uint32_t fa2[4][4];
#pragma unroll
                for (int mi = 0; mi < 4; mi++)
                    ldm4(fa2[mi], stb + O_A2 +
                         (uint32_t)((mwarp + mi * 16 + frow) * (OLDK * 2) + kk * 2));
#pragma unroll
                for (int mi = 0; mi < 4; mi++)
#pragma unroll
                    for (int nf = 0; nf < 4; nf++)
                        mma_bf16(acc[mi][nf], fa2[mi], fb1[nf >> 1][nf & 1], fb1[nf >> 1][(nf & 1) + 2]);
            }
            {
                uint32_t fb2[2][4];
#pragma unroll
                for (int nb = 0; nb < 2; nb++)
                    ldm4(fb2[nb], stb + O_B2 +
                         (uint32_t)((nwarp + nb * 16 + frow) * (OLDK * 2) + kk * 2));
#pragma unroll
                for (int mi = 0; mi < 4; mi++)
#pragma unroll
                    for (int nf = 0; nf < 4; nf++)
                        mma_bf16(acc[mi][nf], fa1[mi], fb2[nf >> 1][nf & 1], fb2[nf >> 1][(nf & 1) + 2]);
            }
        }
        __syncthreads();
    }

    // bias + column sum-of-squares
    float cs0[4], cs1[4];
#pragma unroll
    for (int nf = 0; nf < 4; nf++) { cs0[nf] = 0.f; cs1[nf] = 0.f; }
#pragma unroll
    for (int mi = 0; mi < 4; mi++) {
        int row = mwarp + mi * 16 + (lane >> 2);
        float bi0 = bias[row], bi1 = bias[row + 8];
#pragma unroll
        for (int nf = 0; nf < 4; nf++) {
            acc[mi][nf][0] += bi0;
            acc[mi][nf][1] += bi0;
            acc[mi][nf][2] += bi1;
            acc[mi][nf][3] += bi1;
            cs0[nf] += acc[mi][nf][0] * acc[mi][nf][0] + acc[mi][nf][2] * acc[mi][nf][2];
            cs1[nf] += acc[mi][nf][1] * acc[mi][nf][1] + acc[mi][nf][3] * acc[mi][nf][3];
        }
    }
#pragma unroll
    for (int nf = 0; nf < 4; nf++) {
#pragma unroll
        for (int o = 4; o < 32; o <<= 1) {
            cs0[nf] += __shfl_xor_sync(0xFFFFFFFFu, cs0[nf], o);
            cs1[nf] += __shfl_xor_sync(0xFFFFFFFFu, cs1[nf], o);
        }
    }
    if (lane < 4) {
#pragma unroll
        for (int nf = 0; nf < 4; nf++) {
            int col = nwarp + nf * 8 + lane * 2;
            atomicAdd(&colsq[col], cs0[nf]);
            atomicAdd(&colsq[col + 1], cs1[nf]);
        }
    }
    __syncthreads();
    if (tid < 64) invs[tid] = 16.0f / fmaxf(sqrtf(colsq[tid]), 1e-12f);
    __syncthreads();

    float* ob = out + (size_t)b * CIN * HW + pos0;
#pragma unroll
    for (int mi = 0; mi < 4; mi++) {
        int row = mwarp + mi * 16 + (lane >> 2);
        float gr0 = gout[row], gr1 = gout[row + 8];
#pragma unroll
        for (int nf = 0; nf < 4; nf++) {
            int col = nwarp + nf * 8 + (lane & 3) * 2;
            float i0 = invs[col], i1 = invs[col + 1];
            *(float2*)(ob + (size_t)row * HW + col) =
                make_float2(acc[mi][nf][0] * i0 * gr0, acc[mi][nf][1] * i1 * gr0);
            *(float2*)(ob + (size_t)(row + 8) * HW + col) =
                make_float2(acc[mi][nf][2] * i0 * gr1, acc[mi][nf][3] * i1 * gr1);
        }
    }
}

// ---------------------------------------------------------------------------
extern "C" void kernel_launch(void* const* d_in, const int* in_sizes, int n_in,
                              void* d_out, int out_size) {
    const float* x      = (const float*)d_in[0];
    const float* g_in   = (const float*)d_in[1];
    const float* w_qkv  = (const float*)d_in[2];
    const float* mem_kv = (const float*)d_in[3];
    const float* w_out  = (const float*)d_in[4];
    const float* b_out  = (const float*)d_in[5];
    const float* g_out  = (const float*)d_in[6];
    float* out = (float*)d_out;

    float *s_ptr, *qkv_ptr, *rmax_ptr, *rinv_ptr, *part_ptr, *ctx_ptr;
    __nv_bfloat16 *w1_ptr, *w2_ptr, *wo1_ptr, *wo2_ptr, *x1_ptr, *x2_ptr, *a1_ptr, *a2_ptr;
    cudaGetSymbolAddress((void**)&s_ptr,    g_s);
    cudaGetSymbolAddress((void**)&w1_ptr,   g_w1);
    cudaGetSymbolAddress((void**)&w2_ptr,   g_w2);
    cudaGetSymbolAddress((void**)&wo1_ptr,  g_wo1);
    cudaGetSymbolAddress((void**)&wo2_ptr,  g_wo2);
    cudaGetSymbolAddress((void**)&x1_ptr,   g_x1);
    cudaGetSymbolAddress((void**)&x2_ptr,   g_x2);
    cudaGetSymbolAddress((void**)&qkv_ptr,  g_qkv);
    cudaGetSymbolAddress((void**)&rmax_ptr, g_rmax);
    cudaGetSymbolAddress((void**)&rinv_ptr, g_rinv);
    cudaGetSymbolAddress((void**)&part_ptr, g_part);
    cudaGetSymbolAddress((void**)&ctx_ptr,  g_ctx);
    cudaGetSymbolAddress((void**)&a1_ptr,   g_a1);
    cudaGetSymbolAddress((void**)&a2_ptr,   g_a2);

    cudaFuncSetAttribute(qkv_mma_kernel,
                         cudaFuncAttributeMaxDynamicSharedMemorySize, QSMTOT);
    cudaFuncSetAttribute(outnorm_mma_kernel,
                         cudaFuncAttributeMaxDynamicSharedMemorySize, OSMTOT);

    colscale_kernel<<<(BATCH * HW + 255) / 256, 256>>>(x, s_ptr);
    wconv_kernel<<<(O3 * CIN + 255) / 256, 256>>>(w_qkv, g_in, w1_ptr, w2_ptr);
    woconv_kernel<<<(CIN * HID + 255) / 256, 256>>>(w_out, wo1_ptr, wo2_ptr);
    xconv_kernel<<<dim3(HW / 32, CIN / 32, BATCH), 256>>>(x, s_ptr, x1_ptr, x2_ptr);
    qkv_mma_kernel<<<dim3(HW / 128, O3 / 128, BATCH), 256, QSMTOT>>>(
        w1_ptr, w2_ptr, x1_ptr, x2_ptr, qkv_ptr);
    kstats_kernel<<<dim3(HD, NH, BATCH), 256>>>(qkv_ptr, mem_kv, rmax_ptr, rinv_ptr);
    ctxpart_kernel<<<dim3(NC, NH, BATCH), 256>>>(qkv_ptr, rmax_ptr, part_ptr);
    ctxreduce_kernel<<<dim3(NH, BATCH), 256>>>(part_ptr, mem_kv, rmax_ptr, rinv_ptr, ctx_ptr);
    attend_kernel<<<dim3(HW / 64, NH, BATCH), 256>>>(qkv_ptr, ctx_ptr, a1_ptr, a2_ptr);
    outnorm_mma_kernel<<<dim3(HW / 64, BATCH), 256, OSMTOT>>>(
        wo1_ptr, wo2_ptr, a1_ptr, a2_ptr, b_out, g_out, out);
}

// round 10
// speedup vs baseline: 1.3505x; 1.1897x over previous
#include <cuda_runtime.h>
#include <cuda_fp16.h>
#include <math.h>
#include <stdint.h>
#include <string.h>

// Problem constants
#define BATCH 16
#define CIN   256
#define HW    4096
#define O3    1536
#define HID   512
#define NH    8
#define HD    64
#define NMEM  4
#define NC    8
#define CHUNK 512

typedef unsigned long long u64;

// Scratch (device globals — allocation-free rule)
__device__ float g_s[BATCH * HW];
__device__ __half g_w1[O3 * CIN];
__device__ __half g_w2[O3 * CIN];
__device__ __half g_wo1[CIN * HID];
__device__ __half g_wo2[CIN * HID];
__device__ __half g_x1[(size_t)BATCH * HW * CIN];   // transposed [b][n][c], fp16
__device__ float g_qkv[(size_t)BATCH * O3 * HW];    // 402 MB
__device__ float g_rmax[BATCH * NH * HD];
__device__ float g_rinv[BATCH * NH * HD];
__device__ float g_part[(size_t)NC * BATCH * NH * HD * HD];
__device__ float g_ctx[BATCH * NH * HD * HD];
__device__ __half g_a1[(size_t)BATCH * HW * HID];   // att^T [b][pos][hid], fp16

// ---- packed f32x2 helpers ------------------------------------------------
__device__ __forceinline__ u64 pack_dup(float v) {
    u64 r; asm("mov.b64 %0, {%1, %2};" : "=l"(r) : "f"(v), "f"(v)); return r;
}
__device__ __forceinline__ void ffma2(u64& d, u64 a, u64 b) {
    asm("fma.rn.f32x2 %0, %1, %2, %0;" : "+l"(d) : "l"(a), "l"(b));
}
__device__ __forceinline__ float2 unpack2(u64 v) {
    float2 f; asm("mov.b64 {%0, %1}, %2;" : "=f"(f.x), "=f"(f.y) : "l"(v)); return f;
}

// ---- mma.sync helpers ------------------------------------------------------
__device__ __forceinline__ uint32_t smem_u32(const void* p) {
    uint32_t a;
    asm("{ .reg .u64 t; cvta.to.shared.u64 t, %1; cvt.u32.u64 %0, t; }"
        : "=r"(a) : "l"(p));
    return a;
}
__device__ __forceinline__ void ldm4(uint32_t* r, uint32_t addr) {
    asm volatile("ldmatrix.sync.aligned.m8n8.x4.shared.b16 {%0,%1,%2,%3}, [%4];"
                 : "=r"(r[0]), "=r"(r[1]), "=r"(r[2]), "=r"(r[3]) : "r"(addr));
}
__device__ __forceinline__ void mma_f16(float* c, const uint32_t* a,
                                        uint32_t b0, uint32_t b1) {
    asm volatile(
        "mma.sync.aligned.m16n8k16.row.col.f32.f16.f16.f32 "
        "{%0,%1,%2,%3}, {%4,%5,%6,%7}, {%8,%9}, {%0,%1,%2,%3};"
        : "+f"(c[0]), "+f"(c[1]), "+f"(c[2]), "+f"(c[3])
        : "r"(a[0]), "r"(a[1]), "r"(a[2]), "r"(a[3]), "r"(b0), "r"(b1));
}
__device__ __forceinline__ void cp16(uint32_t dst, const void* src) {
    asm volatile("cp.async.cg.shared.global [%0], [%1], 16;"
                 :: "r"(dst), "l"(src));
}
#define CP_COMMIT() asm volatile("cp.async.commit_group;" ::: "memory")
#define CP_WAIT1()  asm volatile("cp.async.wait_group 1;" ::: "memory")
#define CP_WAIT0()  asm volatile("cp.async.wait_group 0;" ::: "memory")

__device__ __forceinline__ uint32_t pkh(float lo, float hi) {
    __half2 t = __floats2half2_rn(lo, hi);
    uint32_t r; memcpy(&r, &t, 4); return r;
}

// ---------------------------------------------------------------------------
// Kernel 1: per-position rmsnorm scale
// ---------------------------------------------------------------------------
__global__ __launch_bounds__(256) void colscale_kernel(const float* __restrict__ x,
                                                       float* __restrict__ s) {
    int idx = blockIdx.x * 256 + threadIdx.x;
    if (idx >= BATCH * HW) return;
    int b = idx >> 12, pos = idx & (HW - 1);
    const float* p = x + (size_t)b * CIN * HW + pos;
    float acc = 0.f;
#pragma unroll 8
    for (int c = 0; c < CIN; c++) {
        float v = p[(size_t)c * HW];
        acc += v * v;
    }
    s[idx] = 16.0f / fmaxf(sqrtf(acc), 1e-12f);
}

// ---------------------------------------------------------------------------
// Kernel 1b: W fold + fp16 2-way split
// ---------------------------------------------------------------------------
__global__ __launch_bounds__(256) void wconv_kernel(const float* __restrict__ w,
                                                    const float* __restrict__ g,
                                                    __half* __restrict__ w1,
                                                    __half* __restrict__ w2) {
    int i = blockIdx.x * 256 + threadIdx.x;
    if (i >= O3 * CIN) return;
    float wg = w[i] * g[i & (CIN - 1)];
    __half h = __float2half_rn(wg);
    w1[i] = h;
    w2[i] = __float2half_rn(wg - __half2float(h));
}

// Kernel 1b2: w_out fp16 2-way split
__global__ __launch_bounds__(256) void woconv_kernel(const float* __restrict__ w,
                                                     __half* __restrict__ w1,
                                                     __half* __restrict__ w2) {
    int i = blockIdx.x * 256 + threadIdx.x;
    if (i >= CIN * HID) return;
    float v = w[i];
    __half h = __float2half_rn(v);
    w1[i] = h;
    w2[i] = __float2half_rn(v - __half2float(h));
}

// ---------------------------------------------------------------------------
// Kernel 1c: X transpose to [b][n][c], fold rmsnorm scale, single fp16
// ---------------------------------------------------------------------------
__global__ __launch_bounds__(256) void xconv_kernel(const float* __restrict__ x,
                                                    const float* __restrict__ s,
                                                    __half* __restrict__ x1) {
    int b = blockIdx.z;
    int c0 = blockIdx.y * 32, n0 = blockIdx.x * 32;
    __shared__ float t[32][33];
    int tid = threadIdx.x;
    int tx = tid & 31, ty = tid >> 5;
#pragma unroll
    for (int i = 0; i < 4; i++) {
        int c = ty + i * 8;
        t[c][tx] = x[((size_t)b * CIN + c0 + c) * HW + n0 + tx];
    }
    __syncthreads();
#pragma unroll
    for (int i = 0; i < 4; i++) {
        int nr = ty + i * 8;
        float sv = s[b * HW + n0 + nr];
        x1[((size_t)b * HW + n0 + nr) * CIN + c0 + tx] =
            __float2half_rn(t[tx][nr] * sv);
    }
}

// ---------------------------------------------------------------------------
// Kernel 2: QKV GEMM, mma.sync fp16: C = (w1 + w2) @ x1. 2 products.
// CTA tile 128x128, K-tile 32, LDK=40 -> 60KB smem -> 2 CTAs/SM.
// 8 warps (4m x 2n), warp tile 32x64.
// ---------------------------------------------------------------------------
#define QLDK   40
#define QT_B   (128 * QLDK * 2)        // 10240 per tile
#define QSTAGE (3 * QT_B)              // 30720  (A1, A2, B)
#define QSMTOT (2 * QSTAGE)            // 61440
#define Q_A1   0
#define Q_A2   QT_B
#define Q_B    (2 * QT_B)

__global__ void __launch_bounds__(256, 2)
qkv_mma_kernel(const __half* __restrict__ w1,
               const __half* __restrict__ w2,
               const __half* __restrict__ x1,
               float* __restrict__ out) {
    extern __shared__ char smem[];
    uint32_t sb = smem_u32(smem);
    int tid = threadIdx.x;
    int warp = tid >> 5, lane = tid & 31;
    int b = blockIdx.z;
    int rowBase = blockIdx.y * 128;
    int colBase = blockIdx.x * 128;

    const char* srcA1 = (const char*)(w1 + (size_t)rowBase * CIN);
    const char* srcA2 = (const char*)(w2 + (size_t)rowBase * CIN);
    const char* srcB  = (const char*)(x1 + ((size_t)b * HW + colBase) * CIN);

    int lrow = tid >> 2, lseg = tid & 3;   // 64 rows x 4 segs (32 k = 64B)

    auto load_stage = [&](int st, int k0) {
        uint32_t dbase = sb + st * QSTAGE;
#pragma unroll
        for (int j = 0; j < 2; j++) {
            int row = lrow + j * 64;
            uint32_t dp = dbase + row * (QLDK * 2) + lseg * 16;
            size_t go = (size_t)row * (CIN * 2) + k0 * 2 + lseg * 16;
            cp16(dp + Q_A1, srcA1 + go);
            cp16(dp + Q_A2, srcA2 + go);
            cp16(dp + Q_B,  srcB + go);
        }
    };

    int mwarp = (warp >> 1) * 32;
    int nwarp = (warp & 1) * 64;

    float acc[2][8][4];
#pragma unroll
    for (int mi = 0; mi < 2; mi++)
#pragma unroll
        for (int nf = 0; nf < 8; nf++)
#pragma unroll
            for (int q = 0; q < 4; q++) acc[mi][nf][q] = 0.f;

    int flrow = lane & 7, mat = lane >> 3;
    int frow = (mat & 1) * 8 + flrow;
    int fk   = (mat >> 1) * 8;

    load_stage(0, 0);
    CP_COMMIT();

    for (int kt = 0; kt < 8; kt++) {
        if (kt < 7) {
            load_stage((kt + 1) & 1, (kt + 1) * 32);
            CP_COMMIT();
            CP_WAIT1();
        } else {
            CP_WAIT0();
        }
        __syncthreads();
        uint32_t stb = sb + (kt & 1) * QSTAGE;

#pragma unroll
        for (int ks = 0; ks < 2; ks++) {
            int kk = ks * 16 + fk;
            uint32_t fa1[2][4], fa2[2][4], fb[4][4];
#pragma unroll
            for (int mi = 0; mi < 2; mi++) {
                uint32_t off = (uint32_t)((mwarp + mi * 16 + frow) * (QLDK * 2) + kk * 2);
                ldm4(fa1[mi], stb + Q_A1 + off);
                ldm4(fa2[mi], stb + Q_A2 + off);
            }
#pragma unroll
            for (int nb = 0; nb < 4; nb++)
                ldm4(fb[nb], stb + Q_B +
                     (uint32_t)((nwarp + nb * 16 + frow) * (QLDK * 2) + kk * 2));
#pragma unroll
            for (int mi = 0; mi < 2; mi++)
#pragma unroll
                for (int nf = 0; nf < 8; nf++) {
                    int nb = nf >> 1, hi = nf & 1;
                    mma_f16(acc[mi][nf], fa1[mi], fb[nb][hi], fb[nb][hi + 2]);
                    mma_f16(acc[mi][nf], fa2[mi], fb[nb][hi], fb[nb][hi + 2]);
                }
        }
        __syncthreads();
    }

    float* obase = out + (size_t)b * O3 * HW;
#pragma unroll
    for (int mi = 0; mi < 2; mi++) {
        int row = rowBase + mwarp + mi * 16 + (lane >> 2);
#pragma unroll
        for (int nf = 0; nf < 8; nf++) {
            int col = colBase + nwarp + nf * 8 + (lane & 3) * 2;
            *(float2*)(obase + (size_t)row * HW + col) =
                make_float2(acc[mi][nf][0], acc[mi][nf][1]);
            *(float2*)(obase + (size_t)(row + 8) * HW + col) =
                make_float2(acc[mi][nf][2], acc[mi][nf][3]);
        }
    }
}

// ---------------------------------------------------------------------------
// Kernel 3a: k-softmax stats per (b,h,d) row
// ---------------------------------------------------------------------------
__global__ __launch_bounds__(256) void kstats_kernel(const float* __restrict__ qkv,
                                                     const float* __restrict__ memkv,
                                                     float* __restrict__ rmax,
                                                     float* __restrict__ rinv) {
    int d = blockIdx.x, h = blockIdx.y, b = blockIdx.z;
    int tid = threadIdx.x;
    const float* kr = qkv + ((size_t)b * O3 + HID + h * HD + d) * HW;
    const float* MK = memkv + ((size_t)h * HD + d) * NMEM;

    float v[16];
#pragma unroll
    for (int i = 0; i < 16; i++) v[i] = kr[i * 256 + tid];
    float m = v[0];
#pragma unroll
    for (int i = 1; i < 16; i++) m = fmaxf(m, v[i]);
    if (tid < NMEM) m = fmaxf(m, MK[tid]);

    __shared__ float red[8];
#pragma unroll
    for (int o = 16; o; o >>= 1) m = fmaxf(m, __shfl_xor_sync(0xFFFFFFFFu, m, o));
    if ((tid & 31) == 0) red[tid >> 5] = m;
    __syncthreads();
    if (tid == 0) {
        float t = red[0];
#pragma unroll
        for (int i = 1; i < 8; i++) t = fmaxf(t, red[i]);
        red[0] = t;
    }
    __syncthreads();
    m = red[0];
    __syncthreads();

    float ss = 0.f;
#pragma unroll
    for (int i = 0; i < 16; i++) ss += __expf(v[i] - m);
    if (tid < NMEM) ss += __expf(MK[tid] - m);
#pragma unroll
    for (int o = 16; o; o >>= 1) ss += __shfl_xor_sync(0xFFFFFFFFu, ss, o);
    if ((tid & 31) == 0) red[tid >> 5] = ss;
    __syncthreads();
    if (tid == 0) {
        float t = 0.f;
#pragma unroll
        for (int i = 0; i < 8; i++) t += red[i];
        int idx = (b * NH + h) * HD + d;
        rmax[idx] = m;
        rinv[idx] = 1.0f / t;
    }
}

// ---------------------------------------------------------------------------
// Kernel 3b: partial context over n chunks (FFMA2 SIMT)
// ---------------------------------------------------------------------------
__global__ __launch_bounds__(256) void ctxpart_kernel(const float* __restrict__ qkv,
                                                      const float* __restrict__ rmax,
                                                      float* __restrict__ part) {
    int c = blockIdx.x, h = blockIdx.y, b = blockIdx.z;
    const float* K = qkv + ((size_t)b * O3 + HID + h * HD) * HW;
    const float* V = qkv + ((size_t)b * O3 + 2 * HID + h * HD) * HW;

    __shared__ __align__(16) float Kt[64][68];
    __shared__ __align__(16) float Vt[64][68];
    __shared__ float rm[64];

    int tid = threadIdx.x;
    if (tid < 64) rm[tid] = rmax[(b * NH + h) * HD + tid];
    __syncthreads();

    int tx = tid & 15, ty = tid >> 4;
    u64 acc[4][2];
#pragma unroll
    for (int i = 0; i < 4; i++) { acc[i][0] = 0ULL; acc[i][1] = 0ULL; }

    for (int nt = 0; nt < CHUNK / 64; nt++) {
        int n0 = c * CHUNK + nt * 64;
#pragma unroll
        for (int l = 0; l < 16; l++) {
            int lin = l * 256 + tid;
            int d = lin >> 6, j = lin & 63;
            Kt[j][d] = __expf(K[(size_t)d * HW + n0 + j] - rm[d]);
            Vt[j][d] = V[(size_t)d * HW + n0 + j];
        }
        __syncthreads();
#pragma unroll 4
        for (int j = 0; j < 64; j++) {
            float4 kf = *(const float4*)(&Kt[j][ty * 4]);
            u64 k0 = pack_dup(kf.x), k1 = pack_dup(kf.y);
            u64 k2 = pack_dup(kf.z), k3 = pack_dup(kf.w);
            ulonglong2 vv = *(const ulonglong2*)(&Vt[j][tx * 4]);
            ffma2(acc[0][0], k0, vv.x); ffma2(acc[0][1], k0, vv.y);
            ffma2(acc[1][0], k1, vv.x); ffma2(acc[1][1], k1, vv.y);
            ffma2(acc[2][0], k2, vv.x); ffma2(acc[2][1], k2, vv.y);
            ffma2(acc[3][0], k3, vv.x); ffma2(acc[3][1], k3, vv.y);
        }
        __syncthreads();
    }

    float* pb = part + ((size_t)c * BATCH * NH + b * NH + h) * (HD * HD);
#pragma unroll
    for (int i = 0; i < 4; i++) {
        float2 a = unpack2(acc[i][0]);
        float2 bb = unpack2(acc[i][1]);
        *(float4*)(&pb[(ty * 4 + i) * HD + tx * 4]) = make_float4(a.x, a.y, bb.x, bb.y);
    }
}

// ---------------------------------------------------------------------------
// Kernel 3c: reduce partials + mem-kv tail + rinv scaling -> ctx
// ---------------------------------------------------------------------------
__global__ __launch_bounds__(256) void ctxreduce_kernel(const float* __restrict__ part,
                                                        const float* __restrict__ memkv,
                                                        const float* __restrict__ rmax,
                                                        const float* __restrict__ rinv,
                                                        float* __restrict__ ctx) {
    int h = blockIdx.x, b = blockIdx.y;
    __shared__ float mkx[64][4];
    __shared__ float mvs[64][4];
    __shared__ float riv[64];
    int tid = threadIdx.x;
    if (tid < 64) riv[tid] = rinv[(b * NH + h) * HD + tid];
    {
        int d = tid >> 2, j = tid & 3;
        mkx[d][j] = __expf(memkv[((size_t)h * HD + d) * NMEM + j] -
                           rmax[(b * NH + h) * HD + d]);
        mvs[d][j] = memkv[(size_t)NH * HD * NMEM + ((size_t)h * HD + d) * NMEM + j];
    }
    __syncthreads();
    size_t base = (size_t)(b * NH + h) * (HD * HD);
    for (int l = tid; l < HD * HD; l += 256) {
        int d = l >> 6, e = l & 63;
        float s2 = 0.f;
#pragma unroll
        for (int cc = 0; cc < NC; cc++)
            s2 += part[(size_t)cc * BATCH * NH * HD * HD + base + l];
#pragma unroll
        for (int j = 0; j < 4; j++) s2 += mkx[d][j] * mvs[e][j];
        ctx[base + l] = s2 * riv[d];
    }
}

// ---------------------------------------------------------------------------
// Kernel 4: q-softmax + out[e][p] = sum_d ctx[d][e]*qs[d][p]; writes single
// fp16 transposed [b][pos][hid] for the tensorized outnorm.
// ---------------------------------------------------------------------------
__global__ __launch_bounds__(256) void attend_kernel(const float* __restrict__ qkv,
                                                     const float* __restrict__ ctx,
                                                     __half* __restrict__ a1) {
    int pos0 = blockIdx.x * 64;
    int h = blockIdx.y, b = blockIdx.z;
    const float* Q = qkv + ((size_t)b * O3 + h * HD) * HW;
    const float* cb = ctx + (size_t)(b * NH + h) * HD * HD;

    __shared__ __align__(16) float cs[64][68];
    __shared__ __align__(16) float qs[64][68];

    int tid = threadIdx.x;
    for (int l = tid; l < HD * HD; l += 256) {
        int d = l >> 6, e = l & 63;
        cs[d][e] = cb[l];
        qs[d][e] = Q[(size_t)d * HW + pos0 + e];
    }
    __syncthreads();

    if (tid < 64) {
        float m = -1e30f;
#pragma unroll
        for (int d = 0; d < HD; d++) m = fmaxf(m, qs[d][tid]);
        float ss = 0.f;
#pragma unroll
        for (int d = 0; d < HD; d++) ss += __expf(qs[d][tid] - m);
        float inv = 0.125f / ss;
#pragma unroll
        for (int d = 0; d < HD; d++)
            qs[d][tid] = __expf(qs[d][tid] - m) * inv;
    }
    __syncthreads();

    int tx = tid & 15, ty = tid >> 4;
    u64 acc[4][2];
#pragma unroll
    for (int i = 0; i < 4; i++) { acc[i][0] = 0ULL; acc[i][1] = 0ULL; }

#pragma unroll 4
    for (int d = 0; d < HD; d++) {
        float4 cf = *(const float4*)(&cs[d][ty * 4]);
        u64 c0 = pack_dup(cf.x), c1 = pack_dup(cf.y);
        u64 c2 = pack_dup(cf.z), c3 = pack_dup(cf.w);
        ulonglong2 qq = *(const ulonglong2*)(&qs[d][tx * 4]);
        ffma2(acc[0][0], c0, qq.x); ffma2(acc[0][1], c0, qq.y);
        ffma2(acc[1][0], c1, qq.x); ffma2(acc[1][1], c1, qq.y);
        ffma2(acc[2][0], c2, qq.x); ffma2(acc[2][1], c2, qq.y);
        ffma2(acc[3][0], c3, qq.x); ffma2(acc[3][1], c3, qq.y);
    }

    // Stage transposed result into cs as os[pos][e]
    __syncthreads();
#pragma unroll
    for (int i = 0; i < 4; i++) {
        float2 a = unpack2(acc[i][0]);
        float2 bb = unpack2(acc[i][1]);
        int e = ty * 4 + i;
        cs[tx * 4 + 0][e] = a.x;
        cs[tx * 4 + 1][e] = a.y;
        cs[tx * 4 + 2][e] = bb.x;
        cs[tx * 4 + 3][e] = bb.y;
    }
    __syncthreads();

    {
        int pos = tid >> 2, e0 = (tid & 3) * 16;
        size_t base = ((size_t)b * HW + pos0 + pos) * HID + h * HD + e0;
        uint32_t r1[8];
#pragma unroll
        for (int u = 0; u < 8; u++)
            r1[u] = pkh(cs[pos][e0 + 2 * u], cs[pos][e0 + 2 * u + 1]);
        *(uint4*)((char*)a1 + base * 2)      = make_uint4(r1[0], r1[1], r1[2], r1[3]);
        *(uint4*)((char*)a1 + base * 2 + 16) = make_uint4(r1[4], r1[5], r1[6], r1[7]);
    }
}

// ---------------------------------------------------------------------------
// Kernel 5: out GEMM fp16 (2 products) + bias + fused rmsnorm.
// CTA tile 256x64, K-tile 32, LDK=40 -> 92KB total -> 2 CTAs/SM.
// 8 warps (4m x 2n), warp tile 64x32.
// ---------------------------------------------------------------------------
#define OLDK   40
#define OA_T   (256 * OLDK * 2)        // 20480 per A split
#define OB_T   (64 * OLDK * 2)         // 5120 (single B)
#define OSTAGE (2 * OA_T + OB_T)       // 46080
#define OSMTOT (2 * OSTAGE)            // 92160
#define O_A1   0
#define O_A2   OA_T
#define O_B    (2 * OA_T)

__global__ void __launch_bounds__(256, 2)
outnorm_mma_kernel(const __half* __restrict__ wo1,
                   const __half* __restrict__ wo2,
                   const __half* __restrict__ a1,
                   const float* __restrict__ bias,
                   const float* __restrict__ gout,
                   float* __restrict__ out) {
    extern __shared__ char smem[];
    uint32_t sb = smem_u32(smem);
    __shared__ float colsq[64];
    __shared__ float invs[64];

    int tid = threadIdx.x;
    int warp = tid >> 5, lane = tid & 31;
    int b = blockIdx.y;
    int pos0 = blockIdx.x * 64;

    const char* srcA1 = (const char*)wo1;
    const char* srcA2 = (const char*)wo2;
    const char* srcB  = (const char*)(a1 + ((size_t)b * HW + pos0) * HID);

    int lrow = tid >> 2, lseg = tid & 3;   // 64 rows x 4 segs per pass

    auto load_stage = [&](int st, int k0) {
        uint32_t dbase = sb + st * OSTAGE;
#pragma unroll
        for (int j = 0; j < 4; j++) {      // A: 256 rows
            int row = lrow + j * 64;
            uint32_t dp = dbase + row * (OLDK * 2) + lseg * 16;
            size_t go = (size_t)row * (HID * 2) + k0 * 2 + lseg * 16;
            cp16(dp + O_A1, srcA1 + go);
            cp16(dp + O_A2, srcA2 + go);
        }
        {                                  // B: 64 rows
            int row = lrow;
            uint32_t dp = dbase + row * (OLDK * 2) + lseg * 16;
            cp16(dp + O_B, srcB + (size_t)row * (HID * 2) + k0 * 2 + lseg * 16);
        }
    };

    int mwarp = (warp >> 1) * 64;
    int nwarp = (warp & 1) * 32;

    float acc[4][4][4];
#pragma unroll
    for (int mi = 0; mi < 4; mi++)
#pragma unroll
        for (int nf = 0; nf < 4; nf++)
#pragma unroll
            for (int q = 0; q < 4; q++) acc[mi][nf][q] = 0.f;

    int flrow = lane & 7, mat = lane >> 3;
    int frow = (mat & 1) * 8 + flrow;
    int fk   = (mat >> 1) * 8;

    if (tid < 64) colsq[tid] = 0.f;

    load_stage(0, 0);
    CP_COMMIT();

    for (int kt = 0; kt < 16; kt++) {
        if (kt < 15) {
            load_stage((kt + 1) & 1, (kt + 1) * 32);
            CP_COMMIT();
            CP_WAIT1();
        } else {
            CP_WAIT0();
        }
        __syncthreads();
        uint32_t stb = sb + (kt & 1) * OSTAGE;

#pragma unroll
        for (int ks = 0; ks < 2; ks++) {
            int kk = ks * 16 + fk;
            uint32_t fa1[4][4], fa2[4][4], fb[2][4];
#pragma unroll
            for (int mi = 0; mi < 4; mi++) {
                uint32_t off = (uint32_t)((mwarp + mi * 16 + frow) * (OLDK * 2) + kk * 2);
                ldm4(fa1[mi], stb + O_A1 + off);
                ldm4(fa2[mi], stb + O_A2 + off);
            }
#pragma unroll
            for (int nb = 0; nb < 2; nb++)
                ldm4(fb[nb], stb + O_B +
                     (uint32_t)((nwarp + nb * 16 + frow) * (OLDK * 2) + kk * 2));
#pragma unroll
            for (int mi = 0; mi < 4; mi++)
#pragma unroll
                for (int nf = 0; nf < 4; nf++) {
                    int nb = nf >> 1, hi = nf & 1;
                    mma_f16(acc[mi][nf], fa1[mi], fb[nb][hi], fb[nb][hi + 2]);
                    mma_f16(acc[mi][nf], fa2[mi], fb[nb][hi], fb[nb][hi + 2]);
                }
        }
        __syncthreads();
    }

    // bias + column sum-of-squares
    float cs0[4], cs1[4];
#pragma unroll
    for (int nf = 0; nf < 4; nf++) { cs0[nf] = 0.f; cs1[nf] = 0.f; }
#pragma unroll
    for (int mi = 0; mi < 4; mi++) {
        int row = mwarp + mi * 16 + (lane >> 2);
        float bi0 = bias[row], bi1 = bias[row + 8];
#pragma unroll
        for (int nf = 0; nf < 4; nf++) {
            acc[mi][nf][0] += bi0;
            acc[mi][nf][1] += bi0;
            acc[mi][nf][2] += bi1;
            acc[mi][nf][3] += bi1;
            cs0[nf] += acc[mi][nf][0] * acc[mi][nf][0] + acc[mi][nf][2] * acc[mi][nf][2];
            cs1[nf] += acc[mi][nf][1] * acc[mi][nf][1] + acc[mi][nf][3] * acc[mi][nf][3];
        }
    }
#pragma unroll
    for (int nf = 0; nf < 4; nf++) {
#pragma unroll
        for (int o = 4; o < 32; o <<= 1) {
            cs0[nf] += __shfl_xor_sync(0xFFFFFFFFu, cs0[nf], o);
            cs1[nf] += __shfl_xor_sync(0xFFFFFFFFu, cs1[nf], o);
        }
    }
    if (lane < 4) {
#pragma unroll
        for (int nf = 0; nf < 4; nf++) {
            int col = nwarp + nf * 8 + lane * 2;
            atomicAdd(&colsq[col], cs0[nf]);
            atomicAdd(&colsq[col + 1], cs1[nf]);
        }
    }
    __syncthreads();
    if (tid < 64) invs[tid] = 16.0f / fmaxf(sqrtf(colsq[tid]), 1e-12f);
    __syncthreads();

    float* ob = out + (size_t)b * CIN * HW + pos0;
#pragma unroll
    for (int mi = 0; mi < 4; mi++) {
        int row = mwarp + mi * 16 + (lane >> 2);
        float gr0 = gout[row], gr1 = gout[row + 8];
#pragma unroll
        for (int nf = 0; nf < 4; nf++) {
            int col = nwarp + nf * 8 + (lane & 3) * 2;
            float i0 = invs[col], i1 = invs[col + 1];
            *(float2*)(ob + (size_t)row * HW + col) =
                make_float2(acc[mi][nf][0] * i0 * gr0, acc[mi][nf][1] * i1 * gr0);
            *(float2*)(ob + (size_t)(row + 8) * HW + col) =
                make_float2(acc[mi][nf][2] * i0 * gr1, acc[mi][nf][3] * i1 * gr1);
        }
    }
}

// ---------------------------------------------------------------------------
extern "C" void kernel_launch(void* const* d_in, const int* in_sizes, int n_in,
                              void* d_out, int out_size) {
    const float* x      = (const float*)d_in[0];
    const float* g_in   = (const float*)d_in[1];
    const float* w_qkv  = (const float*)d_in[2];
    const float* mem_kv = (const float*)d_in[3];
    const float* w_out  = (const float*)d_in[4];
    const float* b_out  = (const float*)d_in[5];
    const float* g_out  = (const float*)d_in[6];
    float* out = (float*)d_out;

    float *s_ptr, *qkv_ptr, *rmax_ptr, *rinv_ptr, *part_ptr, *ctx_ptr;
    __half *w1_ptr, *w2_ptr, *wo1_ptr, *wo2_ptr, *x1_ptr, *a1_ptr;
    cudaGetSymbolAddress((void**)&s_ptr,    g_s);
    cudaGetSymbolAddress((void**)&w1_ptr,   g_w1);
    cudaGetSymbolAddress((void**)&w2_ptr,   g_w2);
    cudaGetSymbolAddress((void**)&wo1_ptr,  g_wo1);
    cudaGetSymbolAddress((void**)&wo2_ptr,  g_wo2);
    cudaGetSymbolAddress((void**)&x1_ptr,   g_x1);
    cudaGetSymbolAddress((void**)&qkv_ptr,  g_qkv);
    cudaGetSymbolAddress((void**)&rmax_ptr, g_rmax);
    cudaGetSymbolAddress((void**)&rinv_ptr, g_rinv);
    cudaGetSymbolAddress((void**)&part_ptr, g_part);
    cudaGetSymbolAddress((void**)&ctx_ptr,  g_ctx);
    cudaGetSymbolAddress((void**)&a1_ptr,   g_a1);

    cudaFuncSetAttribute(qkv_mma_kernel,
                         cudaFuncAttributeMaxDynamicSharedMemorySize, QSMTOT);
    cudaFuncSetAttribute(outnorm_mma_kernel,
                         cudaFuncAttributeMaxDynamicSharedMemorySize, OSMTOT);

    colscale_kernel<<<(BATCH * HW + 255) / 256, 256>>>(x, s_ptr);
    wconv_kernel<<<(O3 * CIN + 255) / 256, 256>>>(w_qkv, g_in, w1_ptr, w2_ptr);
    woconv_kernel<<<(CIN * HID + 255) / 256, 256>>>(w_out, wo1_ptr, wo2_ptr);
    xconv_kernel<<<dim3(HW / 32, CIN / 32, BATCH), 256>>>(x, s_ptr, x1_ptr);
    qkv_mma_kernel<<<dim3(HW / 128, O3 / 128, BATCH), 256, QSMTOT>>>(
        w1_ptr, w2_ptr, x1_ptr, qkv_ptr);
    kstats_kernel<<<dim3(HD, NH, BATCH), 256>>>(qkv_ptr, mem_kv, rmax_ptr, rinv_ptr);
    ctxpart_kernel<<<dim3(NC, NH, BATCH), 256>>>(qkv_ptr, rmax_ptr, part_ptr);
    ctxreduce_kernel<<<dim3(NH, BATCH), 256>>>(part_ptr, mem_kv, rmax_ptr, rinv_ptr, ctx_ptr);
    attend_kernel<<<dim3(HW / 64, NH, BATCH), 256>>>(qkv_ptr, ctx_ptr, a1_ptr);
    outnorm_mma_kernel<<<dim3(HW / 64, BATCH), 256, OSMTOT>>>(
        wo1_ptr, wo2_ptr, a1_ptr, b_out, g_out, out);
}

// round 11
// speedup vs baseline: 1.7047x; 1.2623x over previous
#include <cuda_runtime.h>
#include <cuda_fp16.h>
#include <math.h>
#include <stdint.h>
#include <string.h>

// Problem constants
#define BATCH 16
#define CIN   256
#define HW    4096
#define O3    1536
#define HID   512
#define NH    8
#define HD    64
#define NMEM  4
#define NC    8
#define CHUNK 512

typedef unsigned long long u64;

// Scratch (device globals — allocation-free rule)
__device__ float g_s[BATCH * HW];
__device__ __half g_w1[O3 * CIN];
__device__ __half g_wo1[CIN * HID];
__device__ __half g_x1[(size_t)BATCH * HW * CIN];   // transposed [b][n][c], fp16
__device__ float g_qkv[(size_t)BATCH * O3 * HW];    // 402 MB
__device__ float g_rmax[BATCH * NH * HD];
__device__ float g_rinv[BATCH * NH * HD];
__device__ float g_part[(size_t)NC * BATCH * NH * HD * HD];
__device__ float g_ctx[BATCH * NH * HD * HD];
__device__ __half g_a1[(size_t)BATCH * HW * HID];   // att^T [b][pos][hid], fp16

// ---- packed f32x2 helpers ------------------------------------------------
__device__ __forceinline__ u64 pack_dup(float v) {
    u64 r; asm("mov.b64 %0, {%1, %2};" : "=l"(r) : "f"(v), "f"(v)); return r;
}
__device__ __forceinline__ void ffma2(u64& d, u64 a, u64 b) {
    asm("fma.rn.f32x2 %0, %1, %2, %0;" : "+l"(d) : "l"(a), "l"(b));
}
__device__ __forceinline__ float2 unpack2(u64 v) {
    float2 f; asm("mov.b64 {%0, %1}, %2;" : "=f"(f.x), "=f"(f.y) : "l"(v)); return f;
}

// ---- mma.sync helpers ------------------------------------------------------
__device__ __forceinline__ uint32_t smem_u32(const void* p) {
    uint32_t a;
    asm("{ .reg .u64 t; cvta.to.shared.u64 t, %1; cvt.u32.u64 %0, t; }"
        : "=r"(a) : "l"(p));
    return a;
}
__device__ __forceinline__ void ldm4(uint32_t* r, uint32_t addr) {
    asm volatile("ldmatrix.sync.aligned.m8n8.x4.shared.b16 {%0,%1,%2,%3}, [%4];"
                 : "=r"(r[0]), "=r"(r[1]), "=r"(r[2]), "=r"(r[3]) : "r"(addr));
}
__device__ __forceinline__ void mma_f16(float* c, const uint32_t* a,
                                        uint32_t b0, uint32_t b1) {
    asm volatile(
        "mma.sync.aligned.m16n8k16.row.col.f32.f16.f16.f32 "
        "{%0,%1,%2,%3}, {%4,%5,%6,%7}, {%8,%9}, {%0,%1,%2,%3};"
        : "+f"(c[0]), "+f"(c[1]), "+f"(c[2]), "+f"(c[3])
        : "r"(a[0]), "r"(a[1]), "r"(a[2]), "r"(a[3]), "r"(b0), "r"(b1));
}
__device__ __forceinline__ void cp16(uint32_t dst, const void* src) {
    asm volatile("cp.async.cg.shared.global [%0], [%1], 16;"
                 :: "r"(dst), "l"(src));
}
#define CP_COMMIT() asm volatile("cp.async.commit_group;" ::: "memory")
#define CP_WAIT1()  asm volatile("cp.async.wait_group 1;" ::: "memory")
#define CP_WAIT0()  asm volatile("cp.async.wait_group 0;" ::: "memory")

__device__ __forceinline__ uint32_t pkh(float lo, float hi) {
    __half2 t = __floats2half2_rn(lo, hi);
    uint32_t r; memcpy(&r, &t, 4); return r;
}

// ---------------------------------------------------------------------------
// Kernel 1: per-position rmsnorm scale
// ---------------------------------------------------------------------------
__global__ __launch_bounds__(256) void colscale_kernel(const float* __restrict__ x,
                                                       float* __restrict__ s) {
    int idx = blockIdx.x * 256 + threadIdx.x;
    if (idx >= BATCH * HW) return;
    int b = idx >> 12, pos = idx & (HW - 1);
    const float* p = x + (size_t)b * CIN * HW + pos;
    float acc = 0.f;
#pragma unroll 8
    for (int c = 0; c < CIN; c++) {
        float v = p[(size_t)c * HW];
        acc += v * v;
    }
    s[idx] = 16.0f / fmaxf(sqrtf(acc), 1e-12f);
}

// ---------------------------------------------------------------------------
// Kernel 1b: W fold -> single fp16
// ---------------------------------------------------------------------------
__global__ __launch_bounds__(256) void wconv_kernel(const float* __restrict__ w,
                                                    const float* __restrict__ g,
                                                    __half* __restrict__ w1) {
    int i = blockIdx.x * 256 + threadIdx.x;
    if (i < O3 * CIN) w1[i] = __float2half_rn(w[i] * g[i & (CIN - 1)]);
}

// Kernel 1b2: w_out -> single fp16
__global__ __launch_bounds__(256) void woconv_kernel(const float* __restrict__ w,
                                                     __half* __restrict__ w1) {
    int i = blockIdx.x * 256 + threadIdx.x;
    if (i < CIN * HID) w1[i] = __float2half_rn(w[i]);
}

// ---------------------------------------------------------------------------
// Kernel 1c: X transpose to [b][n][c], fold rmsnorm scale, single fp16
// ---------------------------------------------------------------------------
__global__ __launch_bounds__(256) void xconv_kernel(const float* __restrict__ x,
                                                    const float* __restrict__ s,
                                                    __half* __restrict__ x1) {
    int b = blockIdx.z;
    int c0 = blockIdx.y * 32, n0 = blockIdx.x * 32;
    __shared__ float t[32][33];
    int tid = threadIdx.x;
    int tx = tid & 31, ty = tid >> 5;
#pragma unroll
    for (int i = 0; i < 4; i++) {
        int c = ty + i * 8;
        t[c][tx] = x[((size_t)b * CIN + c0 + c) * HW + n0 + tx];
    }
    __syncthreads();
#pragma unroll
    for (int i = 0; i < 4; i++) {
        int nr = ty + i * 8;
        float sv = s[b * HW + n0 + nr];
        x1[((size_t)b * HW + n0 + nr) * CIN + c0 + tx] =
            __float2half_rn(t[tx][nr] * sv);
    }
}

// ---------------------------------------------------------------------------
// Kernel 2: QKV GEMM, mma.sync fp16 single product. CTA tile 128x128,
// K-tile 32, LDK=40 -> 40KB smem (2 stages) -> 2 CTAs/SM.
// 8 warps (4m x 2n), warp tile 32x64.
// ---------------------------------------------------------------------------
#define QLDK   40
#define QT_B   (128 * QLDK * 2)        // 10240 per tile
#define QSTAGE (2 * QT_B)              // 20480  (A, B)
#define QSMTOT (2 * QSTAGE)            // 40960
#define Q_A    0
#define Q_B    QT_B

__global__ void __launch_bounds__(256, 2)
qkv_mma_kernel(const __half* __restrict__ w1,
               const __half* __restrict__ x1,
               float* __restrict__ out) {
    extern __shared__ char smem[];
    uint32_t sb = smem_u32(smem);
    int tid = threadIdx.x;
    int warp = tid >> 5, lane = tid & 31;
    int b = blockIdx.z;
    int rowBase = blockIdx.y * 128;
    int colBase = blockIdx.x * 128;

    const char* srcA = (const char*)(w1 + (size_t)rowBase * CIN);
    const char* srcB = (const char*)(x1 + ((size_t)b * HW + colBase) * CIN);

    int lrow = tid >> 2, lseg = tid & 3;   // 64 rows x 4 segs (32 k = 64B)

    auto load_stage = [&](int st, int k0) {
        uint32_t dbase = sb + st * QSTAGE;
#pragma unroll
        for (int j = 0; j < 2; j++) {
            int row = lrow + j * 64;
            uint32_t dp = dbase + row * (QLDK * 2) + lseg * 16;
            size_t go = (size_t)row * (CIN * 2) + k0 * 2 + lseg * 16;
            cp16(dp + Q_A, srcA + go);
            cp16(dp + Q_B, srcB + go);
        }
    };

    int mwarp = (warp >> 1) * 32;
    int nwarp = (warp & 1) * 64;

    float acc[2][8][4];
#pragma unroll
    for (int mi = 0; mi < 2; mi++)
#pragma unroll
        for (int nf = 0; nf < 8; nf++)
#pragma unroll
            for (int q = 0; q < 4; q++) acc[mi][nf][q] = 0.f;

    int flrow = lane & 7, mat = lane >> 3;
    int frow = (mat & 1) * 8 + flrow;
    int fk   = (mat >> 1) * 8;

    load_stage(0, 0);
    CP_COMMIT();

    for (int kt = 0; kt < 8; kt++) {
        if (kt < 7) {
            load_stage((kt + 1) & 1, (kt + 1) * 32);
            CP_COMMIT();
            CP_WAIT1();
        } else {
            CP_WAIT0();
        }
        __syncthreads();
        uint32_t stb = sb + (kt & 1) * QSTAGE;

#pragma unroll
        for (int ks = 0; ks < 2; ks++) {
            int kk = ks * 16 + fk;
            uint32_t fa[2][4], fb[4][4];
#pragma unroll
            for (int mi = 0; mi < 2; mi++)
                ldm4(fa[mi], stb + Q_A +
                     (uint32_t)((mwarp + mi * 16 + frow) * (QLDK * 2) + kk * 2));
#pragma unroll
            for (int nb = 0; nb < 4; nb++)
                ldm4(fb[nb], stb + Q_B +
                     (uint32_t)((nwarp + nb * 16 + frow) * (QLDK * 2) + kk * 2));
#pragma unroll
            for (int mi = 0; mi < 2; mi++)
#pragma unroll
                for (int nf = 0; nf < 8; nf++) {
                    int nb = nf >> 1, hi = nf & 1;
                    mma_f16(acc[mi][nf], fa[mi], fb[nb][hi], fb[nb][hi + 2]);
                }
        }
        __syncthreads();
    }

    float* obase = out + (size_t)b * O3 * HW;
#pragma unroll
    for (int mi = 0; mi < 2; mi++) {
        int row = rowBase + mwarp + mi * 16 + (lane >> 2);
#pragma unroll
        for (int nf = 0; nf < 8; nf++) {
            int col = colBase + nwarp + nf * 8 + (lane & 3) * 2;
            *(float2*)(obase + (size_t)row * HW + col) =
                make_float2(acc[mi][nf][0], acc[mi][nf][1]);
            *(float2*)(obase + (size_t)(row + 8) * HW + col) =
                make_float2(acc[mi][nf][2], acc[mi][nf][3]);
        }
    }
}

// ---------------------------------------------------------------------------
// Kernel 3a: k-softmax stats per (b,h,d) row
// ---------------------------------------------------------------------------
__global__ __launch_bounds__(256) void kstats_kernel(const float* __restrict__ qkv,
                                                     const float* __restrict__ memkv,
                                                     float* __restrict__ rmax,
                                                     float* __restrict__ rinv) {
    int d = blockIdx.x, h = blockIdx.y, b = blockIdx.z;
    int tid = threadIdx.x;
    const float* kr = qkv + ((size_t)b * O3 + HID + h * HD + d) * HW;
    const float* MK = memkv + ((size_t)h * HD + d) * NMEM;

    float v[16];
#pragma unroll
    for (int i = 0; i < 16; i++) v[i] = kr[i * 256 + tid];
    float m = v[0];
#pragma unroll
    for (int i = 1; i < 16; i++) m = fmaxf(m, v[i]);
    if (tid < NMEM) m = fmaxf(m, MK[tid]);

    __shared__ float red[8];
#pragma unroll
    for (int o = 16; o; o >>= 1) m = fmaxf(m, __shfl_xor_sync(0xFFFFFFFFu, m, o));
    if ((tid & 31) == 0) red[tid >> 5] = m;
    __syncthreads();
    if (tid == 0) {
        float t = red[0];
#pragma unroll
        for (int i = 1; i < 8; i++) t = fmaxf(t, red[i]);
        red[0] = t;
    }
    __syncthreads();
    m = red[0];
    __syncthreads();

    float ss = 0.f;
#pragma unroll
    for (int i = 0; i < 16; i++) ss += __expf(v[i] - m);
    if (tid < NMEM) ss += __expf(MK[tid] - m);
#pragma unroll
    for (int o = 16; o; o >>= 1) ss += __shfl_xor_sync(0xFFFFFFFFu, ss, o);
    if ((tid & 31) == 0) red[tid >> 5] = ss;
    __syncthreads();
    if (tid == 0) {
        float t = 0.f;
#pragma unroll
        for (int i = 0; i < 8; i++) t += red[i];
        int idx = (b * NH + h) * HD + d;
        rmax[idx] = m;
        rinv[idx] = 1.0f / t;
    }
}

// ---------------------------------------------------------------------------
// Kernel 3b: partial context over n chunks (FFMA2 SIMT)
// ---------------------------------------------------------------------------
__global__ __launch_bounds__(256) void ctxpart_kernel(const float* __restrict__ qkv,
                                                      const float* __restrict__ rmax,
                                                      float* __restrict__ part) {
    int c = blockIdx.x, h = blockIdx.y, b = blockIdx.z;
    const float* K = qkv + ((size_t)b * O3 + HID + h * HD) * HW;
    const float* V = qkv + ((size_t)b * O3 + 2 * HID + h * HD) * HW;

    __shared__ __align__(16) float Kt[64][68];
    __shared__ __align__(16) float Vt[64][68];
    __shared__ float rm[64];

    int tid = threadIdx.x;
    if (tid < 64) rm[tid] = rmax[(b * NH + h) * HD + tid];
    __syncthreads();

    int tx = tid & 15, ty = tid >> 4;
    u64 acc[4][2];
#pragma unroll
    for (int i = 0; i < 4; i++) { acc[i][0] = 0ULL; acc[i][1] = 0ULL; }

    for (int nt = 0; nt < CHUNK / 64; nt++) {
        int n0 = c * CHUNK + nt * 64;
#pragma unroll
        for (int l = 0; l < 16; l++) {
            int lin = l * 256 + tid;
            int d = lin >> 6, j = lin & 63;
            Kt[j][d] = __expf(K[(size_t)d * HW + n0 + j] - rm[d]);
            Vt[j][d] = V[(size_t)d * HW + n0 + j];
        }
        __syncthreads();
#pragma unroll 4
        for (int j = 0; j < 64; j++) {
            float4 kf = *(const float4*)(&Kt[j][ty * 4]);
            u64 k0 = pack_dup(kf.x), k1 = pack_dup(kf.y);
            u64 k2 = pack_dup(kf.z), k3 = pack_dup(kf.w);
            ulonglong2 vv = *(const ulonglong2*)(&Vt[j][tx * 4]);
            ffma2(acc[0][0], k0, vv.x); ffma2(acc[0][1], k0, vv.y);
            ffma2(acc[1][0], k1, vv.x); ffma2(acc[1][1], k1, vv.y);
            ffma2(acc[2][0], k2, vv.x); ffma2(acc[2][1], k2, vv.y);
            ffma2(acc[3][0], k3, vv.x); ffma2(acc[3][1], k3, vv.y);
        }
        __syncthreads();
    }

    float* pb = part + ((size_t)c * BATCH * NH + b * NH + h) * (HD * HD);
#pragma unroll
    for (int i = 0; i < 4; i++) {
        float2 a = unpack2(acc[i][0]);
        float2 bb = unpack2(acc[i][1]);
        *(float4*)(&pb[(ty * 4 + i) * HD + tx * 4]) = make_float4(a.x, a.y, bb.x, bb.y);
    }
}

// ---------------------------------------------------------------------------
// Kernel 3c: reduce partials + mem-kv tail + rinv scaling -> ctx
// ---------------------------------------------------------------------------
__global__ __launch_bounds__(256) void ctxreduce_kernel(const float* __restrict__ part,
                                                        const float* __restrict__ memkv,
                                                        const float* __restrict__ rmax,
                                                        const float* __restrict__ rinv,
                                                        float* __restrict__ ctx) {
    int h = blockIdx.x, b = blockIdx.y;
    __shared__ float mkx[64][4];
    __shared__ float mvs[64][4];
    __shared__ float riv[64];
    int tid = threadIdx.x;
    if (tid < 64) riv[tid] = rinv[(b * NH + h) * HD + tid];
    {
        int d = tid >> 2, j = tid & 3;
        mkx[d][j] = __expf(memkv[((size_t)h * HD + d) * NMEM + j] -
                           rmax[(b * NH + h) * HD + d]);
        mvs[d][j] = memkv[(size_t)NH * HD * NMEM + ((size_t)h * HD + d) * NMEM + j];
    }
    __syncthreads();
    size_t base = (size_t)(b * NH + h) * (HD * HD);
    for (int l = tid; l < HD * HD; l += 256) {
        int d = l >> 6, e = l & 63;
        float s2 = 0.f;
#pragma unroll
        for (int cc = 0; cc < NC; cc++)
            s2 += part[(size_t)cc * BATCH * NH * HD * HD + base + l];
#pragma unroll
        for (int j = 0; j < 4; j++) s2 += mkx[d][j] * mvs[e][j];
        ctx[base + l] = s2 * riv[d];
    }
}

// ---------------------------------------------------------------------------
// Kernel 4: q-softmax + out[e][p] = sum_d ctx[d][e]*qs[d][p]; writes single
// fp16 transposed [b][pos][hid] for the tensorized outnorm.
// ---------------------------------------------------------------------------
__global__ __launch_bounds__(256) void attend_kernel(const float* __restrict__ qkv,
                                                     const float* __restrict__ ctx,
                                                     __half* __restrict__ a1) {
    int pos0 = blockIdx.x * 64;
    int h = blockIdx.y, b = blockIdx.z;
    const float* Q = qkv + ((size_t)b * O3 + h * HD) * HW;
    const float* cb = ctx + (size_t)(b * NH + h) * HD * HD;

    __shared__ __align__(16) float cs[64][68];
    __shared__ __align__(16) float qs[64][68];

    int tid = threadIdx.x;
    for (int l = tid; l < HD * HD; l += 256) {
        int d = l >> 6, e = l & 63;
        cs[d][e] = cb[l];
        qs[d][e] = Q[(size_t)d * HW + pos0 + e];
    }
    __syncthreads();

    if (tid < 64) {
        float m = -1e30f;
#pragma unroll
        for (int d = 0; d < HD; d++) m = fmaxf(m, qs[d][tid]);
        float ss = 0.f;
#pragma unroll
        for (int d = 0; d < HD; d++) ss += __expf(qs[d][tid] - m);
        float inv = 0.125f / ss;
#pragma unroll
        for (int d = 0; d < HD; d++)
            qs[d][tid] = __expf(qs[d][tid] - m) * inv;
    }
    __syncthreads();

    int tx = tid & 15, ty = tid >> 4;
    u64 acc[4][2];
#pragma unroll
    for (int i = 0; i < 4; i++) { acc[i][0] = 0ULL; acc[i][1] = 0ULL; }

#pragma unroll 4
    for (int d = 0; d < HD; d++) {
        float4 cf = *(const float4*)(&cs[d][ty * 4]);
        u64 c0 = pack_dup(cf.x), c1 = pack_dup(cf.y);
        u64 c2 = pack_dup(cf.z), c3 = pack_dup(cf.w);
        ulonglong2 qq = *(const ulonglong2*)(&qs[d][tx * 4]);
        ffma2(acc[0][0], c0, qq.x); ffma2(acc[0][1], c0, qq.y);
        ffma2(acc[1][0], c1, qq.x); ffma2(acc[1][1], c1, qq.y);
        ffma2(acc[2][0], c2, qq.x); ffma2(acc[2][1], c2, qq.y);
        ffma2(acc[3][0], c3, qq.x); ffma2(acc[3][1], c3, qq.y);
    }

    // Stage transposed result into cs as os[pos][e]
    __syncthreads();
#pragma unroll
    for (int i = 0; i < 4; i++) {
        float2 a = unpack2(acc[i][0]);
        float2 bb = unpack2(acc[i][1]);
        int e = ty * 4 + i;
        cs[tx * 4 + 0][e] = a.x;
        cs[tx * 4 + 1][e] = a.y;
        cs[tx * 4 + 2][e] = bb.x;
        cs[tx * 4 + 3][e] = bb.y;
    }
    __syncthreads();

    {
        int pos = tid >> 2, e0 = (tid & 3) * 16;
        size_t base = ((size_t)b * HW + pos0 + pos) * HID + h * HD + e0;
        uint32_t r1[8];
#pragma unroll
        for (int u = 0; u < 8; u++)
            r1[u] = pkh(cs[pos][e0 + 2 * u], cs[pos][e0 + 2 * u + 1]);
        *(uint4*)((char*)a1 + base * 2)      = make_uint4(r1[0], r1[1], r1[2], r1[3]);
        *(uint4*)((char*)a1 + base * 2 + 16) = make_uint4(r1[4], r1[5], r1[6], r1[7]);
    }
}

// ---------------------------------------------------------------------------
// Kernel 5: out GEMM fp16 single product + bias + fused rmsnorm.
// CTA tile 256x64, K-tile 32, LDK=40 -> 51KB total -> 2+ CTAs/SM.
// 8 warps (4m x 2n), warp tile 64x32.
// ---------------------------------------------------------------------------
#define OLDK   40
#define OA_T   (256 * OLDK * 2)        // 20480 A
#define OB_T   (64 * OLDK * 2)         // 5120 B
#define OSTAGE (OA_T + OB_T)           // 25600
#define OSMTOT (2 * OSTAGE)            // 51200
#define O_A    0
#define O_B    OA_T

__global__ void __launch_bounds__(256, 2)
outnorm_mma_kernel(const __half* __restrict__ wo1,
                   const __half* __restrict__ a1,
                   const float* __restrict__ bias,
                   const float* __restrict__ gout,
                   float* __restrict__ out) {
    extern __shared__ char smem[];
    uint32_t sb = smem_u32(smem);
    __shared__ float colsq[64];
    __shared__ float invs[64];

    int tid = threadIdx.x;
    int warp = tid >> 5, lane = tid & 31;
    int b = blockIdx.y;
    int pos0 = blockIdx.x * 64;

    const char* srcA = (const char*)wo1;
    const char* srcB = (const char*)(a1 + ((size_t)b * HW + pos0) * HID);

    int lrow = tid >> 2, lseg = tid & 3;

    auto load_stage = [&](int st, int k0) {
        uint32_t dbase = sb + st * OSTAGE;
#pragma unroll
        for (int j = 0; j < 4; j++) {      // A: 256 rows
            int row = lrow + j * 64;
            cp16(dbase + O_A + row * (OLDK * 2) + lseg * 16,
                 srcA + (size_t)row * (HID * 2) + k0 * 2 + lseg * 16);
        }
        {                                  // B: 64 rows
            int row = lrow;
            cp16(dbase + O_B + row * (OLDK * 2) + lseg * 16,
                 srcB + (size_t)row * (HID * 2) + k0 * 2 + lseg * 16);
        }
    };

    int mwarp = (warp >> 1) * 64;
    int nwarp = (warp & 1) * 32;

    float acc[4][4][4];
#pragma unroll
    for (int mi = 0; mi < 4; mi++)
#pragma unroll
        for (int nf = 0; nf < 4; nf++)
#pragma unroll
            for (int q = 0; q < 4; q++) acc[mi][nf][q] = 0.f;

    int flrow = lane & 7, mat = lane >> 3;
    int frow = (mat & 1) * 8 + flrow;
    int fk   = (mat >> 1) * 8;

    if (tid < 64) colsq[tid] = 0.f;

    load_stage(0, 0);
    CP_COMMIT();

    for (int kt = 0; kt < 16; kt++) {
        if (kt < 15) {
            load_stage((kt + 1) & 1, (kt + 1) * 32);
            CP_COMMIT();
            CP_WAIT1();
        } else {
            CP_WAIT0();
        }
        __syncthreads();
        uint32_t stb = sb + (kt & 1) * OSTAGE;

#pragma unroll
        for (int ks = 0; ks < 2; ks++) {
            int kk = ks * 16 + fk;
            uint32_t fa[4][4], fb[2][4];
#pragma unroll
            for (int mi = 0; mi < 4; mi++)
                ldm4(fa[mi], stb + O_A +
                     (uint32_t)((mwarp + mi * 16 + frow) * (OLDK * 2) + kk * 2));
#pragma unroll
            for (int nb = 0; nb < 2; nb++)
                ldm4(fb[nb], stb + O_B +
                     (uint32_t)((nwarp + nb * 16 + frow) * (OLDK * 2) + kk * 2));
#pragma unroll
            for (int mi = 0; mi < 4; mi++)
#pragma unroll
                for (int nf = 0; nf < 4; nf++) {
                    int nb = nf >> 1, hi = nf & 1;
                    mma_f16(acc[mi][nf], fa[mi], fb[nb][hi], fb[nb][hi + 2]);
                }
        }
        __syncthreads();
    }

    // bias + column sum-of-squares
    float cs0[4], cs1[4];
#pragma unroll
    for (int nf = 0; nf < 4; nf++) { cs0[nf] = 0.f; cs1[nf] = 0.f; }
#pragma unroll
    for (int mi = 0; mi < 4; mi++) {
        int row = mwarp + mi * 16 + (lane >> 2);
        float bi0 = bias[row], bi1 = bias[row + 8];
#pragma unroll
        for (int nf = 0; nf < 4; nf++) {
            acc[mi][nf][0] += bi0;
            acc[mi][nf][1] += bi0;
            acc[mi][nf][2] += bi1;
            acc[mi][nf][3] += bi1;
            cs0[nf] += acc[mi][nf][0] * acc[mi][nf][0] + acc[mi][nf][2] * acc[mi][nf][2];
            cs1[nf] += acc[mi][nf][1] * acc[mi][nf][1] + acc[mi][nf][3] * acc[mi][nf][3];
        }
    }
#pragma unroll
    for (int nf = 0; nf < 4; nf++) {
#pragma unroll
        for (int o = 4; o < 32; o <<= 1) {
            cs0[nf] += __shfl_xor_sync(0xFFFFFFFFu, cs0[nf], o);
            cs1[nf] += __shfl_xor_sync(0xFFFFFFFFu, cs1[nf], o);
        }
    }
    if (lane < 4) {
#pragma unroll
        for (int nf = 0; nf < 4; nf++) {
            int col = nwarp + nf * 8 + lane * 2;
            atomicAdd(&colsq[col], cs0[nf]);
            atomicAdd(&colsq[col + 1], cs1[nf]);
        }
    }
    __syncthreads();
    if (tid < 64) invs[tid] = 16.0f / fmaxf(sqrtf(colsq[tid]), 1e-12f);
    __syncthreads();

    float* ob = out + (size_t)b * CIN * HW + pos0;
#pragma unroll
    for (int mi = 0; mi < 4; mi++) {
        int row = mwarp + mi * 16 + (lane >> 2);
        float gr0 = gout[row], gr1 = gout[row + 8];
#pragma unroll
        for (int nf = 0; nf < 4; nf++) {
            int col = nwarp + nf * 8 + (lane & 3) * 2;
            float i0 = invs[col], i1 = invs[col + 1];
            *(float2*)(ob + (size_t)row * HW + col) =
                make_float2(acc[mi][nf][0] * i0 * gr0, acc[mi][nf][1] * i1 * gr0);
            *(float2*)(ob + (size_t)(row + 8) * HW + col) =
                make_float2(acc[mi][nf][2] * i0 * gr1, acc[mi][nf][3] * i1 * gr1);
        }
    }
}

// ---------------------------------------------------------------------------
extern "C" void kernel_launch(void* const* d_in, const int* in_sizes, int n_in,
                              void* d_out, int out_size) {
    const float* x      = (const float*)d_in[0];
    const float* g_in   = (const float*)d_in[1];
    const float* w_qkv  = (const float*)d_in[2];
    const float* mem_kv = (const float*)d_in[3];
    const float* w_out  = (const float*)d_in[4];
    const float* b_out  = (const float*)d_in[5];
    const float* g_out  = (const float*)d_in[6];
    float* out = (float*)d_out;

    float *s_ptr, *qkv_ptr, *rmax_ptr, *rinv_ptr, *part_ptr, *ctx_ptr;
    __half *w1_ptr, *wo1_ptr, *x1_ptr, *a1_ptr;
    cudaGetSymbolAddress((void**)&s_ptr,    g_s);
    cudaGetSymbolAddress((void**)&w1_ptr,   g_w1);
    cudaGetSymbolAddress((void**)&wo1_ptr,  g_wo1);
    cudaGetSymbolAddress((void**)&x1_ptr,   g_x1);
    cudaGetSymbolAddress((void**)&qkv_ptr,  g_qkv);
    cudaGetSymbolAddress((void**)&rmax_ptr, g_rmax);
    cudaGetSymbolAddress((void**)&rinv_ptr, g_rinv);
    cudaGetSymbolAddress((void**)&part_ptr, g_part);
    cudaGetSymbolAddress((void**)&ctx_ptr,  g_ctx);
    cudaGetSymbolAddress((void**)&a1_ptr,   g_a1);

    cudaFuncSetAttribute(qkv_mma_kernel,
                         cudaFuncAttributeMaxDynamicSharedMemorySize, QSMTOT);
    cudaFuncSetAttribute(outnorm_mma_kernel,
                         cudaFuncAttributeMaxDynamicSharedMemorySize, OSMTOT);

    colscale_kernel<<<(BATCH * HW + 255) / 256, 256>>>(x, s_ptr);
    wconv_kernel<<<(O3 * CIN + 255) / 256, 256>>>(w_qkv, g_in, w1_ptr);
    woconv_kernel<<<(CIN * HID + 255) / 256, 256>>>(w_out, wo1_ptr);
    xconv_kernel<<<dim3(HW / 32, CIN / 32, BATCH), 256>>>(x, s_ptr, x1_ptr);
    qkv_mma_kernel<<<dim3(HW / 128, O3 / 128, BATCH), 256, QSMTOT>>>(
        w1_ptr, x1_ptr, qkv_ptr);
    kstats_kernel<<<dim3(HD, NH, BATCH), 256>>>(qkv_ptr, mem_kv, rmax_ptr, rinv_ptr);
    ctxpart_kernel<<<dim3(NC, NH, BATCH), 256>>>(qkv_ptr, rmax_ptr, part_ptr);
    ctxreduce_kernel<<<dim3(NH, BATCH), 256>>>(part_ptr, mem_kv, rmax_ptr, rinv_ptr, ctx_ptr);
    attend_kernel<<<dim3(HW / 64, NH, BATCH), 256>>>(qkv_ptr, ctx_ptr, a1_ptr);
    outnorm_mma_kernel<<<dim3(HW / 64, BATCH), 256, OSMTOT>>>(
        wo1_ptr, a1_ptr, b_out, g_out, out);
}

// round 12
// speedup vs baseline: 1.9560x; 1.1474x over previous
#include <cuda_runtime.h>
#include <cuda_fp16.h>
#include <math.h>
#include <stdint.h>
#include <string.h>

// Problem constants
#define BATCH 16
#define CIN   256
#define HW    4096
#define O3    1536
#define HID   512
#define NH    8
#define HD    64
#define NMEM  4
#define NC    8
#define CHUNK 512

typedef unsigned long long u64;

// Scratch (device globals — allocation-free rule)
__device__ __half g_w1[O3 * CIN];
__device__ __half g_wo1[CIN * HID];
__device__ __half g_x1[(size_t)BATCH * HW * CIN];   // transposed [b][n][c], fp16
__device__ __half g_qkv[(size_t)BATCH * O3 * HW];   // 201 MB, fp16
__device__ float g_rmax[BATCH * NH * HD];
__device__ float g_rinv[BATCH * NH * HD];
__device__ float g_part[(size_t)NC * BATCH * NH * HD * HD];
__device__ float g_ctx[BATCH * NH * HD * HD];
__device__ __half g_a1[(size_t)BATCH * HW * HID];   // att^T [b][pos][hid], fp16

// ---- packed f32x2 helpers ------------------------------------------------
__device__ __forceinline__ u64 pack_dup(float v) {
    u64 r; asm("mov.b64 %0, {%1, %2};" : "=l"(r) : "f"(v), "f"(v)); return r;
}
__device__ __forceinline__ void ffma2(u64& d, u64 a, u64 b) {
    asm("fma.rn.f32x2 %0, %1, %2, %0;" : "+l"(d) : "l"(a), "l"(b));
}
__device__ __forceinline__ float2 unpack2(u64 v) {
    float2 f; asm("mov.b64 {%0, %1}, %2;" : "=f"(f.x), "=f"(f.y) : "l"(v)); return f;
}

// ---- mma.sync helpers ------------------------------------------------------
__device__ __forceinline__ uint32_t smem_u32(const void* p) {
    uint32_t a;
    asm("{ .reg .u64 t; cvta.to.shared.u64 t, %1; cvt.u32.u64 %0, t; }"
        : "=r"(a) : "l"(p));
    return a;
}
__device__ __forceinline__ void ldm4(uint32_t* r, uint32_t addr) {
    asm volatile("ldmatrix.sync.aligned.m8n8.x4.shared.b16 {%0,%1,%2,%3}, [%4];"
                 : "=r"(r[0]), "=r"(r[1]), "=r"(r[2]), "=r"(r[3]) : "r"(addr));
}
__device__ __forceinline__ void mma_f16(float* c, const uint32_t* a,
                                        uint32_t b0, uint32_t b1) {
    asm volatile(
        "mma.sync.aligned.m16n8k16.row.col.f32.f16.f16.f32 "
        "{%0,%1,%2,%3}, {%4,%5,%6,%7}, {%8,%9}, {%0,%1,%2,%3};"
        : "+f"(c[0]), "+f"(c[1]), "+f"(c[2]), "+f"(c[3])
        : "r"(a[0]), "r"(a[1]), "r"(a[2]), "r"(a[3]), "r"(b0), "r"(b1));
}
__device__ __forceinline__ void cp16(uint32_t dst, const void* src) {
    asm volatile("cp.async.cg.shared.global [%0], [%1], 16;"
                 :: "r"(dst), "l"(src));
}
#define CP_COMMIT() asm volatile("cp.async.commit_group;" ::: "memory")
#define CP_WAIT1()  asm volatile("cp.async.wait_group 1;" ::: "memory")
#define CP_WAIT0()  asm volatile("cp.async.wait_group 0;" ::: "memory")

__device__ __forceinline__ uint32_t pkh(float lo, float hi) {
    __half2 t = __floats2half2_rn(lo, hi);
    uint32_t r; memcpy(&r, &t, 4); return r;
}

// ---------------------------------------------------------------------------
// Kernel 1: fused rmsnorm-scale + transpose + fp16 convert.
// Block = (32 positions, all 256 channels) of one batch. Reads x ONCE.
// ---------------------------------------------------------------------------
__global__ __launch_bounds__(256) void xnorm_kernel(const float* __restrict__ x,
                                                    __half* __restrict__ x1) {
    int b = blockIdx.y;
    int n0 = blockIdx.x * 32;
    __shared__ float t[256][33];
    __shared__ float ps[8][33];
    __shared__ float sv[32];
    int tid = threadIdx.x;
    int tx = tid & 31, ty = tid >> 5;

    const float* xb = x + (size_t)b * CIN * HW + n0;
#pragma unroll
    for (int i = 0; i < 32; i++) {
        int c = ty + i * 8;
        t[c][tx] = xb[(size_t)c * HW + tx];
    }
    __syncthreads();

    // column sum of squares: group ty sums channels [ty*32, ty*32+32)
    {
        float a = 0.f;
#pragma unroll
        for (int j = 0; j < 32; j++) {
            float v = t[ty * 32 + j][tx];
            a += v * v;
        }
        ps[ty][tx] = a;
    }
    __syncthreads();
    if (tid < 32) {
        float a = 0.f;
#pragma unroll
        for (int g = 0; g < 8; g++) a += ps[g][tid];
        sv[tid] = 16.0f / fmaxf(sqrtf(a), 1e-12f);
    }
    __syncthreads();

    // write transposed fp16: thread handles c0 = cb*64 + tx*2, row nr
#pragma unroll
    for (int cb = 0; cb < 4; cb++) {
#pragma unroll
        for (int i = 0; i < 4; i++) {
            int nr = ty + i * 8;
            int c0 = cb * 64 + tx * 2;
            float s = sv[nr];
            uint32_t h = pkh(t[c0][nr] * s, t[c0 + 1][nr] * s);
            *(uint32_t*)((char*)x1 +
                (((size_t)b * HW + n0 + nr) * CIN + c0) * 2) = h;
        }
    }
}

// ---------------------------------------------------------------------------
// Kernel 1b: W fold -> single fp16
// ---------------------------------------------------------------------------
__global__ __launch_bounds__(256) void wconv_kernel(const float* __restrict__ w,
                                                    const float* __restrict__ g,
                                                    __half* __restrict__ w1) {
    int i = blockIdx.x * 256 + threadIdx.x;
    if (i < O3 * CIN) w1[i] = __float2half_rn(w[i] * g[i & (CIN - 1)]);
}

// Kernel 1b2: w_out -> single fp16
__global__ __launch_bounds__(256) void woconv_kernel(const float* __restrict__ w,
                                                     __half* __restrict__ w1) {
    int i = blockIdx.x * 256 + threadIdx.x;
    if (i < CIN * HID) w1[i] = __float2half_rn(w[i]);
}

// ---------------------------------------------------------------------------
// Kernel 2: QKV GEMM, mma.sync fp16 single product, fp16 output.
// CTA tile 128x128, K-tile 32, LDK=40 -> 40KB smem -> 2 CTAs/SM.
// ---------------------------------------------------------------------------
#define QLDK   40
#define QT_B   (128 * QLDK * 2)
#define QSTAGE (2 * QT_B)
#define QSMTOT (2 * QSTAGE)
#define Q_A    0
#define Q_B    QT_B

__global__ void __launch_bounds__(256, 2)
qkv_mma_kernel(const __half* __restrict__ w1,
               const __half* __restrict__ x1,
               __half* __restrict__ out) {
    extern __shared__ char smem[];
    uint32_t sb = smem_u32(smem);
    int tid = threadIdx.x;
    int warp = tid >> 5, lane = tid & 31;
    int b = blockIdx.z;
    int rowBase = blockIdx.y * 128;
    int colBase = blockIdx.x * 128;

    const char* srcA = (const char*)(w1 + (size_t)rowBase * CIN);
    const char* srcB = (const char*)(x1 + ((size_t)b * HW + colBase) * CIN);

    int lrow = tid >> 2, lseg = tid & 3;

    auto load_stage = [&](int st, int k0) {
        uint32_t dbase = sb + st * QSTAGE;
#pragma unroll
        for (int j = 0; j < 2; j++) {
            int row = lrow + j * 64;
            uint32_t dp = dbase + row * (QLDK * 2) + lseg * 16;
            size_t go = (size_t)row * (CIN * 2) + k0 * 2 + lseg * 16;
            cp16(dp + Q_A, srcA + go);
            cp16(dp + Q_B, srcB + go);
        }
    };

    int mwarp = (warp >> 1) * 32;
    int nwarp = (warp & 1) * 64;

    float acc[2][8][4];
#pragma unroll
    for (int mi = 0; mi < 2; mi++)
#pragma unroll
        for (int nf = 0; nf < 8; nf++)
#pragma unroll
            for (int q = 0; q < 4; q++) acc[mi][nf][q] = 0.f;

    int flrow = lane & 7, mat = lane >> 3;
    int frow = (mat & 1) * 8 + flrow;
    int fk   = (mat >> 1) * 8;

    load_stage(0, 0);
    CP_COMMIT();

    for (int kt = 0; kt < 8; kt++) {
        if (kt < 7) {
            load_stage((kt + 1) & 1, (kt + 1) * 32);
            CP_COMMIT();
            CP_WAIT1();
        } else {
            CP_WAIT0();
        }
        __syncthreads();
        uint32_t stb = sb + (kt & 1) * QSTAGE;

#pragma unroll
        for (int ks = 0; ks < 2; ks++) {
            int kk = ks * 16 + fk;
            uint32_t fa[2][4], fb[4][4];
#pragma unroll
            for (int mi = 0; mi < 2; mi++)
                ldm4(fa[mi], stb + Q_A +
                     (uint32_t)((mwarp + mi * 16 + frow) * (QLDK * 2) + kk * 2));
#pragma unroll
            for (int nb = 0; nb < 4; nb++)
                ldm4(fb[nb], stb + Q_B +
                     (uint32_t)((nwarp + nb * 16 + frow) * (QLDK * 2) + kk * 2));
#pragma unroll
            for (int mi = 0; mi < 2; mi++)
#pragma unroll
                for (int nf = 0; nf < 8; nf++) {
                    int nb = nf >> 1, hi = nf & 1;
                    mma_f16(acc[mi][nf], fa[mi], fb[nb][hi], fb[nb][hi + 2]);
                }
        }
        __syncthreads();
    }

    __half* obase = out + (size_t)b * O3 * HW;
#pragma unroll
    for (int mi = 0; mi < 2; mi++) {
        int row = rowBase + mwarp + mi * 16 + (lane >> 2);
#pragma unroll
        for (int nf = 0; nf < 8; nf++) {
            int col = colBase + nwarp + nf * 8 + (lane & 3) * 2;
            *(uint32_t*)((char*)obase + ((size_t)row * HW + col) * 2) =
                pkh(acc[mi][nf][0], acc[mi][nf][1]);
            *(uint32_t*)((char*)obase + ((size_t)(row + 8) * HW + col) * 2) =
                pkh(acc[mi][nf][2], acc[mi][nf][3]);
        }
    }
}

// ---------------------------------------------------------------------------
// Kernel 3a: k-softmax stats per (b,h,d) row (fp16 input)
// ---------------------------------------------------------------------------
__global__ __launch_bounds__(256) void kstats_kernel(const __half* __restrict__ qkv,
                                                     const float* __restrict__ memkv,
                                                     float* __restrict__ rmax,
                                                     float* __restrict__ rinv) {
    int d = blockIdx.x, h = blockIdx.y, b = blockIdx.z;
    int tid = threadIdx.x;
    const __half2* kr = (const __half2*)(qkv + ((size_t)b * O3 + HID + h * HD + d) * HW);
    const float* MK = memkv + ((size_t)h * HD + d) * NMEM;

    float v[16];
#pragma unroll
    for (int i = 0; i < 8; i++) {
        float2 p = __half22float2(kr[i * 256 + tid]);
        v[2 * i] = p.x;
        v[2 * i + 1] = p.y;
    }
    float m = v[0];
#pragma unroll
    for (int i = 1; i < 16; i++) m = fmaxf(m, v[i]);
    if (tid < NMEM) m = fmaxf(m, MK[tid]);

    __shared__ float red[8];
#pragma unroll
    for (int o = 16; o; o >>= 1) m = fmaxf(m, __shfl_xor_sync(0xFFFFFFFFu, m, o));
    if ((tid & 31) == 0) red[tid >> 5] = m;
    __syncthreads();
    if (tid == 0) {
        float t = red[0];
#pragma unroll
        for (int i = 1; i < 8; i++) t = fmaxf(t, red[i]);
        red[0] = t;
    }
    __syncthreads();
    m = red[0];
    __syncthreads();

    float ss = 0.f;
#pragma unroll
    for (int i = 0; i < 16; i++) ss += __expf(v[i] - m);
    if (tid < NMEM) ss += __expf(MK[tid] - m);
#pragma unroll
    for (int o = 16; o; o >>= 1) ss += __shfl_xor_sync(0xFFFFFFFFu, ss, o);
    if ((tid & 31) == 0) red[tid >> 5] = ss;
    __syncthreads();
    if (tid == 0) {
        float t = 0.f;
#pragma unroll
        for (int i = 0; i < 8; i++) t += red[i];
        int idx = (b * NH + h) * HD + d;
        rmax[idx] = m;
        rinv[idx] = 1.0f / t;
    }
}

// ---------------------------------------------------------------------------
// Kernel 3b: partial context over n chunks (FFMA2 SIMT, fp16 input)
// ---------------------------------------------------------------------------
__global__ __launch_bounds__(256) void ctxpart_kernel(const __half* __restrict__ qkv,
                                                      const float* __restrict__ rmax,
                                                      float* __restrict__ part) {
    int c = blockIdx.x, h = blockIdx.y, b = blockIdx.z;
    const __half* K = qkv + ((size_t)b * O3 + HID + h * HD) * HW;
    const __half* V = qkv + ((size_t)b * O3 + 2 * HID + h * HD) * HW;

    __shared__ __align__(16) float Kt[64][68];
    __shared__ __align__(16) float Vt[64][68];
    __shared__ float rm[64];

    int tid = threadIdx.x;
    if (tid < 64) rm[tid] = rmax[(b * NH + h) * HD + tid];
    __syncthreads();

    int tx = tid & 15, ty = tid >> 4;
    u64 acc[4][2];
#pragma unroll
    for (int i = 0; i < 4; i++) { acc[i][0] = 0ULL; acc[i][1] = 0ULL; }

    for (int nt = 0; nt < CHUNK / 64; nt++) {
        int n0 = c * CHUNK + nt * 64;
#pragma unroll
        for (int l = 0; l < 8; l++) {
            int lin = l * 512 + tid * 2;
            int d = lin >> 6, j = lin & 63;
            float2 kv = __half22float2(*(const __half2*)(K + (size_t)d * HW + n0 + j));
            float2 vv = __half22float2(*(const __half2*)(V + (size_t)d * HW + n0 + j));
            Kt[j][d]     = __expf(kv.x - rm[d]);
            Kt[j + 1][d] = __expf(kv.y - rm[d]);
            Vt[j][d]     = vv.x;
            Vt[j + 1][d] = vv.y;
        }
        __syncthreads();
#pragma unroll 4
        for (int j = 0; j < 64; j++) {
            float4 kf = *(const float4*)(&Kt[j][ty * 4]);
            u64 k0 = pack_dup(kf.x), k1 = pack_dup(kf.y);
            u64 k2 = pack_dup(kf.z), k3 = pack_dup(kf.w);
            ulonglong2 vv = *(const ulonglong2*)(&Vt[j][tx * 4]);
            ffma2(acc[0][0], k0, vv.x); ffma2(acc[0][1], k0, vv.y);
            ffma2(acc[1][0], k1, vv.x); ffma2(acc[1][1], k1, vv.y);
            ffma2(acc[2][0], k2, vv.x); ffma2(acc[2][1], k2, vv.y);
            ffma2(acc[3][0], k3, vv.x); ffma2(acc[3][1], k3, vv.y);
        }
        __syncthreads();
    }

    float* pb = part + ((size_t)c * BATCH * NH + b * NH + h) * (HD * HD);
#pragma unroll
    for (int i = 0; i < 4; i++) {
        float2 a = unpack2(acc[i][0]);
        float2 bb = unpack2(acc[i][1]);
        *(float4*)(&pb[(ty * 4 + i) * HD + tx * 4]) = make_float4(a.x, a.y, bb.x, bb.y);
    }
}

// ---------------------------------------------------------------------------
// Kernel 3c: reduce partials + mem-kv tail + rinv scaling -> ctx
// ---------------------------------------------------------------------------
__global__ __launch_bounds__(256) void ctxreduce_kernel(const float* __restrict__ part,
                                                        const float* __restrict__ memkv,
                                                        const float* __restrict__ rmax,
                                                        const float* __restrict__ rinv,
                                                        float* __restrict__ ctx) {
    int h = blockIdx.x, b = blockIdx.y;
    __shared__ float mkx[64][4];
    __shared__ float mvs[64][4];
    __shared__ float riv[64];
    int tid = threadIdx.x;
    if (tid < 64) riv[tid] = rinv[(b * NH + h) * HD + tid];
    {
        int d = tid >> 2, j = tid & 3;
        mkx[d][j] = __expf(memkv[((size_t)h * HD + d) * NMEM + j] -
                           rmax[(b * NH + h) * HD + d]);
        mvs[d][j] = memkv[(size_t)NH * HD * NMEM + ((size_t)h * HD + d) * NMEM + j];
    }
    __syncthreads();
    size_t base = (size_t)(b * NH + h) * (HD * HD);
    for (int l = tid; l < HD * HD; l += 256) {
        int d = l >> 6, e = l & 63;
        float s2 = 0.f;
#pragma unroll
        for (int cc = 0; cc < NC; cc++)
            s2 += part[(size_t)cc * BATCH * NH * HD * HD + base + l];
#pragma unroll
        for (int j = 0; j < 4; j++) s2 += mkx[d][j] * mvs[e][j];
        ctx[base + l] = s2 * riv[d];
    }
}

// ---------------------------------------------------------------------------
// Kernel 4: q-softmax + out[e][p] = sum_d ctx[d][e]*qs[d][p]; fp16 Q in,
// fp16 transposed a1 out.
// ---------------------------------------------------------------------------
__global__ __launch_bounds__(256) void attend_kernel(const __half* __restrict__ qkv,
                                                     const float* __restrict__ ctx,
                                                     __half* __restrict__ a1) {
    int pos0 = blockIdx.x * 64;
    int h = blockIdx.y, b = blockIdx.z;
    const __half* Q = qkv + ((size_t)b * O3 + h * HD) * HW;
    const float* cb = ctx + (size_t)(b * NH + h) * HD * HD;

    __shared__ __align__(16) float cs[64][68];
    __shared__ __align__(16) float qs[64][68];

    int tid = threadIdx.x;
    for (int l = tid; l < HD * HD / 2; l += 256) {
        int d = l >> 5, e2 = (l & 31) * 2;
        float2 qv = __half22float2(*(const __half2*)(Q + (size_t)d * HW + pos0 + e2));
        qs[d][e2] = qv.x;
        qs[d][e2 + 1] = qv.y;
        cs[d][e2] = cb[d * HD + e2];
        cs[d][e2 + 1] = cb[d * HD + e2 + 1];
    }
    __syncthreads();

    if (tid < 64) {
        float m = -1e30f;
#pragma unroll
        for (int d = 0; d < HD; d++) m = fmaxf(m, qs[d][tid]);
        float ss = 0.f;
#pragma unroll
        for (int d = 0; d < HD; d++) ss += __expf(qs[d][tid] - m);
        float inv = 0.125f / ss;
#pragma unroll
        for (int d = 0; d < HD; d++)
            qs[d][tid] = __expf(qs[d][tid] - m) * inv;
    }
    __syncthreads();

    int tx = tid & 15, ty = tid >> 4;
    u64 acc[4][2];
#pragma unroll
    for (int i = 0; i < 4; i++) { acc[i][0] = 0ULL; acc[i][1] = 0ULL; }

#pragma unroll 4
    for (int d = 0; d < HD; d++) {
        float4 cf = *(const float4*)(&cs[d][ty * 4]);
        u64 c0 = pack_dup(cf.x), c1 = pack_dup(cf.y);
        u64 c2 = pack_dup(cf.z), c3 = pack_dup(cf.w);
        ulonglong2 qq = *(const ulonglong2*)(&qs[d][tx * 4]);
        ffma2(acc[0][0], c0, qq.x); ffma2(acc[0][1], c0, qq.y);
        ffma2(acc[1][0], c1, qq.x); ffma2(acc[1][1], c1, qq.y);
        ffma2(acc[2][0], c2, qq.x); ffma2(acc[2][1], c2, qq.y);
        ffma2(acc[3][0], c3, qq.x); ffma2(acc[3][1], c3, qq.y);
    }

    // Stage transposed result into cs as os[pos][e]
    __syncthreads();
#pragma unroll
    for (int i = 0; i < 4; i++) {
        float2 a = unpack2(acc[i][0]);
        float2 bb = unpack2(acc[i][1]);
        int e = ty * 4 + i;
        cs[tx * 4 + 0][e] = a.x;
        cs[tx * 4 + 1][e] = a.y;
        cs[tx * 4 + 2][e] = bb.x;
        cs[tx * 4 + 3][e] = bb.y;
    }
    __syncthreads();

    {
        int pos = tid >> 2, e0 = (tid & 3) * 16;
        size_t base = ((size_t)b * HW + pos0 + pos) * HID + h * HD + e0;
        uint32_t r1[8];
#pragma unroll
        for (int u = 0; u < 8; u++)
            r1[u] = pkh(cs[pos][e0 + 2 * u], cs[pos][e0 + 2 * u + 1]);
        *(uint4*)((char*)a1 + base * 2)      = make_uint4(r1[0], r1[1], r1[2], r1[3]);
        *(uint4*)((char*)a1 + base * 2 + 16) = make_uint4(r1[4], r1[5], r1[6], r1[7]);
    }
}

// ---------------------------------------------------------------------------
// Kernel 5: out GEMM fp16 single product + bias + fused rmsnorm.
// CTA tile 256x64, K-tile 32, LDK=40 -> 51KB total -> 2 CTAs/SM.
// ---------------------------------------------------------------------------
#define OLDK   40
#define OA_T   (256 * OLDK * 2)
#define OB_T   (64 * OLDK * 2)
#define OSTAGE (OA_T + OB_T)
#define OSMTOT (2 * OSTAGE)
#define O_A    0
#define O_B    OA_T

__global__ void __launch_bounds__(256, 2)
outnorm_mma_kernel(const __half* __restrict__ wo1,
                   const __half* __restrict__ a1,
                   const float* __restrict__ bias,
                   const float* __restrict__ gout,
                   float* __restrict__ out) {
    extern __shared__ char smem[];
    uint32_t sb = smem_u32(smem);
    __shared__ float colsq[64];
    __shared__ float invs[64];

    int tid = threadIdx.x;
    int warp = tid >> 5, lane = tid & 31;
    int b = blockIdx.y;
    int pos0 = blockIdx.x * 64;

    const char* srcA = (const char*)wo1;
    const char* srcB = (const char*)(a1 + ((size_t)b * HW + pos0) * HID);

    int lrow = tid >> 2, lseg = tid & 3;

    auto load_stage = [&](int st, int k0) {
        uint32_t dbase = sb + st * OSTAGE;
#pragma unroll
        for (int j = 0; j < 4; j++) {
            int row = lrow + j * 64;
            cp16(dbase + O_A + row * (OLDK * 2) + lseg * 16,
                 srcA + (size_t)row * (HID * 2) + k0 * 2 + lseg * 16);
        }
        {
            int row = lrow;
            cp16(dbase + O_B + row * (OLDK * 2) + lseg * 16,
                 srcB + (size_t)row * (HID * 2) + k0 * 2 + lseg * 16);
        }
    };

    int mwarp = (warp >> 1) * 64;
    int nwarp = (warp & 1) * 32;

    float acc[4][4][4];
#pragma unroll
    for (int mi = 0; mi < 4; mi++)
#pragma unroll
        for (int nf = 0; nf < 4; nf++)
#pragma unroll
            for (int q = 0; q < 4; q++) acc[mi][nf][q] = 0.f;

    int flrow = lane & 7, mat = lane >> 3;
    int frow = (mat & 1) * 8 + flrow;
    int fk   = (mat >> 1) * 8;

    if (tid < 64) colsq[tid] = 0.f;

    load_stage(0, 0);
    CP_COMMIT();

    for (int kt = 0; kt < 16; kt++) {
        if (kt < 15) {
            load_stage((kt + 1) & 1, (kt + 1) * 32);
            CP_COMMIT();
            CP_WAIT1();
        } else {
            CP_WAIT0();
        }
        __syncthreads();
        uint32_t stb = sb + (kt & 1) * OSTAGE;

#pragma unroll
        for (int ks = 0; ks < 2; ks++) {
            int kk = ks * 16 + fk;
            uint32_t fa[4][4], fb[2][4];
#pragma unroll
            for (int mi = 0; mi < 4; mi++)
                ldm4(fa[mi], stb + O_A +
                     (uint32_t)((mwarp + mi * 16 + frow) * (OLDK * 2) + kk * 2));
#pragma unroll
            for (int nb = 0; nb < 2; nb++)
                ldm4(fb[nb], stb + O_B +
                     (uint32_t)((nwarp + nb * 16 + frow) * (OLDK * 2) + kk * 2));
#pragma unroll
            for (int mi = 0; mi < 4; mi++)
#pragma unroll
                for (int nf = 0; nf < 4; nf++) {
                    int nb = nf >> 1, hi = nf & 1;
                    mma_f16(acc[mi][nf], fa[mi], fb[nb][hi], fb[nb][hi + 2]);
                }
        }
        __syncthreads();
    }

    // bias + column sum-of-squares
    float cs0[4], cs1[4];
#pragma unroll
    for (int nf = 0; nf < 4; nf++) { cs0[nf] = 0.f; cs1[nf] = 0.f; }
#pragma unroll
    for (int mi = 0; mi < 4; mi++) {
        int row = mwarp + mi * 16 + (lane >> 2);
        float bi0 = bias[row], bi1 = bias[row + 8];
#pragma unroll
        for (int nf = 0; nf < 4; nf++) {
            acc[mi][nf][0] += bi0;
            acc[mi][nf][1] += bi0;
            acc[mi][nf][2] += bi1;
            acc[mi][nf][3] += bi1;
            cs0[nf] += acc[mi][nf][0] * acc[mi][nf][0] + acc[mi][nf][2] * acc[mi][nf][2];
            cs1[nf] += acc[mi][nf][1] * acc[mi][nf][1] + acc[mi][nf][3] * acc[mi][nf][3];
        }
    }
#pragma unroll
    for (int nf = 0; nf < 4; nf++) {
#pragma unroll
        for (int o = 4; o < 32; o <<= 1) {
            cs0[nf] += __shfl_xor_sync(0xFFFFFFFFu, cs0[nf], o);
            cs1[nf] += __shfl_xor_sync(0xFFFFFFFFu, cs1[nf], o);
        }
    }
    if (lane < 4) {
#pragma unroll
        for (int nf = 0; nf < 4; nf++) {
            int col = nwarp + nf * 8 + lane * 2;
            atomicAdd(&colsq[col], cs0[nf]);
            atomicAdd(&colsq[col + 1], cs1[nf]);
        }
    }
    __syncthreads();
    if (tid < 64) invs[tid] = 16.0f / fmaxf(sqrtf(colsq[tid]), 1e-12f);
    __syncthreads();

    float* ob = out + (size_t)b * CIN * HW + pos0;
#pragma unroll
    for (int mi = 0; mi < 4; mi++) {
        int row = mwarp + mi * 16 + (lane >> 2);
        float gr0 = gout[row], gr1 = gout[row + 8];
#pragma unroll
        for (int nf = 0; nf < 4; nf++) {
            int col = nwarp + nf * 8 + (lane & 3) * 2;
            float i0 = invs[col], i1 = invs[col + 1];
            *(float2*)(ob + (size_t)row * HW + col) =
                make_float2(acc[mi][nf][0] * i0 * gr0, acc[mi][nf][1] * i1 * gr0);
            *(float2*)(ob + (size_t)(row + 8) * HW + col) =
                make_float2(acc[mi][nf][2] * i0 * gr1, acc[mi][nf][3] * i1 * gr1);
        }
    }
}

// ---------------------------------------------------------------------------
extern "C" void kernel_launch(void* const* d_in, const int* in_sizes, int n_in,
                              void* d_out, int out_size) {
    const float* x      = (const float*)d_in[0];
    const float* g_in   = (const float*)d_in[1];
    const float* w_qkv  = (const float*)d_in[2];
    const float* mem_kv = (const float*)d_in[3];
    const float* w_out  = (const float*)d_in[4];
    const float* b_out  = (const float*)d_in[5];
    const float* g_out  = (const float*)d_in[6];
    float* out = (float*)d_out;

    float *rmax_ptr, *rinv_ptr, *part_ptr, *ctx_ptr;
    __half *w1_ptr, *wo1_ptr, *x1_ptr, *qkv_ptr, *a1_ptr;
    cudaGetSymbolAddress((void**)&w1_ptr,   g_w1);
    cudaGetSymbolAddress((void**)&wo1_ptr,  g_wo1);
    cudaGetSymbolAddress((void**)&x1_ptr,   g_x1);
    cudaGetSymbolAddress((void**)&qkv_ptr,  g_qkv);
    cudaGetSymbolAddress((void**)&rmax_ptr, g_rmax);
    cudaGetSymbolAddress((void**)&rinv_ptr, g_rinv);
    cudaGetSymbolAddress((void**)&part_ptr, g_part);
    cudaGetSymbolAddress((void**)&ctx_ptr,  g_ctx);
    cudaGetSymbolAddress((void**)&a1_ptr,   g_a1);

    cudaFuncSetAttribute(qkv_mma_kernel,
                         cudaFuncAttributeMaxDynamicSharedMemorySize, QSMTOT);
    cudaFuncSetAttribute(outnorm_mma_kernel,
                         cudaFuncAttributeMaxDynamicSharedMemorySize, OSMTOT);

    wconv_kernel<<<(O3 * CIN + 255) / 256, 256>>>(w_qkv, g_in, w1_ptr);
    woconv_kernel<<<(CIN * HID + 255) / 256, 256>>>(w_out, wo1_ptr);
    xnorm_kernel<<<dim3(HW / 32, BATCH), 256>>>(x, x1_ptr);
    qkv_mma_kernel<<<dim3(HW / 128, O3 / 128, BATCH), 256, QSMTOT>>>(
        w1_ptr, x1_ptr, qkv_ptr);
    kstats_kernel<<<dim3(HD, NH, BATCH), 256>>>(qkv_ptr, mem_kv, rmax_ptr, rinv_ptr);
    ctxpart_kernel<<<dim3(NC, NH, BATCH), 256>>>(qkv_ptr, rmax_ptr, part_ptr);
    ctxreduce_kernel<<<dim3(NH, BATCH), 256>>>(part_ptr, mem_kv, rmax_ptr, rinv_ptr, ctx_ptr);
    attend_kernel<<<dim3(HW / 64, NH, BATCH), 256>>>(qkv_ptr, ctx_ptr, a1_ptr);
    outnorm_mma_kernel<<<dim3(HW / 64, BATCH), 256, OSMTOT>>>(
        wo1_ptr, a1_ptr, b_out, g_out, out);
}

// round 13
// speedup vs baseline: 2.3644x; 1.2087x over previous
#include <cuda_runtime.h>
#include <cuda_fp16.h>
#include <math.h>
#include <stdint.h>
#include <string.h>

// Problem constants
#define BATCH 16
#define CIN   256
#define HW    4096
#define O3    1536
#define HID   512
#define NH    8
#define HD    64
#define NMEM  4
#define NC    8
#define CHUNK 512

// Scratch (device globals — allocation-free rule)
__device__ __half g_w1[O3 * CIN];
__device__ __half g_wo1[CIN * HID];
__device__ __half g_x1[(size_t)BATCH * HW * CIN];   // transposed [b][n][c], fp16
__device__ __half g_qkv[(size_t)BATCH * O3 * HW];   // 201 MB, fp16
__device__ __half g_ek[(size_t)BATCH * NH * HD * HW]; // exp(K-rmax)*rinv, fp16, 67MB
__device__ float g_rmax[BATCH * NH * HD];
__device__ float g_rinv[BATCH * NH * HD];
__device__ float g_part[(size_t)NC * BATCH * NH * HD * HD];
__device__ float g_ctx[BATCH * NH * HD * HD];
__device__ __half g_a1[(size_t)BATCH * HW * HID];   // att^T [b][pos][hid], fp16

// ---- mma.sync helpers ------------------------------------------------------
__device__ __forceinline__ uint32_t smem_u32(const void* p) {
    uint32_t a;
    asm("{ .reg .u64 t; cvta.to.shared.u64 t, %1; cvt.u32.u64 %0, t; }"
        : "=r"(a) : "l"(p));
    return a;
}
__device__ __forceinline__ void ldm4(uint32_t* r, uint32_t addr) {
    asm volatile("ldmatrix.sync.aligned.m8n8.x4.shared.b16 {%0,%1,%2,%3}, [%4];"
                 : "=r"(r[0]), "=r"(r[1]), "=r"(r[2]), "=r"(r[3]) : "r"(addr));
}
__device__ __forceinline__ void mma_f16(float* c, const uint32_t* a,
                                        uint32_t b0, uint32_t b1) {
    asm volatile(
        "mma.sync.aligned.m16n8k16.row.col.f32.f16.f16.f32 "
        "{%0,%1,%2,%3}, {%4,%5,%6,%7}, {%8,%9}, {%0,%1,%2,%3};"
        : "+f"(c[0]), "+f"(c[1]), "+f"(c[2]), "+f"(c[3])
        : "r"(a[0]), "r"(a[1]), "r"(a[2]), "r"(a[3]), "r"(b0), "r"(b1));
}
__device__ __forceinline__ void cp16(uint32_t dst, const void* src) {
    asm volatile("cp.async.cg.shared.global [%0], [%1], 16;"
                 :: "r"(dst), "l"(src));
}
#define CP_COMMIT() asm volatile("cp.async.commit_group;" ::: "memory")
#define CP_WAIT1()  asm volatile("cp.async.wait_group 1;" ::: "memory")
#define CP_WAIT0()  asm volatile("cp.async.wait_group 0;" ::: "memory")

__device__ __forceinline__ uint32_t pkh(float lo, float hi) {
    __half2 t = __floats2half2_rn(lo, hi);
    uint32_t r; memcpy(&r, &t, 4); return r;
}

// ---------------------------------------------------------------------------
// Kernel 1: fused rmsnorm-scale + transpose + fp16 convert.
// ---------------------------------------------------------------------------
__global__ __launch_bounds__(256) void xnorm_kernel(const float* __restrict__ x,
                                                    __half* __restrict__ x1) {
    int b = blockIdx.y;
    int n0 = blockIdx.x * 32;
    __shared__ float t[256][33];
    __shared__ float ps[8][33];
    __shared__ float sv[32];
    int tid = threadIdx.x;
    int tx = tid & 31, ty = tid >> 5;

    const float* xb = x + (size_t)b * CIN * HW + n0;
#pragma unroll
    for (int i = 0; i < 32; i++) {
        int c = ty + i * 8;
        t[c][tx] = xb[(size_t)c * HW + tx];
    }
    __syncthreads();
    {
        float a = 0.f;
#pragma unroll
        for (int j = 0; j < 32; j++) {
            float v = t[ty * 32 + j][tx];
            a += v * v;
        }
        ps[ty][tx] = a;
    }
    __syncthreads();
    if (tid < 32) {
        float a = 0.f;
#pragma unroll
        for (int g = 0; g < 8; g++) a += ps[g][tid];
        sv[tid] = 16.0f / fmaxf(sqrtf(a), 1e-12f);
    }
    __syncthreads();
#pragma unroll
    for (int cb = 0; cb < 4; cb++) {
#pragma unroll
        for (int i = 0; i < 4; i++) {
            int nr = ty + i * 8;
            int c0 = cb * 64 + tx * 2;
            float s = sv[nr];
            uint32_t h = pkh(t[c0][nr] * s, t[c0 + 1][nr] * s);
            *(uint32_t*)((char*)x1 +
                (((size_t)b * HW + n0 + nr) * CIN + c0) * 2) = h;
        }
    }
}

// ---------------------------------------------------------------------------
// Kernel 1b / 1b2: weight converts
// ---------------------------------------------------------------------------
__global__ __launch_bounds__(256) void wconv_kernel(const float* __restrict__ w,
                                                    const float* __restrict__ g,
                                                    __half* __restrict__ w1) {
    int i = blockIdx.x * 256 + threadIdx.x;
    if (i < O3 * CIN) w1[i] = __float2half_rn(w[i] * g[i & (CIN - 1)]);
}
__global__ __launch_bounds__(256) void woconv_kernel(const float* __restrict__ w,
                                                     __half* __restrict__ w1) {
    int i = blockIdx.x * 256 + threadIdx.x;
    if (i < CIN * HID) w1[i] = __float2half_rn(w[i]);
}

// ---------------------------------------------------------------------------
// Kernel 2: QKV GEMM, mma.sync fp16, fp16 out. CTA 128x128, K-tile 32,
// LDK=40, 2 CTAs/SM. (unchanged from R12)
// ---------------------------------------------------------------------------
#define QLDK   40
#define QT_B   (128 * QLDK * 2)
#define QSTAGE (2 * QT_B)
#define QSMTOT (2 * QSTAGE)
#define Q_A    0
#define Q_B    QT_B

__global__ void __launch_bounds__(256, 2)
qkv_mma_kernel(const __half* __restrict__ w1,
               const __half* __restrict__ x1,
               __half* __restrict__ out) {
    extern __shared__ char smem[];
    uint32_t sb = smem_u32(smem);
    int tid = threadIdx.x;
    int warp = tid >> 5, lane = tid & 31;
    int b = blockIdx.z;
    int rowBase = blockIdx.y * 128;
    int colBase = blockIdx.x * 128;

    const char* srcA = (const char*)(w1 + (size_t)rowBase * CIN);
    const char* srcB = (const char*)(x1 + ((size_t)b * HW + colBase) * CIN);

    int lrow = tid >> 2, lseg = tid & 3;

    auto load_stage = [&](int st, int k0) {
        uint32_t dbase = sb + st * QSTAGE;
#pragma unroll
        for (int j = 0; j < 2; j++) {
            int row = lrow + j * 64;
            uint32_t dp = dbase + row * (QLDK * 2) + lseg * 16;
            size_t go = (size_t)row * (CIN * 2) + k0 * 2 + lseg * 16;
            cp16(dp + Q_A, srcA + go);
            cp16(dp + Q_B, srcB + go);
        }
    };

    int mwarp = (warp >> 1) * 32;
    int nwarp = (warp & 1) * 64;

    float acc[2][8][4];
#pragma unroll
    for (int mi = 0; mi < 2; mi++)
#pragma unroll
        for (int nf = 0; nf < 8; nf++)
#pragma unroll
            for (int q = 0; q < 4; q++) acc[mi][nf][q] = 0.f;

    int flrow = lane & 7, mat = lane >> 3;
    int frow = (mat & 1) * 8 + flrow;
    int fk   = (mat >> 1) * 8;

    load_stage(0, 0);
    CP_COMMIT();

    for (int kt = 0; kt < 8; kt++) {
        if (kt < 7) {
            load_stage((kt + 1) & 1, (kt + 1) * 32);
            CP_COMMIT();
            CP_WAIT1();
        } else {
            CP_WAIT0();
        }
        __syncthreads();
        uint32_t stb = sb + (kt & 1) * QSTAGE;

#pragma unroll
        for (int ks = 0; ks < 2; ks++) {
            int kk = ks * 16 + fk;
            uint32_t fa[2][4], fb[4][4];
#pragma unroll
            for (int mi = 0; mi < 2; mi++)
                ldm4(fa[mi], stb + Q_A +
                     (uint32_t)((mwarp + mi * 16 + frow) * (QLDK * 2) + kk * 2));
#pragma unroll
            for (int nb = 0; nb < 4; nb++)
                ldm4(fb[nb], stb + Q_B +
                     (uint32_t)((nwarp + nb * 16 + frow) * (QLDK * 2) + kk * 2));
#pragma unroll
            for (int mi = 0; mi < 2; mi++)
#pragma unroll
                for (int nf = 0; nf < 8; nf++) {
                    int nb = nf >> 1, hi = nf & 1;
                    mma_f16(acc[mi][nf], fa[mi], fb[nb][hi], fb[nb][hi + 2]);
                }
        }
        __syncthreads();
    }

    __half* obase = out + (size_t)b * O3 * HW;
#pragma unroll
    for (int mi = 0; mi < 2; mi++) {
        int row = rowBase + mwarp + mi * 16 + (lane >> 2);
#pragma unroll
        for (int nf = 0; nf < 8; nf++) {
            int col = colBase + nwarp + nf * 8 + (lane & 3) * 2;
            *(uint32_t*)((char*)obase + ((size_t)row * HW + col) * 2) =
                pkh(acc[mi][nf][0], acc[mi][nf][1]);
            *(uint32_t*)((char*)obase + ((size_t)(row + 8) * HW + col) * 2) =
                pkh(acc[mi][nf][2], acc[mi][nf][3]);
        }
    }
}

// ---------------------------------------------------------------------------
// Kernel 3a: k-softmax stats + write ek = exp(K-rmax)*rinv (fp16)
// ---------------------------------------------------------------------------
__global__ __launch_bounds__(256) void kstats_kernel(const __half* __restrict__ qkv,
                                                     const float* __restrict__ memkv,
                                                     float* __restrict__ rmax,
                                                     float* __restrict__ rinv,
                                                     __half* __restrict__ ek) {
    int d = blockIdx.x, h = blockIdx.y, b = blockIdx.z;
    int tid = threadIdx.x;
    const __half2* kr = (const __half2*)(qkv + ((size_t)b * O3 + HID + h * HD + d) * HW);
    const float* MK = memkv + ((size_t)h * HD + d) * NMEM;

    float v[16];
#pragma unroll
    for (int i = 0; i < 8; i++) {
        float2 p = __half22float2(kr[i * 256 + tid]);
        v[2 * i] = p.x;
        v[2 * i + 1] = p.y;
    }
    float m = v[0];
#pragma unroll
    for (int i = 1; i < 16; i++) m = fmaxf(m, v[i]);
    if (tid < NMEM) m = fmaxf(m, MK[tid]);

    __shared__ float red[8];
#pragma unroll
    for (int o = 16; o; o >>= 1) m = fmaxf(m, __shfl_xor_sync(0xFFFFFFFFu, m, o));
    if ((tid & 31) == 0) red[tid >> 5] = m;
    __syncthreads();
    if (tid == 0) {
        float t = red[0];
#pragma unroll
        for (int i = 1; i < 8; i++) t = fmaxf(t, red[i]);
        red[0] = t;
    }
    __syncthreads();
    m = red[0];
    __syncthreads();

    float ss = 0.f;
#pragma unroll
    for (int i = 0; i < 16; i++) ss += __expf(v[i] - m);
    if (tid < NMEM) ss += __expf(MK[tid] - m);
#pragma unroll
    for (int o = 16; o; o >>= 1) ss += __shfl_xor_sync(0xFFFFFFFFu, ss, o);
    if ((tid & 31) == 0) red[tid >> 5] = ss;
    __syncthreads();
    if (tid == 0) {
        float t = 0.f;
#pragma unroll
        for (int i = 0; i < 8; i++) t += red[i];
        float rv = 1.0f / t;
        int idx = (b * NH + h) * HD + d;
        rmax[idx] = m;
        rinv[idx] = rv;
        red[0] = rv;
    }
    __syncthreads();
    float rv = red[0];
    __half2* ekw = (__half2*)(ek + ((size_t)(b * NH + h) * HD + d) * HW);
#pragma unroll
    for (int i = 0; i < 8; i++)
        ekw[i * 256 + tid] = __floats2half2_rn(__expf(v[2 * i] - m) * rv,
                                               __expf(v[2 * i + 1] - m) * rv);
}

// ---------------------------------------------------------------------------
// Kernel 3b: partial context via mma.sync fp16.
// part[d][e] += ek[d][n] * V[e][n] over n in chunk. M=64, N=64, K=512.
// 8 warps (2m x 4n), warp tile 32x16. K-tile 64, double buffered.
// ---------------------------------------------------------------------------
#define CLDK 72
#define CT_T (64 * CLDK * 2)     // 9216
#define CSTAGE (2 * CT_T)        // 18432

__global__ __launch_bounds__(256) void ctxpart_kernel(const __half* __restrict__ ek,
                                                      const __half* __restrict__ qkv,
                                                      float* __restrict__ part) {
    __shared__ __align__(16) char csm[2 * CSTAGE];
    uint32_t sb = smem_u32(csm);
    int tid = threadIdx.x, warp = tid >> 5, lane = tid & 31;
    int c = blockIdx.x, h = blockIdx.y, b = blockIdx.z;

    const char* srcA = (const char*)(ek + ((size_t)(b * NH + h) * HD) * HW + c * CHUNK);
    const char* srcB = (const char*)(qkv + ((size_t)b * O3 + 2 * HID + h * HD) * HW + c * CHUNK);

    int lrow = tid >> 3, lseg = tid & 7;   // 32 rows x 8 segs (64 k = 128B)

    auto load_stage = [&](int st, int n0) {
        uint32_t dbase = sb + st * CSTAGE;
#pragma unroll
        for (int j = 0; j < 2; j++) {
            int row = lrow + j * 32;
            uint32_t dp = dbase + row * (CLDK * 2) + lseg * 16;
            size_t go = ((size_t)row * HW + n0) * 2 + lseg * 16;
            cp16(dp, srcA + go);
            cp16(dp + CT_T, srcB + go);
        }
    };

    int mwarp = (warp >> 2) * 32;
    int nwarp = (warp & 3) * 16;

    float acc[2][2][4];
#pragma unroll
    for (int mi = 0; mi < 2; mi++)
#pragma unroll
        for (int nf = 0; nf < 2; nf++)
#pragma unroll
            for (int q = 0; q < 4; q++) acc[mi][nf][q] = 0.f;

    int flrow = lane & 7, mat = lane >> 3;
    int frow = (mat & 1) * 8 + flrow;
    int fk   = (mat >> 1) * 8;

    load_stage(0, 0);
    CP_COMMIT();

    for (int kt = 0; kt < 8; kt++) {
        if (kt < 7) {
            load_stage((kt + 1) & 1, (kt + 1) * 64);
            CP_COMMIT();
            CP_WAIT1();
        } else {
            CP_WAIT0();
        }
        __syncthreads();
        uint32_t stb = sb + (kt & 1) * CSTAGE;

#pragma unroll
        for (int ks = 0; ks < 4; ks++) {
            int kk = ks * 16 + fk;
            uint32_t fa[2][4], fb[4];
#pragma unroll
            for (int mi = 0; mi < 2; mi++)
                ldm4(fa[mi], stb +
                     (uint32_t)((mwarp + mi * 16 + frow) * (CLDK * 2) + kk * 2));
            ldm4(fb, stb + CT_T +
                 (uint32_t)((nwarp + frow) * (CLDK * 2) + kk * 2));
#pragma unroll
            for (int mi = 0; mi < 2; mi++)
#pragma unroll
                for (int nf = 0; nf < 2; nf++)
                    mma_f16(acc[mi][nf], fa[mi], fb[nf], fb[nf + 2]);
        }
        __syncthreads();
    }

    float* pb = part + ((size_t)c * BATCH * NH + b * NH + h) * (HD * HD);
#pragma unroll
    for (int mi = 0; mi < 2; mi++) {
        int d = mwarp + mi * 16 + (lane >> 2);
#pragma unroll
        for (int nf = 0; nf < 2; nf++) {
            int e = nwarp + nf * 8 + (lane & 3) * 2;
            *(float2*)(&pb[d * HD + e]) = make_float2(acc[mi][nf][0], acc[mi][nf][1]);
            *(float2*)(&pb[(d + 8) * HD + e]) = make_float2(acc[mi][nf][2], acc[mi][nf][3]);
        }
    }
}

// ---------------------------------------------------------------------------
// Kernel 3c: reduce partials + mem-kv tail (rinv applied) -> ctx
// ---------------------------------------------------------------------------
__global__ __launch_bounds__(256) void ctxreduce_kernel(const float* __restrict__ part,
                                                        const float* __restrict__ memkv,
                                                        const float* __restrict__ rmax,
                                                        const float* __restrict__ rinv,
                                                        float* __restrict__ ctx) {
    int h = blockIdx.x, b = blockIdx.y;
    __shared__ float mkx[64][4];
    __shared__ float mvs[64][4];
    int tid = threadIdx.x;
    {
        int d = tid >> 2, j = tid & 3;
        int idx = (b * NH + h) * HD + d;
        mkx[d][j] = __expf(memkv[((size_t)h * HD + d) * NMEM + j] - rmax[idx]) * rinv[idx];
        mvs[d][j] = memkv[(size_t)NH * HD * NMEM + ((size_t)h * HD + d) * NMEM + j];
    }
    __syncthreads();
    size_t base = (size_t)(b * NH + h) * (HD * HD);
    for (int l = tid; l < HD * HD; l += 256) {
        int d = l >> 6, e = l & 63;
        float s2 = 0.f;
#pragma unroll
        for (int cc = 0; cc < NC; cc++)
            s2 += part[(size_t)cc * BATCH * NH * HD * HD + base + l];
#pragma unroll
        for (int j = 0; j < 4; j++) s2 += mkx[d][j] * mvs[e][j];
        ctx[base + l] = s2;
    }
}

// ---------------------------------------------------------------------------
// Kernel 4: q-softmax + tensorized 64x64x64 GEMM: out[e][p] = ctx[d][e]*qs[d][p].
// A = ctx^T [e][d] fp16 smem, B = qs^T [p][d] fp16 smem. 8 warps (2m x 4n).
// ---------------------------------------------------------------------------
__global__ __launch_bounds__(256) void attend_kernel(const __half* __restrict__ qkv,
                                                     const float* __restrict__ ctx,
                                                     __half* __restrict__ a1) {
    int pos0 = blockIdx.x * 64;
    int h = blockIdx.y, b = blockIdx.z;
    const __half* Q = qkv + ((size_t)b * O3 + h * HD) * HW;
    const float* cb = ctx + (size_t)(b * NH + h) * HD * HD;

    __shared__ __align__(16) float qs[64][68];     // [d][p] fp32 for softmax
    __shared__ __align__(16) __half cth[64][72];   // [e][d]
    __shared__ __align__(16) __half qth[64][72];   // [p][d], reused as out [p][e]

    int tid = threadIdx.x, warp = tid >> 5, lane = tid & 31;

    for (int l = tid; l < 64 * 32; l += 256) {
        int d = l >> 5, p2 = (l & 31) * 2;
        float2 qv = __half22float2(*(const __half2*)(Q + (size_t)d * HW + pos0 + p2));
        qs[d][p2] = qv.x;
        qs[d][p2 + 1] = qv.y;
    }
    for (int l = tid; l < HD * HD; l += 256) {
        int d = l >> 6, e = l & 63;
        cth[e][d] = __float2half_rn(cb[l]);
    }
    __syncthreads();

    if (tid < 64) {
        float m = -1e30f;
#pragma unroll
        for (int d = 0; d < HD; d++) m = fmaxf(m, qs[d][tid]);
        float ss = 0.f;
#pragma unroll
        for (int d = 0; d < HD; d++) ss += __expf(qs[d][tid] - m);
        float inv = 0.125f / ss;
#pragma unroll
        for (int d = 0; d < HD; d++)
            qth[tid][d] = __float2half_rn(__expf(qs[d][tid] - m) * inv);
    }
    __syncthreads();

    int mwarp = (warp >> 2) * 32;
    int nwarp = (warp & 3) * 16;

    float acc[2][2][4];
#pragma unroll
    for (int mi = 0; mi < 2; mi++)
#pragma unroll
        for (int nf = 0; nf < 2; nf++)
#pragma unroll
            for (int q = 0; q < 4; q++) acc[mi][nf][q] = 0.f;

    int flrow = lane & 7, mat = lane >> 3;
    int frow = (mat & 1) * 8 + flrow;
    int fk   = (mat >> 1) * 8;

    uint32_t sc = smem_u32(cth), sq = smem_u32(qth);
#pragma unroll
    for (int ks = 0; ks < 4; ks++) {
        int kk = ks * 16 + fk;
        uint32_t fa[2][4], fb[4];
#pragma unroll
        for (int mi = 0; mi < 2; mi++)
            ldm4(fa[mi], sc + (uint32_t)((mwarp + mi * 16 + frow) * 144 + kk * 2));
        ldm4(fb, sq + (uint32_t)((nwarp + frow) * 144 + kk * 2));
#pragma unroll
        for (int mi = 0; mi < 2; mi++)
#pragma unroll
            for (int nf = 0; nf < 2; nf++)
                mma_f16(acc[mi][nf], fa[mi], fb[nf], fb[nf + 2]);
    }
    __syncthreads();

    // stage out^T [p][e] into qth
#pragma unroll
    for (int mi = 0; mi < 2; mi++) {
        int e = mwarp + mi * 16 + (lane >> 2);
#pragma unroll
        for (int nf = 0; nf < 2; nf++) {
            int p = nwarp + nf * 8 + (lane & 3) * 2;
            qth[p][e]         = __float2half_rn(acc[mi][nf][0]);
            qth[p + 1][e]     = __float2half_rn(acc[mi][nf][1]);
            qth[p][e + 8]     = __float2half_rn(acc[mi][nf][2]);
            qth[p + 1][e + 8] = __float2half_rn(acc[mi][nf][3]);
        }
    }
    __syncthreads();

    {
        int pos = tid >> 2, e0 = (tid & 3) * 16;
        size_t base = ((size_t)b * HW + pos0 + pos) * HID + h * HD + e0;
        uint32_t r[8];
#pragma unroll
        for (int u = 0; u < 8; u++)
            r[u] = *(const uint32_t*)(&qth[pos][e0 + 2 * u]);
        *(uint4*)((char*)a1 + base * 2)      = make_uint4(r[0], r[1], r[2], r[3]);
        *(uint4*)((char*)a1 + base * 2 + 16) = make_uint4(r[4], r[5], r[6], r[7]);
    }
}

// ---------------------------------------------------------------------------
// Kernel 5: out GEMM fp16 + bias + fused rmsnorm. CTA 256x128, K-tile 32,
// 512 thr / 16 warps (4m x 4n), warp tile 64x32.
// ---------------------------------------------------------------------------
#define OLDK   40
#define OA_T   (256 * OLDK * 2)        // 20480
#define OB_T   (128 * OLDK * 2)        // 10240
#define OSTAGE (OA_T + OB_T)           // 30720
#define OSMTOT (2 * OSTAGE)            // 61440
#define O_A    0
#define O_B    OA_T

__global__ void __launch_bounds__(512, 1)
outnorm_mma_kernel(const __half* __restrict__ wo1,
                   const __half* __restrict__ a1,
                   const float* __restrict__ bias,
                   const float* __restrict__ gout,
                   float* __restrict__ out) {
    extern __shared__ char smem[];
    uint32_t sb = smem_u32(smem);
    __shared__ float colsq[128];
    __shared__ float invs[128];

    int tid = threadIdx.x;
    int warp = tid >> 5, lane = tid & 31;
    int b = blockIdx.y;
    int pos0 = blockIdx.x * 128;

    const char* srcA = (const char*)wo1;
    const char* srcB = (const char*)(a1 + ((size_t)b * HW + pos0) * HID);

    int lrow = tid >> 2, lseg = tid & 3;    // 128 rows x 4 segs per pass

    auto load_stage = [&](int st, int k0) {
        uint32_t dbase = sb + st * OSTAGE;
#pragma unroll
        for (int j = 0; j < 2; j++) {       // A: 256 rows
            int row = lrow + j * 128;
            cp16(dbase + O_A + row * (OLDK * 2) + lseg * 16,
                 srcA + (size_t)row * (HID * 2) + k0 * 2 + lseg * 16);
        }
        {                                   // B: 128 rows
            int row = lrow;
            cp16(dbase + O_B + row * (OLDK * 2) + lseg * 16,
                 srcB + (size_t)row * (HID * 2) + k0 * 2 + lseg * 16);
        }
    };

    int mwarp = (warp >> 2) * 64;
    int nwarp = (warp & 3) * 32;

    float acc[4][4][4];
#pragma unroll
    for (int mi = 0; mi < 4; mi++)
#pragma unroll
        for (int nf = 0; nf < 4; nf++)
#pragma unroll
            for (int q = 0; q < 4; q++) acc[mi][nf][q] = 0.f;

    int flrow = lane & 7, mat = lane >> 3;
    int frow = (mat & 1) * 8 + flrow;
    int fk   = (mat >> 1) * 8;

    if (tid < 128) colsq[tid] = 0.f;

    load_stage(0, 0);
    CP_COMMIT();

    for (int kt = 0; kt < 16; kt++) {
        if (kt < 15) {
            load_stage((kt + 1) & 1, (kt + 1) * 32);
            CP_COMMIT();
            CP_WAIT1();
        } else {
            CP_WAIT0();
        }
        __syncthreads();
        uint32_t stb = sb + (kt & 1) * OSTAGE;

#pragma unroll
        for (int ks = 0; ks < 2; ks++) {
            int kk = ks * 16 + fk;
            uint32_t fa[4][4], fb[2][4];
#pragma unroll
            for (int mi = 0; mi < 4; mi++)
                ldm4(fa[mi], stb + O_A +
                     (uint32_t)((mwarp + mi * 16 + frow) * (OLDK * 2) + kk * 2));
#pragma unroll
            for (int nb = 0; nb < 2; nb++)
                ldm4(fb[nb], stb + O_B +
                     (uint32_t)((nwarp + nb * 16 + frow) * (OLDK * 2) + kk * 2));
#pragma unroll
            for (int mi = 0; mi < 4; mi++)
#pragma unroll
                for (int nf = 0; nf < 4; nf++) {
                    int nb = nf >> 1, hi = nf & 1;
                    mma_f16(acc[mi][nf], fa[mi], fb[nb][hi], fb[nb][hi + 2]);
                }
        }
        __syncthreads();
    }

    // bias + column sum-of-squares
    float cs0[4], cs1[4];
#pragma unroll
    for (int nf = 0; nf < 4; nf++) { cs0[nf] = 0.f; cs1[nf] = 0.f; }
#pragma unroll
    for (int mi = 0; mi < 4; mi++) {
        int row = mwarp + mi * 16 + (lane >> 2);
        float bi0 = bias[row], bi1 = bias[row + 8];
#pragma unroll
        for (int nf = 0; nf < 4; nf++) {
            acc[mi][nf][0] += bi0;
            acc[mi][nf][1] += bi0;
            acc[mi][nf][2] += bi1;
            acc[mi][nf][3] += bi1;
            cs0[nf] += acc[mi][nf][0] * acc[mi][nf][0] + acc[mi][nf][2] * acc[mi][nf][2];
            cs1[nf] += acc[mi][nf][1] * acc[mi][nf][1] + acc[mi][nf][3] * acc[mi][nf][3];
        }
    }
#pragma unroll
    for (int nf = 0; nf < 4; nf++) {
#pragma unroll
        for (int o = 4; o < 32; o <<= 1) {
            cs0[nf] += __shfl_xor_sync(0xFFFFFFFFu, cs0[nf], o);
            cs1[nf] += __shfl_xor_sync(0xFFFFFFFFu, cs1[nf], o);
        }
    }
    if (lane < 4) {
#pragma unroll
        for (int nf = 0; nf < 4; nf++) {
            int col = nwarp + nf * 8 + lane * 2;
            atomicAdd(&colsq[col], cs0[nf]);
            atomicAdd(&colsq[col + 1], cs1[nf]);
        }
    }
    __syncthreads();
    if (tid < 128) invs[tid] = 16.0f / fmaxf(sqrtf(colsq[tid]), 1e-12f);
    __syncthreads();

    float* ob = out + (size_t)b * CIN * HW + pos0;
#pragma unroll
    for (int mi = 0; mi < 4; mi++) {
        int row = mwarp + mi * 16 + (lane >> 2);
        float gr0 = gout[row], gr1 = gout[row + 8];
#pragma unroll
        for (int nf = 0; nf < 4; nf++) {
            int col = nwarp + nf * 8 + (lane & 3) * 2;
            float i0 = invs[col], i1 = invs[col + 1];
            *(float2*)(ob + (size_t)row * HW + col) =
                make_float2(acc[mi][nf][0] * i0 * gr0, acc[mi][nf][1] * i1 * gr0);
            *(float2*)(ob + (size_t)(row + 8) * HW + col) =
                make_float2(acc[mi][nf][2] * i0 * gr1, acc[mi][nf][3] * i1 * gr1);
        }
    }
}

// ---------------------------------------------------------------------------
extern "C" void kernel_launch(void* const* d_in, const int* in_sizes, int n_in,
                              void* d_out, int out_size) {
    const float* x      = (const float*)d_in[0];
    const float* g_in   = (const float*)d_in[1];
    const float* w_qkv  = (const float*)d_in[2];
    const float* mem_kv = (const float*)d_in[3];
    const float* w_out  = (const float*)d_in[4];
    const float* b_out  = (const float*)d_in[5];
    const float* g_out  = (const float*)d_in[6];
    float* out = (float*)d_out;

    float *rmax_ptr, *rinv_ptr, *part_ptr, *ctx_ptr;
    __half *w1_ptr, *wo1_ptr, *x1_ptr, *qkv_ptr, *ek_ptr, *a1_ptr;
    cudaGetSymbolAddress((void**)&w1_ptr,   g_w1);
    cudaGetSymbolAddress((void**)&wo1_ptr,  g_wo1);
    cudaGetSymbolAddress((void**)&x1_ptr,   g_x1);
    cudaGetSymbolAddress((void**)&qkv_ptr,  g_qkv);
    cudaGetSymbolAddress((void**)&ek_ptr,   g_ek);
    cudaGetSymbolAddress((void**)&rmax_ptr, g_rmax);
    cudaGetSymbolAddress((void**)&rinv_ptr, g_rinv);
    cudaGetSymbolAddress((void**)&part_ptr, g_part);
    cudaGetSymbolAddress((void**)&ctx_ptr,  g_ctx);
    cudaGetSymbolAddress((void**)&a1_ptr,   g_a1);

    cudaFuncSetAttribute(qkv_mma_kernel,
                         cudaFuncAttributeMaxDynamicSharedMemorySize, QSMTOT);
    cudaFuncSetAttribute(outnorm_mma_kernel,
                         cudaFuncAttributeMaxDynamicSharedMemorySize, OSMTOT);

    wconv_kernel<<<(O3 * CIN + 255) / 256, 256>>>(w_qkv, g_in, w1_ptr);
    woconv_kernel<<<(CIN * HID + 255) / 256, 256>>>(w_out, wo1_ptr);
    xnorm_kernel<<<dim3(HW / 32, BATCH), 256>>>(x, x1_ptr);
    qkv_mma_kernel<<<dim3(HW / 128, O3 / 128, BATCH), 256, QSMTOT>>>(
        w1_ptr, x1_ptr, qkv_ptr);
    kstats_kernel<<<dim3(HD, NH, BATCH), 256>>>(qkv_ptr, mem_kv, rmax_ptr, rinv_ptr, ek_ptr);
    ctxpart_kernel<<<dim3(NC, NH, BATCH), 256>>>(ek_ptr, qkv_ptr, part_ptr);
    ctxreduce_kernel<<<dim3(NH, BATCH), 256>>>(part_ptr, mem_kv, rmax_ptr, rinv_ptr, ctx_ptr);
    attend_kernel<<<dim3(HW / 64, NH, BATCH), 256>>>(qkv_ptr, ctx_ptr, a1_ptr);
    outnorm_mma_kernel<<<dim3(HW / 128, BATCH), 512, OSMTOT>>>(
        wo1_ptr, a1_ptr, b_out, g_out, out);
}